// round 10
// baseline (speedup 1.0000x reference)
#include <cuda_runtime.h>
#include <cuda_bf16.h>

#define Bb 8
#define Nn 4096

typedef unsigned long long ull;
typedef unsigned int u32;

// scratch
__device__ int g_nbr[Bb * Nn * 16];
__device__ float g_W1p[64 * 256];       // W1[0:64] - W1[128:192] (x part, fp32)
__device__ uint4 g_W1f[4 * 32 * 32];    // W1n frag-packed bf16 hi/lo
__device__ uint4 g_W2f[16 * 4 * 32];    // W2 frag-packed bf16 hi/lo

// ---------------------------------------------------------------------------
__device__ __forceinline__ void split2(float a, float b, u32& hi, u32& lo) {
    __nv_bfloat16 ha = __float2bfloat16_rn(a);
    __nv_bfloat16 hb = __float2bfloat16_rn(b);
    hi = ((u32)__bfloat16_as_ushort(hb) << 16) | (u32)__bfloat16_as_ushort(ha);
    const float ra = a - __bfloat162float(ha);
    const float rb = b - __bfloat162float(hb);
    __nv_bfloat16 la = __float2bfloat16_rn(ra);
    __nv_bfloat16 lb = __float2bfloat16_rn(rb);
    lo = ((u32)__bfloat16_as_ushort(lb) << 16) | (u32)__bfloat16_as_ushort(la);
}

__device__ __forceinline__ void mma_bf16(float* d, u32 a0, u32 a1, u32 a2, u32 a3,
                                         u32 b0, u32 b1) {
    asm volatile(
        "mma.sync.aligned.m16n8k16.row.col.f32.bf16.bf16.f32 "
        "{%0,%1,%2,%3}, {%4,%5,%6,%7}, {%8,%9}, {%0,%1,%2,%3};"
        : "+f"(d[0]), "+f"(d[1]), "+f"(d[2]), "+f"(d[3])
        : "r"(a0), "r"(a1), "r"(a2), "r"(a3), "r"(b0), "r"(b1));
}

__device__ __forceinline__ void ldsm_x4(u32& r0, u32& r1, u32& r2, u32& r3,
                                        u32 saddr) {
    asm volatile(
        "ldmatrix.sync.aligned.m8n8.x4.shared.b16 {%0,%1,%2,%3}, [%4];"
        : "=r"(r0), "=r"(r1), "=r"(r2), "=r"(r3) : "r"(saddr));
}

// ---------------------------------------------------------------------------
// Kernel 1: KNN (blocks 0..255; 512 thr: 128 queries x 4 segments, whole
// batch staged in 64KB smem) + weight prep (blocks 256..287).
// ---------------------------------------------------------------------------
__global__ __launch_bounds__(512) void knn_prep_kernel(const float* __restrict__ pos,
                                                       const float* __restrict__ W1,
                                                       const float* __restrict__ W2) {
    const int bx = blockIdx.x;
    const int t = threadIdx.x;
    if (bx >= 256) {
        const int i = (bx - 256) * 512 + t;             // 0..16383
        {   // W1p (x-part, fp32)
            const int j = i >> 8;
            const int c = i & 255;
            g_W1p[i] = W1[j * 256 + c] - W1[(128 + j) * 256 + c];
        }
        if (i < 4096) {     // W1n frag pack: [kt 0..3][nt 0..31][lane]
            const int lane = i & 31;
            const int nt = (i >> 5) & 31;
            const int kt = i >> 10;
            const int j0 = kt * 16 + (lane & 3) * 2;
            const int n = nt * 8 + (lane >> 2);
            const float w00 = W1[(64 + j0) * 256 + n] + W1[(128 + j0) * 256 + n];
            const float w01 = W1[(64 + j0 + 1) * 256 + n] + W1[(128 + j0 + 1) * 256 + n];
            const float w10 = W1[(64 + j0 + 8) * 256 + n] + W1[(128 + j0 + 8) * 256 + n];
            const float w11 = W1[(64 + j0 + 9) * 256 + n] + W1[(128 + j0 + 9) * 256 + n];
            u32 h0, l0, h1, l1;
            split2(w00, w01, h0, l0);
            split2(w10, w11, h1, l1);
            g_W1f[i] = make_uint4(h0, h1, l0, l1);
        }
        if (i < 2048) {     // W2 frag pack: [kt 0..15][nt 0..3][lane]
            const int lane = i & 31;
            const int nt = (i >> 5) & 3;
            const int kt = i >> 7;
            const int j0 = kt * 16 + (lane & 3) * 2;
            const int n = nt * 8 + (lane >> 2);
            u32 h0, l0, h1, l1;
            split2(W2[j0 * 32 + n], W2[(j0 + 1) * 32 + n], h0, l0);
            split2(W2[(j0 + 8) * 32 + n], W2[(j0 + 9) * 32 + n], h1, l1);
            g_W2f[i] = make_uint4(h0, h1, l0, l1);
        }
        return;
    }

    extern __shared__ float4 stile[];   // 4096 candidates = 64KB

    const int b = bx >> 5;
    const int q = t & 127;
    const int s = t >> 7;               // segment 0..3
    const int n = ((bx & 31) << 7) + q;

    const float qx = pos[(b * Nn + n) * 3 + 0];
    const float qy = pos[(b * Nn + n) * 3 + 1];
    const float qz = pos[(b * Nn + n) * 3 + 2];
    const float sqn = __fadd_rn(__fadd_rn(__fmul_rn(qx, qx), __fmul_rn(qy, qy)),
                                __fmul_rn(qz, qz));

    // stage the full batch once
    for (int i = t; i < 4096; i += 512) {
        const float px = pos[(b * Nn + i) * 3 + 0];
        const float py = pos[(b * Nn + i) * 3 + 1];
        const float pz = pos[(b * Nn + i) * 3 + 2];
        const float sq = __fadd_rn(__fadd_rn(__fmul_rn(px, px), __fmul_rn(py, py)),
                                   __fmul_rn(pz, pz));
        stile[i] = make_float4(px, py, pz, sq);
    }
    __syncthreads();

    float bd[16];
    int bi[16];
#pragma unroll
    for (int j = 0; j < 16; ++j) { bd[j] = 3.0e38f; bi[j] = 0; }
    float worst = 3.0e38f;
    int wslot = 0;

    const int m0 = s << 10;
#pragma unroll 4
    for (int i = 0; i < 1024; ++i) {
        const float4 c = stile[m0 + i];
        const int m = m0 + i;
        float dot = __fmaf_rn(qx, c.x, 0.f);
        dot = __fmaf_rn(qy, c.y, dot);
        dot = __fmaf_rn(qz, c.z, dot);
        const float dist = __fsub_rn(__fadd_rn(sqn, c.w), __fmul_rn(2.0f, dot));
        if (dist < worst && m != n) {
#pragma unroll
            for (int j = 0; j < 16; ++j)
                if (j == wslot) { bd[j] = dist; bi[j] = m; }
            worst = bd[0]; wslot = 0;
#pragma unroll
            for (int j = 1; j < 16; ++j)
                if (bd[j] > worst) { worst = bd[j]; wslot = j; }
        }
    }
    __syncthreads();

    // dump partial heaps (reuse the 64KB tile)
    float* fbuf = (float*)stile;            // [512][16]
    int* ibuf = (int*)stile + 512 * 16;     // [512][16]
#pragma unroll
    for (int j = 0; j < 16; ++j) {
        fbuf[t * 16 + j] = bd[j];
        ibuf[t * 16 + j] = bi[j];
    }
    __syncthreads();

    // merge: threads of segment 0 combine 4 x 16 -> top 16
    if (s == 0) {
        float md[16];
        int mi[16];
#pragma unroll
        for (int j = 0; j < 16; ++j) { md[j] = 3.0e38f; mi[j] = 0; }
        float w2 = 3.0e38f;
        int ws2 = 0;
        for (int seg = 0; seg < 4; ++seg) {
            const int base = (seg * 128 + q) * 16;
#pragma unroll
            for (int j = 0; j < 16; ++j) {
                const float d = fbuf[base + j];
                const int idx = ibuf[base + j];
                if (d < w2) {
#pragma unroll
                    for (int r = 0; r < 16; ++r)
                        if (r == ws2) { md[r] = d; mi[r] = idx; }
                    w2 = md[0]; ws2 = 0;
#pragma unroll
                    for (int r = 1; r < 16; ++r)
                        if (md[r] > w2) { w2 = md[r]; ws2 = r; }
                }
            }
        }
#pragma unroll
        for (int j = 0; j < 16; ++j)
            g_nbr[(b * Nn + n) * 16 + j] = mi[j];
    }
}

// ---------------------------------------------------------------------------
// Kernel 2: fused DenseEdgeConv. 4 points = 64 rows, 256 threads (8 warps).
// GEMM1/GEMM2 on tensor cores; fragments loaded via ldmatrix.x4.
// ---------------------------------------------------------------------------
#define P4 4
#define SROW 68

// u32-unit offsets
#define OFF_AHI   0                          // [64 r][36 kpair]
#define OFF_ALO   (OFF_AHI + 64 * 36)
#define OFF_HHI   (OFF_ALO + 64 * 36)        // [64 r][68 kpair] (half of h1)
#define OFF_HLO   (OFF_HHI + 64 * 68)
#define OFF_Y2    (OFF_HLO + 64 * 68)        // [64 ch][68 kk] fp32
#define OFF_XH    (OFF_Y2 + 64 * 68)         // [4 p][256]
#define OFF_XN    (OFF_XH + P4 * 256)
#define OFF_MIDX  (OFF_XN + P4 * 64)
#define OFF_XG    (OFF_MIDX + P4 * 32)
#define OFF_YBAR  (OFF_XG + P4 * 64)
#define OFF_GATE  (OFF_YBAR + P4 * 64)
#define OFF_LASTX (OFF_GATE + P4 * 128)
#define OFF_NID   (OFF_LASTX + P4 * 32)
#define SMEM_U32  (OFF_NID + 64)

__global__ __launch_bounds__(256, 2) void conv_kernel(
    const float* __restrict__ x,
    const float* __restrict__ b1,
    const float* __restrict__ W2, const float* __restrict__ b2,
    const float* __restrict__ Wmid, const float* __restrict__ bmid,
    const float* __restrict__ Wg, const float* __restrict__ bg,
    const float* __restrict__ Wlast, const float* __restrict__ blast,
    float* __restrict__ out)
{
    extern __shared__ float sm[];
    u32* sAhi = (u32*)sm + OFF_AHI;
    u32* sAlo = (u32*)sm + OFF_ALO;
    u32* sHhi = (u32*)sm + OFF_HHI;
    u32* sHlo = (u32*)sm + OFF_HLO;
    float* sY2 = sm + OFF_Y2;
    float* sXh = sm + OFF_XH;
    float* sXn = sm + OFF_XN;
    float* sMidX = sm + OFF_MIDX;
    float* sXg = sm + OFF_XG;
    float* sYbar = sm + OFF_YBAR;
    float* sGate = sm + OFF_GATE;
    float* sLastX = sm + OFF_LASTX;
    int* sNid = (int*)((u32*)sm + OFF_NID);

    const int t = threadIdx.x;
    const int g0 = blockIdx.x * P4;
    const int b = g0 >> 12;

    sXn[t] = x[(g0 + (t >> 6)) * 64 + (t & 63)];
    if (t < 64) sNid[t] = g_nbr[g0 * 16 + t];
    __syncthreads();

    // ---- gather neighbors -> bf16 hi/lo smem + xh + mid_x -----------------
#pragma unroll
    for (int it = 0; it < 4; ++it) {
        const int idx = it * 256 + t;
        const int kk = idx >> 4;            // 0..63
        const int c4 = (idx & 15) << 2;
        const float4 v = *(const float4*)(x + (b * Nn + sNid[kk]) * 64 + c4);
        u32 h0, l0, h1, l1;
        split2(v.x, v.y, h0, l0);
        split2(v.z, v.w, h1, l1);
        const int base = kk * 36 + (c4 >> 1);
        sAhi[base] = h0; sAhi[base + 1] = h1;
        sAlo[base] = l0; sAlo[base + 1] = l1;
    }
    if (t < 128) {
        const int c0 = t;
        float a[4][2];
#pragma unroll
        for (int p = 0; p < 4; ++p) { a[p][0] = 0.f; a[p][1] = 0.f; }
#pragma unroll 4
        for (int j = 0; j < 64; ++j) {
            const float w0 = g_W1p[j * 256 + c0];
            const float w1 = g_W1p[j * 256 + c0 + 128];
#pragma unroll
            for (int p = 0; p < 4; ++p) {
                const float xv = sXn[p * 64 + j];
                a[p][0] = __fmaf_rn(xv, w0, a[p][0]);
                a[p][1] = __fmaf_rn(xv, w1, a[p][1]);
            }
        }
        const float bb0 = b1[c0];
        const float bb1 = b1[c0 + 128];
#pragma unroll
        for (int p = 0; p < 4; ++p) {
            sXh[p * 256 + c0] = a[p][0] + bb0;
            sXh[p * 256 + c0 + 128] = a[p][1] + bb1;
        }
    } else {
        const int p = (t >> 5) & 3;
        const int c = t & 31;
        float a = 0.f;
#pragma unroll 4
        for (int j = 0; j < 64; ++j)
            a = __fmaf_rn(sXn[p * 64 + j], Wmid[(32 + j) * 32 + c], a);
        sMidX[p * 32 + c] = a;
    }
    __syncthreads();

    // ---- tensor-core GEMM1 + GEMM2 over two 128-col halves ----------------
    const int lane = t & 31;
    const int w = t >> 5;
    const int mt = w & 3;               // m-tile = point
    const int nhw = w >> 2;             // 0..1
    const int lt = lane & 3;            // thread in group
    const int lg = lane >> 2;

    // ldmatrix lane addressing (row-major fragments)
    const int lrow = mt * 16 + (lane & 15);
    const int lk4 = (lane >> 4) << 2;           // u32 k-offset within tile
    const u32 aHiB = (u32)__cvta_generic_to_shared(sAhi) + (lrow * 36 + lk4) * 4;
    const u32 aLoB = (u32)__cvta_generic_to_shared(sAlo) + (lrow * 36 + lk4) * 4;
    const u32 hHiB = (u32)__cvta_generic_to_shared(sHhi) + (lrow * 68 + lk4) * 4;
    const u32 hLoB = (u32)__cvta_generic_to_shared(sHlo) + (lrow * 68 + lk4) * 4;

    float d2[2][4];
#pragma unroll
    for (int q = 0; q < 2; ++q)
#pragma unroll
        for (int r = 0; r < 4; ++r) d2[q][r] = 0.f;

#pragma unroll
    for (int h = 0; h < 2; ++h) {
        // GEMM1 half: rows 64 x cols 128 (ntg = h*16 + nhw*8 + nt)
        float d1[8][4];
#pragma unroll
        for (int nt = 0; nt < 8; ++nt)
#pragma unroll
            for (int r = 0; r < 4; ++r) d1[nt][r] = 0.f;

#pragma unroll
        for (int kt = 0; kt < 4; ++kt) {
            u32 ah0, ah1, ah2, ah3, al0, al1, al2, al3;
            ldsm_x4(ah0, ah1, ah2, ah3, aHiB + kt * 32);
            ldsm_x4(al0, al1, al2, al3, aLoB + kt * 32);
#pragma unroll
            for (int nt = 0; nt < 8; ++nt) {
                const int ntg = h * 16 + nhw * 8 + nt;
                const uint4 bb = g_W1f[((kt * 32 + ntg) << 5) + lane];
                mma_bf16(d1[nt], ah0, ah1, ah2, ah3, bb.x, bb.y);
                mma_bf16(d1[nt], ah0, ah1, ah2, ah3, bb.z, bb.w);
                mma_bf16(d1[nt], al0, al1, al2, al3, bb.x, bb.y);
            }
        }
        // epilogue: + xh, relu, bf16-split, store to sH (half layout)
#pragma unroll
        for (int nt = 0; nt < 8; ++nt) {
            const int ntg = h * 16 + nhw * 8 + nt;
            const int c0 = ntg * 8 + 2 * lt;
            const float xh0 = sXh[mt * 256 + c0];
            const float xh1 = sXh[mt * 256 + c0 + 1];
            const float v0 = fmaxf(d1[nt][0] + xh0, 0.f);
            const float v1 = fmaxf(d1[nt][1] + xh1, 0.f);
            const float v2 = fmaxf(d1[nt][2] + xh0, 0.f);
            const float v3 = fmaxf(d1[nt][3] + xh1, 0.f);
            u32 h01, l01, h23, l23;
            split2(v0, v1, h01, l01);
            split2(v2, v3, h23, l23);
            const int pair = (nhw * 8 + nt) * 4 + lt;
            const int r0 = mt * 16 + lg;
            sHhi[r0 * 68 + pair] = h01;
            sHhi[(r0 + 8) * 68 + pair] = h23;
            sHlo[r0 * 68 + pair] = l01;
            sHlo[(r0 + 8) * 68 + pair] = l23;
        }
        __syncthreads();

        // GEMM2 partial: K-tiles ktg = h*8 .. h*8+7
#pragma unroll
        for (int ktl = 0; ktl < 8; ++ktl) {
            u32 ah0, ah1, ah2, ah3, al0, al1, al2, al3;
            ldsm_x4(ah0, ah1, ah2, ah3, hHiB + ktl * 32);
            ldsm_x4(al0, al1, al2, al3, hLoB + ktl * 32);
            const int ktg = h * 8 + ktl;
#pragma unroll
            for (int q = 0; q < 2; ++q) {
                const int nt2 = nhw * 2 + q;
                const uint4 bb = g_W2f[((ktg * 4 + nt2) << 5) + lane];
                mma_bf16(d2[q], ah0, ah1, ah2, ah3, bb.x, bb.y);
                mma_bf16(d2[q], ah0, ah1, ah2, ah3, bb.z, bb.w);
                mma_bf16(d2[q], al0, al1, al2, al3, bb.x, bb.y);
            }
        }
        __syncthreads();
    }

    // ---- GEMM2 epilogue -> sY2 rows 32..63 (h), fp32 -----------------------
#pragma unroll
    for (int q = 0; q < 2; ++q) {
        const int nt2 = nhw * 2 + q;
        const int c0 = nt2 * 8 + 2 * lt;
        const int kk0 = mt * 16 + lg;
        const float bb0 = b2[c0];
        const float bb1 = b2[c0 + 1];
        sY2[(32 + c0) * SROW + kk0] = fmaxf(d2[q][0] + bb0, 0.f);
        sY2[(33 + c0) * SROW + kk0] = fmaxf(d2[q][1] + bb1, 0.f);
        sY2[(32 + c0) * SROW + kk0 + 8] = fmaxf(d2[q][2] + bb0, 0.f);
        sY2[(33 + c0) * SROW + kk0 + 8] = fmaxf(d2[q][3] + bb1, 0.f);
    }
    __syncthreads();

    // ---- scalar tail --------------------------------------------------------
    const int cpair = t & 15;
    const int kq = t >> 4;
    const int kk2 = kq << 2;
    const int pq = kq >> 2;

    {   // mid: m = relu(h @ Wmid[0:32] + mid_x + bmid) -> sY2 rows 0..31
        float a00 = 0.f, a01 = 0.f, a02 = 0.f, a03 = 0.f;
        float a10 = 0.f, a11 = 0.f, a12 = 0.f, a13 = 0.f;
#pragma unroll 4
        for (int j = 0; j < 32; ++j) {
            const float2 wv = *(const float2*)(Wmid + (j << 5) + 2 * cpair);
            const float4 av = *(const float4*)(sY2 + (32 + j) * SROW + kk2);
            a00 = __fmaf_rn(av.x, wv.x, a00); a01 = __fmaf_rn(av.y, wv.x, a01);
            a02 = __fmaf_rn(av.z, wv.x, a02); a03 = __fmaf_rn(av.w, wv.x, a03);
            a10 = __fmaf_rn(av.x, wv.y, a10); a11 = __fmaf_rn(av.y, wv.y, a11);
            a12 = __fmaf_rn(av.z, wv.y, a12); a13 = __fmaf_rn(av.w, wv.y, a13);
        }
        const float bx0 = sMidX[pq * 32 + 2 * cpair] + bmid[2 * cpair];
        const float bx1 = sMidX[pq * 32 + 2 * cpair + 1] + bmid[2 * cpair + 1];
        float4 r0, r1;
        r0.x = fmaxf(a00 + bx0, 0.f); r0.y = fmaxf(a01 + bx0, 0.f);
        r0.z = fmaxf(a02 + bx0, 0.f); r0.w = fmaxf(a03 + bx0, 0.f);
        r1.x = fmaxf(a10 + bx1, 0.f); r1.y = fmaxf(a11 + bx1, 0.f);
        r1.z = fmaxf(a12 + bx1, 0.f); r1.w = fmaxf(a13 + bx1, 0.f);
        *(float4*)(sY2 + (2 * cpair) * SROW + kk2) = r0;
        *(float4*)(sY2 + (2 * cpair + 1) * SROW + kk2) = r1;
    }
    __syncthreads();

    {   // ybar = mean_k (64 k-dependent channels)
        const int jj = t & 63;
        const int pp = t >> 6;
        const float* row = sY2 + jj * SROW + pp * 16;
        const float4 s0 = *(const float4*)(row + 0);
        const float4 s1 = *(const float4*)(row + 4);
        const float4 s2 = *(const float4*)(row + 8);
        const float4 s3 = *(const float4*)(row + 12);
        const float s = (s0.x + s0.y + s0.z + s0.w) + (s1.x + s1.y + s1.z + s1.w)
                      + (s2.x + s2.y + s2.z + s2.w) + (s3.x + s3.y + s3.z + s3.w);
        sYbar[pp * 64 + jj] = s * (1.0f / 16.0f);
    }
    __syncthreads();

    if (t < 128) {  // gate = sigmoid([ybar, xn] @ Wg + bg)
        const int c2 = (t & 63) * 2;
        const int p0 = (t >> 6) * 2;
        float a00 = 0.f, a01 = 0.f, a10 = 0.f, a11 = 0.f;
#pragma unroll 4
        for (int j = 0; j < 128; ++j) {
            const float2 wv = *(const float2*)(Wg + j * 128 + c2);
            const float y0 = (j < 64) ? sYbar[p0 * 64 + j] : sXn[p0 * 64 + j - 64];
            const float y1 = (j < 64) ? sYbar[(p0 + 1) * 64 + j]
                                      : sXn[(p0 + 1) * 64 + j - 64];
            a00 = __fmaf_rn(y0, wv.x, a00);
            a01 = __fmaf_rn(y0, wv.y, a01);
            a10 = __fmaf_rn(y1, wv.x, a10);
            a11 = __fmaf_rn(y1, wv.y, a11);
        }
        const float bb0 = bg[c2];
        const float bb1 = bg[c2 + 1];
        sGate[p0 * 128 + c2] = 1.0f / (1.0f + expf(-(a00 + bb0)));
        sGate[p0 * 128 + c2 + 1] = 1.0f / (1.0f + expf(-(a01 + bb1)));
        sGate[(p0 + 1) * 128 + c2] = 1.0f / (1.0f + expf(-(a10 + bb0)));
        sGate[(p0 + 1) * 128 + c2 + 1] = 1.0f / (1.0f + expf(-(a11 + bb1)));
    }
    __syncthreads();

    {   // xg = xn*gate; out channels 96..159 (k-invariant)
        const int c = t & 63;
        const int p = t >> 6;
        const float xg = sXn[p * 64 + c] * sGate[p * 128 + 64 + c];
        sXg[p * 64 + c] = xg;
        out[(g0 + p) * 160 + 96 + c] = xg;
    }
    __syncthreads();

    {   // y2 *= gate; out channels 32..95 = max_k
        const int jj = t & 63;
        const int pp = t >> 6;
        const float gv = sGate[pp * 128 + jj];
        float* row = sY2 + jj * SROW + pp * 16;
        float mx = -3.0e38f;
#pragma unroll
        for (int q = 0; q < 4; ++q) {
            float4 v = *(const float4*)(row + 4 * q);
            v.x *= gv; v.y *= gv; v.z *= gv; v.w *= gv;
            mx = fmaxf(mx, fmaxf(fmaxf(v.x, v.y), fmaxf(v.z, v.w)));
            *(float4*)(row + 4 * q) = v;
        }
        out[(g0 + pp) * 160 + 32 + jj] = mx;
    }
    if (t < 128) {  // last_x[p][c] = (xn*gate) . Wlast[64:128, c]
        const int p = t >> 5;
        const int c = t & 31;
        float a = 0.f;
#pragma unroll 4
        for (int j = 0; j < 64; ++j)
            a = __fmaf_rn(sXg[p * 64 + j], Wlast[(64 + j) * 32 + c], a);
        sLastX[p * 32 + c] = a;
    }
    __syncthreads();

    float* sRed = sXh;
    {   // last (k-dep 64 rows): out ch 0..31 = max_k
        float a00 = 0.f, a01 = 0.f, a02 = 0.f, a03 = 0.f;
        float a10 = 0.f, a11 = 0.f, a12 = 0.f, a13 = 0.f;
#pragma unroll 4
        for (int j = 0; j < 64; ++j) {
            const float2 wv = *(const float2*)(Wlast + (j << 5) + 2 * cpair);
            const float4 av = *(const float4*)(sY2 + j * SROW + kk2);
            a00 = __fmaf_rn(av.x, wv.x, a00); a01 = __fmaf_rn(av.y, wv.x, a01);
            a02 = __fmaf_rn(av.z, wv.x, a02); a03 = __fmaf_rn(av.w, wv.x, a03);
            a10 = __fmaf_rn(av.x, wv.y, a10); a11 = __fmaf_rn(av.y, wv.y, a11);
            a12 = __fmaf_rn(av.z, wv.y, a12); a13 = __fmaf_rn(av.w, wv.y, a13);
        }
        const float t0 = sLastX[pq * 32 + 2 * cpair] + blast[2 * cpair];
        const float t1 = sLastX[pq * 32 + 2 * cpair + 1] + blast[2 * cpair + 1];
        const float mx0 = fmaxf(fmaxf(a00 + t0, a01 + t0), fmaxf(a02 + t0, a03 + t0));
        const float mx1 = fmaxf(fmaxf(a10 + t1, a11 + t1), fmaxf(a12 + t1, a13 + t1));
        sRed[kq * 32 + 2 * cpair] = mx0;
        sRed[kq * 32 + 2 * cpair + 1] = mx1;
    }
    __syncthreads();
    if (t < 128) {
        const int p = t >> 5;
        const int cc = t & 31;
        float mx = sRed[(p * 4 + 0) * 32 + cc];
        mx = fmaxf(mx, sRed[(p * 4 + 1) * 32 + cc]);
        mx = fmaxf(mx, sRed[(p * 4 + 2) * 32 + cc]);
        mx = fmaxf(mx, sRed[(p * 4 + 3) * 32 + cc]);
        out[(g0 + p) * 160 + cc] = mx;
    }
}

// ---------------------------------------------------------------------------
extern "C" void kernel_launch(void* const* d_in, const int* in_sizes, int n_in,
                              void* d_out, int out_size) {
    const float* x = (const float*)d_in[0];
    const float* pos = (const float*)d_in[1];
    const float* W1 = (const float*)d_in[2];
    const float* b1 = (const float*)d_in[3];
    const float* W2 = (const float*)d_in[4];
    const float* b2 = (const float*)d_in[5];
    const float* Wmid = (const float*)d_in[6];
    const float* bmid = (const float*)d_in[7];
    const float* Wg = (const float*)d_in[8];
    const float* bg = (const float*)d_in[9];
    const float* Wlast = (const float*)d_in[10];
    const float* blast = (const float*)d_in[11];
    float* out = (float*)d_out;

    const int knn_smem = 4096 * 16;     // 64KB
    cudaFuncSetAttribute(knn_prep_kernel, cudaFuncAttributeMaxDynamicSharedMemorySize,
                         knn_smem);
    const int smem_bytes = SMEM_U32 * 4;
    cudaFuncSetAttribute(conv_kernel, cudaFuncAttributeMaxDynamicSharedMemorySize,
                         smem_bytes);

    knn_prep_kernel<<<256 + 32, 512, knn_smem>>>(pos, W1, W2);
    conv_kernel<<<(Bb * Nn) / P4, 256, smem_bytes>>>(
        x, b1, W2, b2, Wmid, bmid, Wg, bg, Wlast, blast, out);
}

// round 11
// speedup vs baseline: 1.0612x; 1.0612x over previous
#include <cuda_runtime.h>
#include <cuda_bf16.h>

#define Bb 8
#define Nn 4096

typedef unsigned long long ull;
typedef unsigned int u32;

// scratch
__device__ int g_nbr[Bb * Nn * 16];
__device__ float g_W1p[64 * 256];       // W1[0:64] - W1[128:192] (x part, fp32)
__device__ uint4 g_W1f[4 * 32 * 32];    // W1n frag-packed bf16 hi/lo
__device__ uint4 g_W2f[16 * 4 * 32];    // W2 frag-packed bf16 hi/lo

// ---------------------------------------------------------------------------
__device__ __forceinline__ void split2(float a, float b, u32& hi, u32& lo) {
    __nv_bfloat16 ha = __float2bfloat16_rn(a);
    __nv_bfloat16 hb = __float2bfloat16_rn(b);
    hi = ((u32)__bfloat16_as_ushort(hb) << 16) | (u32)__bfloat16_as_ushort(ha);
    const float ra = a - __bfloat162float(ha);
    const float rb = b - __bfloat162float(hb);
    __nv_bfloat16 la = __float2bfloat16_rn(ra);
    __nv_bfloat16 lb = __float2bfloat16_rn(rb);
    lo = ((u32)__bfloat16_as_ushort(lb) << 16) | (u32)__bfloat16_as_ushort(la);
}

__device__ __forceinline__ void mma_bf16(float* d, u32 a0, u32 a1, u32 a2, u32 a3,
                                         u32 b0, u32 b1) {
    asm volatile(
        "mma.sync.aligned.m16n8k16.row.col.f32.bf16.bf16.f32 "
        "{%0,%1,%2,%3}, {%4,%5,%6,%7}, {%8,%9}, {%0,%1,%2,%3};"
        : "+f"(d[0]), "+f"(d[1]), "+f"(d[2]), "+f"(d[3])
        : "r"(a0), "r"(a1), "r"(a2), "r"(a3), "r"(b0), "r"(b1));
}

// ---------------------------------------------------------------------------
// Kernel 1: KNN (blocks 0..255, scalar R4 form) + weight prep (blocks 256..383)
// ---------------------------------------------------------------------------
__global__ __launch_bounds__(128) void knn_prep_kernel(const float* __restrict__ pos,
                                                       const float* __restrict__ W1,
                                                       const float* __restrict__ W2) {
    const int bx = blockIdx.x;
    const int t = threadIdx.x;
    if (bx >= 256) {
        const int i = (bx - 256) * 128 + t;             // 0..16383
        {   // W1p (x-part, fp32)
            const int j = i >> 8;
            const int c = i & 255;
            g_W1p[i] = W1[j * 256 + c] - W1[(128 + j) * 256 + c];
        }
        if (i < 4096) {     // W1n frag pack: [kt 0..3][nt 0..31][lane]
            const int lane = i & 31;
            const int nt = (i >> 5) & 31;
            const int kt = i >> 10;
            const int j0 = kt * 16 + (lane & 3) * 2;
            const int n = nt * 8 + (lane >> 2);
            const float w00 = W1[(64 + j0) * 256 + n] + W1[(128 + j0) * 256 + n];
            const float w01 = W1[(64 + j0 + 1) * 256 + n] + W1[(128 + j0 + 1) * 256 + n];
            const float w10 = W1[(64 + j0 + 8) * 256 + n] + W1[(128 + j0 + 8) * 256 + n];
            const float w11 = W1[(64 + j0 + 9) * 256 + n] + W1[(128 + j0 + 9) * 256 + n];
            u32 h0, l0, h1, l1;
            split2(w00, w01, h0, l0);
            split2(w10, w11, h1, l1);
            g_W1f[i] = make_uint4(h0, h1, l0, l1);
        }
        if (i < 2048) {     // W2 frag pack: [kt 0..15][nt 0..3][lane]
            const int lane = i & 31;
            const int nt = (i >> 5) & 3;
            const int kt = i >> 7;
            const int j0 = kt * 16 + (lane & 3) * 2;
            const int n = nt * 8 + (lane >> 2);
            u32 h0, l0, h1, l1;
            split2(W2[j0 * 32 + n], W2[(j0 + 1) * 32 + n], h0, l0);
            split2(W2[(j0 + 8) * 32 + n], W2[(j0 + 9) * 32 + n], h1, l1);
            g_W2f[i] = make_uint4(h0, h1, l0, l1);
        }
        return;
    }

    const int b = bx >> 5;
    const int n = ((bx & 31) << 7) + t;

    const float qx = pos[(b * Nn + n) * 3 + 0];
    const float qy = pos[(b * Nn + n) * 3 + 1];
    const float qz = pos[(b * Nn + n) * 3 + 2];
    const float sqn = __fadd_rn(__fadd_rn(__fmul_rn(qx, qx), __fmul_rn(qy, qy)),
                                __fmul_rn(qz, qz));

    float bd[16];
    int bi[16];
#pragma unroll
    for (int j = 0; j < 16; ++j) { bd[j] = 3.0e38f; bi[j] = 0; }
    float worst = 3.0e38f;
    int wslot = 0;

    __shared__ float4 tile[1024];

    for (int t0 = 0; t0 < Nn; t0 += 1024) {
        __syncthreads();
        for (int i = t; i < 1024; i += 128) {
            const float px = pos[(b * Nn + t0 + i) * 3 + 0];
            const float py = pos[(b * Nn + t0 + i) * 3 + 1];
            const float pz = pos[(b * Nn + t0 + i) * 3 + 2];
            const float sq = __fadd_rn(__fadd_rn(__fmul_rn(px, px), __fmul_rn(py, py)),
                                       __fmul_rn(pz, pz));
            tile[i] = make_float4(px, py, pz, sq);
        }
        __syncthreads();
#pragma unroll 4
        for (int i = 0; i < 1024; ++i) {
            const float4 c = tile[i];
            const int m = t0 + i;
            float dot = __fmaf_rn(qx, c.x, 0.f);
            dot = __fmaf_rn(qy, c.y, dot);
            dot = __fmaf_rn(qz, c.z, dot);
            const float dist = __fsub_rn(__fadd_rn(sqn, c.w), __fmul_rn(2.0f, dot));
            if (dist < worst && m != n) {
#pragma unroll
                for (int j = 0; j < 16; ++j)
                    if (j == wslot) { bd[j] = dist; bi[j] = m; }
                worst = bd[0]; wslot = 0;
#pragma unroll
                for (int j = 1; j < 16; ++j)
                    if (bd[j] > worst) { worst = bd[j]; wslot = j; }
            }
        }
    }

#pragma unroll
    for (int j = 0; j < 16; ++j)
        g_nbr[(b * Nn + n) * 16 + j] = bi[j];
}

// ---------------------------------------------------------------------------
// Kernel 2: fused DenseEdgeConv. 4 points = 64 rows, 256 threads (8 warps).
// GEMM1/GEMM2 on tensor cores (bf16 3-term compensated), rest scalar fp32.
// sY2 aliases the (dead after GEMM1) A region -> smem 62KB.
// ---------------------------------------------------------------------------
#define P4 4
#define SROW 68

// u32-unit offsets
#define OFF_AHI   0                          // [64 r][36 kpair]  (GEMM1 only)
#define OFF_ALO   (OFF_AHI + 64 * 36)
#define OFF_Y2    0                          // [64 ch][68 kk] fp32 — ALIASES A
#define OFF_HHI   (OFF_ALO + 64 * 36)        // [64 r][68 kpair] (half of h1)
#define OFF_HLO   (OFF_HHI + 64 * 68)
#define OFF_XH    (OFF_HLO + 64 * 68)        // [4 p][256] (also last-reduce scratch)
#define OFF_XN    (OFF_XH + P4 * 256)
#define OFF_MIDX  (OFF_XN + P4 * 64)
#define OFF_XG    (OFF_MIDX + P4 * 32)
#define OFF_YBAR  (OFF_XG + P4 * 64)
#define OFF_GATE  (OFF_YBAR + P4 * 64)
#define OFF_LASTX (OFF_GATE + P4 * 128)
#define OFF_NID   (OFF_LASTX + P4 * 32)
#define SMEM_U32  (OFF_NID + 64)

__global__ __launch_bounds__(256, 2) void conv_kernel(
    const float* __restrict__ x,
    const float* __restrict__ b1,
    const float* __restrict__ W2, const float* __restrict__ b2,
    const float* __restrict__ Wmid, const float* __restrict__ bmid,
    const float* __restrict__ Wg, const float* __restrict__ bg,
    const float* __restrict__ Wlast, const float* __restrict__ blast,
    float* __restrict__ out)
{
    extern __shared__ float sm[];
    u32* sAhi = (u32*)sm + OFF_AHI;
    u32* sAlo = (u32*)sm + OFF_ALO;
    u32* sHhi = (u32*)sm + OFF_HHI;
    u32* sHlo = (u32*)sm + OFF_HLO;
    float* sY2 = sm + OFF_Y2;           // valid only after GEMM1 is done with A
    float* sXh = sm + OFF_XH;
    float* sXn = sm + OFF_XN;
    float* sMidX = sm + OFF_MIDX;
    float* sXg = sm + OFF_XG;
    float* sYbar = sm + OFF_YBAR;
    float* sGate = sm + OFF_GATE;
    float* sLastX = sm + OFF_LASTX;
    int* sNid = (int*)((u32*)sm + OFF_NID);

    const int t = threadIdx.x;
    const int g0 = blockIdx.x * P4;
    const int b = g0 >> 12;

    sXn[t] = x[(g0 + (t >> 6)) * 64 + (t & 63)];
    if (t < 64) sNid[t] = g_nbr[g0 * 16 + t];
    __syncthreads();

    // ---- gather neighbors -> bf16 hi/lo smem + xh + mid_x -----------------
#pragma unroll
    for (int it = 0; it < 4; ++it) {
        const int idx = it * 256 + t;
        const int kk = idx >> 4;            // 0..63
        const int c4 = (idx & 15) << 2;
        const float4 v = *(const float4*)(x + (b * Nn + sNid[kk]) * 64 + c4);
        u32 h0, l0, h1, l1;
        split2(v.x, v.y, h0, l0);
        split2(v.z, v.w, h1, l1);
        const int base = kk * 36 + (c4 >> 1);
        sAhi[base] = h0; sAhi[base + 1] = h1;
        sAlo[base] = l0; sAlo[base + 1] = l1;
    }
    if (t < 128) {
        const int c0 = t;
        float a[4][2];
#pragma unroll
        for (int p = 0; p < 4; ++p) { a[p][0] = 0.f; a[p][1] = 0.f; }
#pragma unroll 4
        for (int j = 0; j < 64; ++j) {
            const float w0 = g_W1p[j * 256 + c0];
            const float w1 = g_W1p[j * 256 + c0 + 128];
#pragma unroll
            for (int p = 0; p < 4; ++p) {
                const float xv = sXn[p * 64 + j];
                a[p][0] = __fmaf_rn(xv, w0, a[p][0]);
                a[p][1] = __fmaf_rn(xv, w1, a[p][1]);
            }
        }
        const float bb0 = b1[c0];
        const float bb1 = b1[c0 + 128];
#pragma unroll
        for (int p = 0; p < 4; ++p) {
            sXh[p * 256 + c0] = a[p][0] + bb0;
            sXh[p * 256 + c0 + 128] = a[p][1] + bb1;
        }
    } else {
        const int p = (t >> 5) & 3;
        const int c = t & 31;
        float a = 0.f;
#pragma unroll 4
        for (int j = 0; j < 64; ++j)
            a = __fmaf_rn(sXn[p * 64 + j], Wmid[(32 + j) * 32 + c], a);
        sMidX[p * 32 + c] = a;
    }
    __syncthreads();

    // ---- tensor-core GEMM1 + GEMM2 over two 128-col halves ----------------
    const int lane = t & 31;
    const int w = t >> 5;
    const int mt = w & 3;               // m-tile = point
    const int nhw = w >> 2;             // 0..1
    const int lt = lane & 3;            // thread in group
    const int lg = lane >> 2;

    float d2[2][4];
#pragma unroll
    for (int q = 0; q < 2; ++q)
#pragma unroll
        for (int r = 0; r < 4; ++r) d2[q][r] = 0.f;

#pragma unroll
    for (int h = 0; h < 2; ++h) {
        // GEMM1 half: rows 64 x cols 128 (ntg = h*16 + nhw*8 + nt)
        float d1[8][4];
#pragma unroll
        for (int nt = 0; nt < 8; ++nt)
#pragma unroll
            for (int r = 0; r < 4; ++r) d1[nt][r] = 0.f;

#pragma unroll
        for (int kt = 0; kt < 4; ++kt) {
            const int abase = (mt * 16 + lg) * 36 + kt * 8 + lt;
            const u32 ah0 = sAhi[abase];
            const u32 ah1 = sAhi[abase + 8 * 36];
            const u32 ah2 = sAhi[abase + 4];
            const u32 ah3 = sAhi[abase + 8 * 36 + 4];
            const u32 al0 = sAlo[abase];
            const u32 al1 = sAlo[abase + 8 * 36];
            const u32 al2 = sAlo[abase + 4];
            const u32 al3 = sAlo[abase + 8 * 36 + 4];
#pragma unroll
            for (int nt = 0; nt < 8; ++nt) {
                const int ntg = h * 16 + nhw * 8 + nt;
                const uint4 bb = g_W1f[((kt * 32 + ntg) << 5) + lane];
                mma_bf16(d1[nt], ah0, ah1, ah2, ah3, bb.x, bb.y);
                mma_bf16(d1[nt], ah0, ah1, ah2, ah3, bb.z, bb.w);
                mma_bf16(d1[nt], al0, al1, al2, al3, bb.x, bb.y);
            }
        }
        // epilogue: + xh, relu, bf16-split, store to sH (half layout)
#pragma unroll
        for (int nt = 0; nt < 8; ++nt) {
            const int ntg = h * 16 + nhw * 8 + nt;
            const int c0 = ntg * 8 + 2 * lt;
            const float xh0 = sXh[mt * 256 + c0];
            const float xh1 = sXh[mt * 256 + c0 + 1];
            const float v0 = fmaxf(d1[nt][0] + xh0, 0.f);
            const float v1 = fmaxf(d1[nt][1] + xh1, 0.f);
            const float v2 = fmaxf(d1[nt][2] + xh0, 0.f);
            const float v3 = fmaxf(d1[nt][3] + xh1, 0.f);
            u32 h01, l01, h23, l23;
            split2(v0, v1, h01, l01);
            split2(v2, v3, h23, l23);
            const int pair = (nhw * 8 + nt) * 4 + lt;
            const int r0 = mt * 16 + lg;
            sHhi[r0 * 68 + pair] = h01;
            sHhi[(r0 + 8) * 68 + pair] = h23;
            sHlo[r0 * 68 + pair] = l01;
            sHlo[(r0 + 8) * 68 + pair] = l23;
        }
        __syncthreads();

        // GEMM2 partial: K-tiles ktg = h*8 .. h*8+7
#pragma unroll
        for (int ktl = 0; ktl < 8; ++ktl) {
            const int hbase = (mt * 16 + lg) * 68 + ktl * 8 + lt;
            const u32 ah0 = sHhi[hbase];
            const u32 ah1 = sHhi[hbase + 8 * 68];
            const u32 ah2 = sHhi[hbase + 4];
            const u32 ah3 = sHhi[hbase + 8 * 68 + 4];
            const u32 al0 = sHlo[hbase];
            const u32 al1 = sHlo[hbase + 8 * 68];
            const u32 al2 = sHlo[hbase + 4];
            const u32 al3 = sHlo[hbase + 8 * 68 + 4];
            const int ktg = h * 8 + ktl;
#pragma unroll
            for (int q = 0; q < 2; ++q) {
                const int nt2 = nhw * 2 + q;
                const uint4 bb = g_W2f[((ktg * 4 + nt2) << 5) + lane];
                mma_bf16(d2[q], ah0, ah1, ah2, ah3, bb.x, bb.y);
                mma_bf16(d2[q], ah0, ah1, ah2, ah3, bb.z, bb.w);
                mma_bf16(d2[q], al0, al1, al2, al3, bb.x, bb.y);
            }
        }
        __syncthreads();
    }

    // ---- GEMM2 epilogue -> sY2 rows 32..63 (h), fp32 (A region now dead) ---
#pragma unroll
    for (int q = 0; q < 2; ++q) {
        const int nt2 = nhw * 2 + q;
        const int c0 = nt2 * 8 + 2 * lt;
        const int kk0 = mt * 16 + lg;
        const float bb0 = b2[c0];
        const float bb1 = b2[c0 + 1];
        sY2[(32 + c0) * SROW + kk0] = fmaxf(d2[q][0] + bb0, 0.f);
        sY2[(33 + c0) * SROW + kk0] = fmaxf(d2[q][1] + bb1, 0.f);
        sY2[(32 + c0) * SROW + kk0 + 8] = fmaxf(d2[q][2] + bb0, 0.f);
        sY2[(33 + c0) * SROW + kk0 + 8] = fmaxf(d2[q][3] + bb1, 0.f);
    }
    __syncthreads();

    // ---- scalar tail --------------------------------------------------------
    const int cpair = t & 15;
    const int kq = t >> 4;
    const int kk2 = kq << 2;
    const int pq = kq >> 2;

    {   // mid: m = relu(h @ Wmid[0:32] + mid_x + bmid) -> sY2 rows 0..31
        float a00 = 0.f, a01 = 0.f, a02 = 0.f, a03 = 0.f;
        float a10 = 0.f, a11 = 0.f, a12 = 0.f, a13 = 0.f;
#pragma unroll 4
        for (int j = 0; j < 32; ++j) {
            const float2 wv = *(const float2*)(Wmid + (j << 5) + 2 * cpair);
            const float4 av = *(const float4*)(sY2 + (32 + j) * SROW + kk2);
            a00 = __fmaf_rn(av.x, wv.x, a00); a01 = __fmaf_rn(av.y, wv.x, a01);
            a02 = __fmaf_rn(av.z, wv.x, a02); a03 = __fmaf_rn(av.w, wv.x, a03);
            a10 = __fmaf_rn(av.x, wv.y, a10); a11 = __fmaf_rn(av.y, wv.y, a11);
            a12 = __fmaf_rn(av.z, wv.y, a12); a13 = __fmaf_rn(av.w, wv.y, a13);
        }
        const float bx0 = sMidX[pq * 32 + 2 * cpair] + bmid[2 * cpair];
        const float bx1 = sMidX[pq * 32 + 2 * cpair + 1] + bmid[2 * cpair + 1];
        float4 r0, r1;
        r0.x = fmaxf(a00 + bx0, 0.f); r0.y = fmaxf(a01 + bx0, 0.f);
        r0.z = fmaxf(a02 + bx0, 0.f); r0.w = fmaxf(a03 + bx0, 0.f);
        r1.x = fmaxf(a10 + bx1, 0.f); r1.y = fmaxf(a11 + bx1, 0.f);
        r1.z = fmaxf(a12 + bx1, 0.f); r1.w = fmaxf(a13 + bx1, 0.f);
        *(float4*)(sY2 + (2 * cpair) * SROW + kk2) = r0;
        *(float4*)(sY2 + (2 * cpair + 1) * SROW + kk2) = r1;
    }
    __syncthreads();

    {   // ybar = mean_k (64 k-dependent channels)
        const int jj = t & 63;
        const int pp = t >> 6;
        const float* row = sY2 + jj * SROW + pp * 16;
        const float4 s0 = *(const float4*)(row + 0);
        const float4 s1 = *(const float4*)(row + 4);
        const float4 s2 = *(const float4*)(row + 8);
        const float4 s3 = *(const float4*)(row + 12);
        const float s = (s0.x + s0.y + s0.z + s0.w) + (s1.x + s1.y + s1.z + s1.w)
                      + (s2.x + s2.y + s2.z + s2.w) + (s3.x + s3.y + s3.z + s3.w);
        sYbar[pp * 64 + jj] = s * (1.0f / 16.0f);
    }
    __syncthreads();

    {   // gate = sigmoid([ybar, xn] @ Wg + bg) — ALL 256 threads:
        // thread = (point pg, channel-pair c2g); same j-order => bit-identical
        const int c2g = (t & 63) * 2;
        const int pg = t >> 6;
        float a0 = 0.f, a1 = 0.f;
#pragma unroll 4
        for (int j = 0; j < 128; ++j) {
            const float2 wv = *(const float2*)(Wg + j * 128 + c2g);
            const float y = (j < 64) ? sYbar[pg * 64 + j] : sXn[pg * 64 + j - 64];
            a0 = __fmaf_rn(y, wv.x, a0);
            a1 = __fmaf_rn(y, wv.y, a1);
        }
        sGate[pg * 128 + c2g] = 1.0f / (1.0f + expf(-(a0 + bg[c2g])));
        sGate[pg * 128 + c2g + 1] = 1.0f / (1.0f + expf(-(a1 + bg[c2g + 1])));
    }
    __syncthreads();

    {   // xg = xn*gate; out channels 96..159 (k-invariant)
        const int c = t & 63;
        const int p = t >> 6;
        const float xg = sXn[p * 64 + c] * sGate[p * 128 + 64 + c];
        sXg[p * 64 + c] = xg;
        out[(g0 + p) * 160 + 96 + c] = xg;
    }
    __syncthreads();

    {   // y2 *= gate; out channels 32..95 = max_k
        const int jj = t & 63;
        const int pp = t >> 6;
        const float gv = sGate[pp * 128 + jj];
        float* row = sY2 + jj * SROW + pp * 16;
        float mx = -3.0e38f;
#pragma unroll
        for (int q = 0; q < 4; ++q) {
            float4 v = *(const float4*)(row + 4 * q);
            v.x *= gv; v.y *= gv; v.z *= gv; v.w *= gv;
            mx = fmaxf(mx, fmaxf(fmaxf(v.x, v.y), fmaxf(v.z, v.w)));
            *(float4*)(row + 4 * q) = v;
        }
        out[(g0 + pp) * 160 + 32 + jj] = mx;
    }
    if (t < 128) {  // last_x[p][c] = (xn*gate) . Wlast[64:128, c]
        const int p = t >> 5;
        const int c = t & 31;
        float a = 0.f;
#pragma unroll 4
        for (int j = 0; j < 64; ++j)
            a = __fmaf_rn(sXg[p * 64 + j], Wlast[(64 + j) * 32 + c], a);
        sLastX[p * 32 + c] = a;
    }
    __syncthreads();

    float* sRed = sXh;
    {   // last (k-dep 64 rows): out ch 0..31 = max_k
        float a00 = 0.f, a01 = 0.f, a02 = 0.f, a03 = 0.f;
        float a10 = 0.f, a11 = 0.f, a12 = 0.f, a13 = 0.f;
#pragma unroll 4
        for (int j = 0; j < 64; ++j) {
            const float2 wv = *(const float2*)(Wlast + (j << 5) + 2 * cpair);
            const float4 av = *(const float4*)(sY2 + j * SROW + kk2);
            a00 = __fmaf_rn(av.x, wv.x, a00); a01 = __fmaf_rn(av.y, wv.x, a01);
            a02 = __fmaf_rn(av.z, wv.x, a02); a03 = __fmaf_rn(av.w, wv.x, a03);
            a10 = __fmaf_rn(av.x, wv.y, a10); a11 = __fmaf_rn(av.y, wv.y, a11);
            a12 = __fmaf_rn(av.z, wv.y, a12); a13 = __fmaf_rn(av.w, wv.y, a13);
        }
        const float t0 = sLastX[pq * 32 + 2 * cpair] + blast[2 * cpair];
        const float t1 = sLastX[pq * 32 + 2 * cpair + 1] + blast[2 * cpair + 1];
        const float mx0 = fmaxf(fmaxf(a00 + t0, a01 + t0), fmaxf(a02 + t0, a03 + t0));
        const float mx1 = fmaxf(fmaxf(a10 + t1, a11 + t1), fmaxf(a12 + t1, a13 + t1));
        sRed[kq * 32 + 2 * cpair] = mx0;
        sRed[kq * 32 + 2 * cpair + 1] = mx1;
    }
    __syncthreads();
    if (t < 128) {
        const int p = t >> 5;
        const int cc = t & 31;
        float mx = sRed[(p * 4 + 0) * 32 + cc];
        mx = fmaxf(mx, sRed[(p * 4 + 1) * 32 + cc]);
        mx = fmaxf(mx, sRed[(p * 4 + 2) * 32 + cc]);
        mx = fmaxf(mx, sRed[(p * 4 + 3) * 32 + cc]);
        out[(g0 + p) * 160 + cc] = mx;
    }
}

// ---------------------------------------------------------------------------
extern "C" void kernel_launch(void* const* d_in, const int* in_sizes, int n_in,
                              void* d_out, int out_size) {
    const float* x = (const float*)d_in[0];
    const float* pos = (const float*)d_in[1];
    const float* W1 = (const float*)d_in[2];
    const float* b1 = (const float*)d_in[3];
    const float* W2 = (const float*)d_in[4];
    const float* b2 = (const float*)d_in[5];
    const float* Wmid = (const float*)d_in[6];
    const float* bmid = (const float*)d_in[7];
    const float* Wg = (const float*)d_in[8];
    const float* bg = (const float*)d_in[9];
    const float* Wlast = (const float*)d_in[10];
    const float* blast = (const float*)d_in[11];
    float* out = (float*)d_out;

    const int smem_bytes = SMEM_U32 * 4;
    cudaFuncSetAttribute(conv_kernel, cudaFuncAttributeMaxDynamicSharedMemorySize,
                         smem_bytes);

    knn_prep_kernel<<<256 + 128, 128>>>(pos, W1, W2);
    conv_kernel<<<(Bb * Nn) / P4, 256, smem_bytes>>>(
        x, b1, W2, b2, Wmid, bmid, Wg, bg, Wlast, blast, out);
}

// round 12
// speedup vs baseline: 1.1172x; 1.0527x over previous
#include <cuda_runtime.h>
#include <cuda_bf16.h>

#define Bb 8
#define Nn 4096

typedef unsigned long long ull;
typedef unsigned int u32;

// scratch
__device__ int g_nbr[Bb * Nn * 16];
__device__ float g_W1p[64 * 256];       // W1[0:64] - W1[128:192] (x part, fp32)
__device__ uint4 g_W1f[4 * 32 * 32];    // W1n frag-packed bf16 hi/lo
__device__ uint4 g_W2f[16 * 4 * 32];    // W2 frag-packed bf16 hi/lo

// ---------------------------------------------------------------------------
__device__ __forceinline__ void split2(float a, float b, u32& hi, u32& lo) {
    __nv_bfloat16 ha = __float2bfloat16_rn(a);
    __nv_bfloat16 hb = __float2bfloat16_rn(b);
    hi = ((u32)__bfloat16_as_ushort(hb) << 16) | (u32)__bfloat16_as_ushort(ha);
    const float ra = a - __bfloat162float(ha);
    const float rb = b - __bfloat162float(hb);
    __nv_bfloat16 la = __float2bfloat16_rn(ra);
    __nv_bfloat16 lb = __float2bfloat16_rn(rb);
    lo = ((u32)__bfloat16_as_ushort(lb) << 16) | (u32)__bfloat16_as_ushort(la);
}

__device__ __forceinline__ void mma_bf16(float* d, u32 a0, u32 a1, u32 a2, u32 a3,
                                         u32 b0, u32 b1) {
    asm volatile(
        "mma.sync.aligned.m16n8k16.row.col.f32.bf16.bf16.f32 "
        "{%0,%1,%2,%3}, {%4,%5,%6,%7}, {%8,%9}, {%0,%1,%2,%3};"
        : "+f"(d[0]), "+f"(d[1]), "+f"(d[2]), "+f"(d[3])
        : "r"(a0), "r"(a1), "r"(a2), "r"(a3), "r"(b0), "r"(b1));
}

// ---------------------------------------------------------------------------
// Kernel 1: KNN (blocks 0..255, ballot-guarded predicated insert with tree
// argmax — identical selected set to the scalar version) + weight prep.
// ---------------------------------------------------------------------------
__global__ __launch_bounds__(128) void knn_prep_kernel(const float* __restrict__ pos,
                                                       const float* __restrict__ W1,
                                                       const float* __restrict__ W2) {
    const int bx = blockIdx.x;
    const int t = threadIdx.x;
    if (bx >= 256) {
        const int i = (bx - 256) * 128 + t;             // 0..16383
        {   // W1p (x-part, fp32)
            const int j = i >> 8;
            const int c = i & 255;
            g_W1p[i] = W1[j * 256 + c] - W1[(128 + j) * 256 + c];
        }
        if (i < 4096) {     // W1n frag pack: [kt 0..3][nt 0..31][lane]
            const int lane = i & 31;
            const int nt = (i >> 5) & 31;
            const int kt = i >> 10;
            const int j0 = kt * 16 + (lane & 3) * 2;
            const int n = nt * 8 + (lane >> 2);
            const float w00 = W1[(64 + j0) * 256 + n] + W1[(128 + j0) * 256 + n];
            const float w01 = W1[(64 + j0 + 1) * 256 + n] + W1[(128 + j0 + 1) * 256 + n];
            const float w10 = W1[(64 + j0 + 8) * 256 + n] + W1[(128 + j0 + 8) * 256 + n];
            const float w11 = W1[(64 + j0 + 9) * 256 + n] + W1[(128 + j0 + 9) * 256 + n];
            u32 h0, l0, h1, l1;
            split2(w00, w01, h0, l0);
            split2(w10, w11, h1, l1);
            g_W1f[i] = make_uint4(h0, h1, l0, l1);
        }
        if (i < 2048) {     // W2 frag pack: [kt 0..15][nt 0..3][lane]
            const int lane = i & 31;
            const int nt = (i >> 5) & 3;
            const int kt = i >> 7;
            const int j0 = kt * 16 + (lane & 3) * 2;
            const int n = nt * 8 + (lane >> 2);
            u32 h0, l0, h1, l1;
            split2(W2[j0 * 32 + n], W2[(j0 + 1) * 32 + n], h0, l0);
            split2(W2[(j0 + 8) * 32 + n], W2[(j0 + 9) * 32 + n], h1, l1);
            g_W2f[i] = make_uint4(h0, h1, l0, l1);
        }
        return;
    }

    const int b = bx >> 5;
    const int n = ((bx & 31) << 7) + t;

    const float qx = pos[(b * Nn + n) * 3 + 0];
    const float qy = pos[(b * Nn + n) * 3 + 1];
    const float qz = pos[(b * Nn + n) * 3 + 2];
    const float sqn = __fadd_rn(__fadd_rn(__fmul_rn(qx, qx), __fmul_rn(qy, qy)),
                                __fmul_rn(qz, qz));

    float bd[16];
    int bi[16];
#pragma unroll
    for (int j = 0; j < 16; ++j) { bd[j] = 3.0e38f; bi[j] = 0; }
    float worst = 3.0e38f;
    int wslot = 0;

    __shared__ float4 tile[1024];

    for (int t0 = 0; t0 < Nn; t0 += 1024) {
        __syncthreads();
        for (int i = t; i < 1024; i += 128) {
            const float px = pos[(b * Nn + t0 + i) * 3 + 0];
            const float py = pos[(b * Nn + t0 + i) * 3 + 1];
            const float pz = pos[(b * Nn + t0 + i) * 3 + 2];
            const float sq = __fadd_rn(__fadd_rn(__fmul_rn(px, px), __fmul_rn(py, py)),
                                       __fmul_rn(pz, pz));
            tile[i] = make_float4(px, py, pz, sq);
        }
        __syncthreads();
#pragma unroll 2
        for (int i = 0; i < 1024; ++i) {
            const float4 c = tile[i];
            const int m = t0 + i;
            float dot = __fmaf_rn(qx, c.x, 0.f);
            dot = __fmaf_rn(qy, c.y, dot);
            dot = __fmaf_rn(qz, c.z, dot);
            const float dist = __fsub_rn(__fadd_rn(sqn, c.w), __fmul_rn(2.0f, dot));
            const bool need = (dist < worst) && (m != n);
            if (__ballot_sync(0xffffffffu, need)) {
                // predicated slot write (no inner branch)
#pragma unroll
                for (int j = 0; j < 16; ++j) {
                    const bool take = need && (j == wslot);
                    bd[j] = take ? dist : bd[j];
                    bi[j] = take ? m : bi[j];
                }
                // balanced-tree argmax; >= prefers lower index on ties,
                // matching the original first-max-slot semantics exactly.
                float v0, v1, v2, v3, v4, v5, v6, v7;
                int s0, s1, s2, s3, s4, s5, s6, s7;
                v0 = (bd[0] >= bd[1]) ? bd[0] : bd[1];
                s0 = (bd[0] >= bd[1]) ? 0 : 1;
                v1 = (bd[2] >= bd[3]) ? bd[2] : bd[3];
                s1 = (bd[2] >= bd[3]) ? 2 : 3;
                v2 = (bd[4] >= bd[5]) ? bd[4] : bd[5];
                s2 = (bd[4] >= bd[5]) ? 4 : 5;
                v3 = (bd[6] >= bd[7]) ? bd[6] : bd[7];
                s3 = (bd[6] >= bd[7]) ? 6 : 7;
                v4 = (bd[8] >= bd[9]) ? bd[8] : bd[9];
                s4 = (bd[8] >= bd[9]) ? 8 : 9;
                v5 = (bd[10] >= bd[11]) ? bd[10] : bd[11];
                s5 = (bd[10] >= bd[11]) ? 10 : 11;
                v6 = (bd[12] >= bd[13]) ? bd[12] : bd[13];
                s6 = (bd[12] >= bd[13]) ? 12 : 13;
                v7 = (bd[14] >= bd[15]) ? bd[14] : bd[15];
                s7 = (bd[14] >= bd[15]) ? 14 : 15;
                s0 = (v0 >= v1) ? s0 : s1;  v0 = (v0 >= v1) ? v0 : v1;
                s2 = (v2 >= v3) ? s2 : s3;  v2 = (v2 >= v3) ? v2 : v3;
                s4 = (v4 >= v5) ? s4 : s5;  v4 = (v4 >= v5) ? v4 : v5;
                s6 = (v6 >= v7) ? s6 : s7;  v6 = (v6 >= v7) ? v6 : v7;
                s0 = (v0 >= v2) ? s0 : s2;  v0 = (v0 >= v2) ? v0 : v2;
                s4 = (v4 >= v6) ? s4 : s6;  v4 = (v4 >= v6) ? v4 : v6;
                wslot = (v0 >= v4) ? s0 : s4;
                worst = (v0 >= v4) ? v0 : v4;
            }
        }
    }

#pragma unroll
    for (int j = 0; j < 16; ++j)
        g_nbr[(b * Nn + n) * 16 + j] = bi[j];
}

// ---------------------------------------------------------------------------
// Kernel 2: fused DenseEdgeConv (unchanged from round 11; conv=~798us).
// ---------------------------------------------------------------------------
#define P4 4
#define SROW 68

#define OFF_AHI   0
#define OFF_ALO   (OFF_AHI + 64 * 36)
#define OFF_Y2    0
#define OFF_HHI   (OFF_ALO + 64 * 36)
#define OFF_HLO   (OFF_HHI + 64 * 68)
#define OFF_XH    (OFF_HLO + 64 * 68)
#define OFF_XN    (OFF_XH + P4 * 256)
#define OFF_MIDX  (OFF_XN + P4 * 64)
#define OFF_XG    (OFF_MIDX + P4 * 32)
#define OFF_YBAR  (OFF_XG + P4 * 64)
#define OFF_GATE  (OFF_YBAR + P4 * 64)
#define OFF_LASTX (OFF_GATE + P4 * 128)
#define OFF_NID   (OFF_LASTX + P4 * 32)
#define SMEM_U32  (OFF_NID + 64)

__global__ __launch_bounds__(256, 2) void conv_kernel(
    const float* __restrict__ x,
    const float* __restrict__ b1,
    const float* __restrict__ W2, const float* __restrict__ b2,
    const float* __restrict__ Wmid, const float* __restrict__ bmid,
    const float* __restrict__ Wg, const float* __restrict__ bg,
    const float* __restrict__ Wlast, const float* __restrict__ blast,
    float* __restrict__ out)
{
    extern __shared__ float sm[];
    u32* sAhi = (u32*)sm + OFF_AHI;
    u32* sAlo = (u32*)sm + OFF_ALO;
    u32* sHhi = (u32*)sm + OFF_HHI;
    u32* sHlo = (u32*)sm + OFF_HLO;
    float* sY2 = sm + OFF_Y2;
    float* sXh = sm + OFF_XH;
    float* sXn = sm + OFF_XN;
    float* sMidX = sm + OFF_MIDX;
    float* sXg = sm + OFF_XG;
    float* sYbar = sm + OFF_YBAR;
    float* sGate = sm + OFF_GATE;
    float* sLastX = sm + OFF_LASTX;
    int* sNid = (int*)((u32*)sm + OFF_NID);

    const int t = threadIdx.x;
    const int g0 = blockIdx.x * P4;
    const int b = g0 >> 12;

    sXn[t] = x[(g0 + (t >> 6)) * 64 + (t & 63)];
    if (t < 64) sNid[t] = g_nbr[g0 * 16 + t];
    __syncthreads();

#pragma unroll
    for (int it = 0; it < 4; ++it) {
        const int idx = it * 256 + t;
        const int kk = idx >> 4;
        const int c4 = (idx & 15) << 2;
        const float4 v = *(const float4*)(x + (b * Nn + sNid[kk]) * 64 + c4);
        u32 h0, l0, h1, l1;
        split2(v.x, v.y, h0, l0);
        split2(v.z, v.w, h1, l1);
        const int base = kk * 36 + (c4 >> 1);
        sAhi[base] = h0; sAhi[base + 1] = h1;
        sAlo[base] = l0; sAlo[base + 1] = l1;
    }
    if (t < 128) {
        const int c0 = t;
        float a[4][2];
#pragma unroll
        for (int p = 0; p < 4; ++p) { a[p][0] = 0.f; a[p][1] = 0.f; }
#pragma unroll 4
        for (int j = 0; j < 64; ++j) {
            const float w0 = g_W1p[j * 256 + c0];
            const float w1 = g_W1p[j * 256 + c0 + 128];
#pragma unroll
            for (int p = 0; p < 4; ++p) {
                const float xv = sXn[p * 64 + j];
                a[p][0] = __fmaf_rn(xv, w0, a[p][0]);
                a[p][1] = __fmaf_rn(xv, w1, a[p][1]);
            }
        }
        const float bb0 = b1[c0];
        const float bb1 = b1[c0 + 128];
#pragma unroll
        for (int p = 0; p < 4; ++p) {
            sXh[p * 256 + c0] = a[p][0] + bb0;
            sXh[p * 256 + c0 + 128] = a[p][1] + bb1;
        }
    } else {
        const int p = (t >> 5) & 3;
        const int c = t & 31;
        float a = 0.f;
#pragma unroll 4
        for (int j = 0; j < 64; ++j)
            a = __fmaf_rn(sXn[p * 64 + j], Wmid[(32 + j) * 32 + c], a);
        sMidX[p * 32 + c] = a;
    }
    __syncthreads();

    const int lane = t & 31;
    const int w = t >> 5;
    const int mt = w & 3;
    const int nhw = w >> 2;
    const int lt = lane & 3;
    const int lg = lane >> 2;

    float d2[2][4];
#pragma unroll
    for (int q = 0; q < 2; ++q)
#pragma unroll
        for (int r = 0; r < 4; ++r) d2[q][r] = 0.f;

#pragma unroll
    for (int h = 0; h < 2; ++h) {
        float d1[8][4];
#pragma unroll
        for (int nt = 0; nt < 8; ++nt)
#pragma unroll
            for (int r = 0; r < 4; ++r) d1[nt][r] = 0.f;

#pragma unroll
        for (int kt = 0; kt < 4; ++kt) {
            const int abase = (mt * 16 + lg) * 36 + kt * 8 + lt;
            const u32 ah0 = sAhi[abase];
            const u32 ah1 = sAhi[abase + 8 * 36];
            const u32 ah2 = sAhi[abase + 4];
            const u32 ah3 = sAhi[abase + 8 * 36 + 4];
            const u32 al0 = sAlo[abase];
            const u32 al1 = sAlo[abase + 8 * 36];
            const u32 al2 = sAlo[abase + 4];
            const u32 al3 = sAlo[abase + 8 * 36 + 4];
#pragma unroll
            for (int nt = 0; nt < 8; ++nt) {
                const int ntg = h * 16 + nhw * 8 + nt;
                const uint4 bb = g_W1f[((kt * 32 + ntg) << 5) + lane];
                mma_bf16(d1[nt], ah0, ah1, ah2, ah3, bb.x, bb.y);
                mma_bf16(d1[nt], ah0, ah1, ah2, ah3, bb.z, bb.w);
                mma_bf16(d1[nt], al0, al1, al2, al3, bb.x, bb.y);
            }
        }
#pragma unroll
        for (int nt = 0; nt < 8; ++nt) {
            const int ntg = h * 16 + nhw * 8 + nt;
            const int c0 = ntg * 8 + 2 * lt;
            const float xh0 = sXh[mt * 256 + c0];
            const float xh1 = sXh[mt * 256 + c0 + 1];
            const float v0 = fmaxf(d1[nt][0] + xh0, 0.f);
            const float v1 = fmaxf(d1[nt][1] + xh1, 0.f);
            const float v2 = fmaxf(d1[nt][2] + xh0, 0.f);
            const float v3 = fmaxf(d1[nt][3] + xh1, 0.f);
            u32 h01, l01, h23, l23;
            split2(v0, v1, h01, l01);
            split2(v2, v3, h23, l23);
            const int pair = (nhw * 8 + nt) * 4 + lt;
            const int r0 = mt * 16 + lg;
            sHhi[r0 * 68 + pair] = h01;
            sHhi[(r0 + 8) * 68 + pair] = h23;
            sHlo[r0 * 68 + pair] = l01;
            sHlo[(r0 + 8) * 68 + pair] = l23;
        }
        __syncthreads();

#pragma unroll
        for (int ktl = 0; ktl < 8; ++ktl) {
            const int hbase = (mt * 16 + lg) * 68 + ktl * 8 + lt;
            const u32 ah0 = sHhi[hbase];
            const u32 ah1 = sHhi[hbase + 8 * 68];
            const u32 ah2 = sHhi[hbase + 4];
            const u32 ah3 = sHhi[hbase + 8 * 68 + 4];
            const u32 al0 = sHlo[hbase];
            const u32 al1 = sHlo[hbase + 8 * 68];
            const u32 al2 = sHlo[hbase + 4];
            const u32 al3 = sHlo[hbase + 8 * 68 + 4];
            const int ktg = h * 8 + ktl;
#pragma unroll
            for (int q = 0; q < 2; ++q) {
                const int nt2 = nhw * 2 + q;
                const uint4 bb = g_W2f[((ktg * 4 + nt2) << 5) + lane];
                mma_bf16(d2[q], ah0, ah1, ah2, ah3, bb.x, bb.y);
                mma_bf16(d2[q], ah0, ah1, ah2, ah3, bb.z, bb.w);
                mma_bf16(d2[q], al0, al1, al2, al3, bb.x, bb.y);
            }
        }
        __syncthreads();
    }

#pragma unroll
    for (int q = 0; q < 2; ++q) {
        const int nt2 = nhw * 2 + q;
        const int c0 = nt2 * 8 + 2 * lt;
        const int kk0 = mt * 16 + lg;
        const float bb0 = b2[c0];
        const float bb1 = b2[c0 + 1];
        sY2[(32 + c0) * SROW + kk0] = fmaxf(d2[q][0] + bb0, 0.f);
        sY2[(33 + c0) * SROW + kk0] = fmaxf(d2[q][1] + bb1, 0.f);
        sY2[(32 + c0) * SROW + kk0 + 8] = fmaxf(d2[q][2] + bb0, 0.f);
        sY2[(33 + c0) * SROW + kk0 + 8] = fmaxf(d2[q][3] + bb1, 0.f);
    }
    __syncthreads();

    const int cpair = t & 15;
    const int kq = t >> 4;
    const int kk2 = kq << 2;
    const int pq = kq >> 2;

    {   // mid
        float a00 = 0.f, a01 = 0.f, a02 = 0.f, a03 = 0.f;
        float a10 = 0.f, a11 = 0.f, a12 = 0.f, a13 = 0.f;
#pragma unroll 4
        for (int j = 0; j < 32; ++j) {
            const float2 wv = *(const float2*)(Wmid + (j << 5) + 2 * cpair);
            const float4 av = *(const float4*)(sY2 + (32 + j) * SROW + kk2);
            a00 = __fmaf_rn(av.x, wv.x, a00); a01 = __fmaf_rn(av.y, wv.x, a01);
            a02 = __fmaf_rn(av.z, wv.x, a02); a03 = __fmaf_rn(av.w, wv.x, a03);
            a10 = __fmaf_rn(av.x, wv.y, a10); a11 = __fmaf_rn(av.y, wv.y, a11);
            a12 = __fmaf_rn(av.z, wv.y, a12); a13 = __fmaf_rn(av.w, wv.y, a13);
        }
        const float bx0 = sMidX[pq * 32 + 2 * cpair] + bmid[2 * cpair];
        const float bx1 = sMidX[pq * 32 + 2 * cpair + 1] + bmid[2 * cpair + 1];
        float4 r0, r1;
        r0.x = fmaxf(a00 + bx0, 0.f); r0.y = fmaxf(a01 + bx0, 0.f);
        r0.z = fmaxf(a02 + bx0, 0.f); r0.w = fmaxf(a03 + bx0, 0.f);
        r1.x = fmaxf(a10 + bx1, 0.f); r1.y = fmaxf(a11 + bx1, 0.f);
        r1.z = fmaxf(a12 + bx1, 0.f); r1.w = fmaxf(a13 + bx1, 0.f);
        *(float4*)(sY2 + (2 * cpair) * SROW + kk2) = r0;
        *(float4*)(sY2 + (2 * cpair + 1) * SROW + kk2) = r1;
    }
    __syncthreads();

    {   // ybar
        const int jj = t & 63;
        const int pp = t >> 6;
        const float* row = sY2 + jj * SROW + pp * 16;
        const float4 s0 = *(const float4*)(row + 0);
        const float4 s1 = *(const float4*)(row + 4);
        const float4 s2 = *(const float4*)(row + 8);
        const float4 s3 = *(const float4*)(row + 12);
        const float s = (s0.x + s0.y + s0.z + s0.w) + (s1.x + s1.y + s1.z + s1.w)
                      + (s2.x + s2.y + s2.z + s2.w) + (s3.x + s3.y + s3.z + s3.w);
        sYbar[pp * 64 + jj] = s * (1.0f / 16.0f);
    }
    __syncthreads();

    {   // gate (all 256 threads)
        const int c2g = (t & 63) * 2;
        const int pg = t >> 6;
        float a0 = 0.f, a1 = 0.f;
#pragma unroll 4
        for (int j = 0; j < 128; ++j) {
            const float2 wv = *(const float2*)(Wg + j * 128 + c2g);
            const float y = (j < 64) ? sYbar[pg * 64 + j] : sXn[pg * 64 + j - 64];
            a0 = __fmaf_rn(y, wv.x, a0);
            a1 = __fmaf_rn(y, wv.y, a1);
        }
        sGate[pg * 128 + c2g] = 1.0f / (1.0f + expf(-(a0 + bg[c2g])));
        sGate[pg * 128 + c2g + 1] = 1.0f / (1.0f + expf(-(a1 + bg[c2g + 1])));
    }
    __syncthreads();

    {   // xg; out 96..159
        const int c = t & 63;
        const int p = t >> 6;
        const float xg = sXn[p * 64 + c] * sGate[p * 128 + 64 + c];
        sXg[p * 64 + c] = xg;
        out[(g0 + p) * 160 + 96 + c] = xg;
    }
    __syncthreads();

    {   // y2 *= gate; out 32..95
        const int jj = t & 63;
        const int pp = t >> 6;
        const float gv = sGate[pp * 128 + jj];
        float* row = sY2 + jj * SROW + pp * 16;
        float mx = -3.0e38f;
#pragma unroll
        for (int q = 0; q < 4; ++q) {
            float4 v = *(const float4*)(row + 4 * q);
            v.x *= gv; v.y *= gv; v.z *= gv; v.w *= gv;
            mx = fmaxf(mx, fmaxf(fmaxf(v.x, v.y), fmaxf(v.z, v.w)));
            *(float4*)(row + 4 * q) = v;
        }
        out[(g0 + pp) * 160 + 32 + jj] = mx;
    }
    if (t < 128) {  // last_x
        const int p = t >> 5;
        const int c = t & 31;
        float a = 0.f;
#pragma unroll 4
        for (int j = 0; j < 64; ++j)
            a = __fmaf_rn(sXg[p * 64 + j], Wlast[(64 + j) * 32 + c], a);
        sLastX[p * 32 + c] = a;
    }
    __syncthreads();

    float* sRed = sXh;
    {   // last: out 0..31
        float a00 = 0.f, a01 = 0.f, a02 = 0.f, a03 = 0.f;
        float a10 = 0.f, a11 = 0.f, a12 = 0.f, a13 = 0.f;
#pragma unroll 4
        for (int j = 0; j < 64; ++j) {
            const float2 wv = *(const float2*)(Wlast + (j << 5) + 2 * cpair);
            const float4 av = *(const float4*)(sY2 + j * SROW + kk2);
            a00 = __fmaf_rn(av.x, wv.x, a00); a01 = __fmaf_rn(av.y, wv.x, a01);
            a02 = __fmaf_rn(av.z, wv.x, a02); a03 = __fmaf_rn(av.w, wv.x, a03);
            a10 = __fmaf_rn(av.x, wv.y, a10); a11 = __fmaf_rn(av.y, wv.y, a11);
            a12 = __fmaf_rn(av.z, wv.y, a12); a13 = __fmaf_rn(av.w, wv.y, a13);
        }
        const float t0 = sLastX[pq * 32 + 2 * cpair] + blast[2 * cpair];
        const float t1 = sLastX[pq * 32 + 2 * cpair + 1] + blast[2 * cpair + 1];
        const float mx0 = fmaxf(fmaxf(a00 + t0, a01 + t0), fmaxf(a02 + t0, a03 + t0));
        const float mx1 = fmaxf(fmaxf(a10 + t1, a11 + t1), fmaxf(a12 + t1, a13 + t1));
        sRed[kq * 32 + 2 * cpair] = mx0;
        sRed[kq * 32 + 2 * cpair + 1] = mx1;
    }
    __syncthreads();
    if (t < 128) {
        const int p = t >> 5;
        const int cc = t & 31;
        float mx = sRed[(p * 4 + 0) * 32 + cc];
        mx = fmaxf(mx, sRed[(p * 4 + 1) * 32 + cc]);
        mx = fmaxf(mx, sRed[(p * 4 + 2) * 32 + cc]);
        mx = fmaxf(mx, sRed[(p * 4 + 3) * 32 + cc]);
        out[(g0 + p) * 160 + cc] = mx;
    }
}

// ---------------------------------------------------------------------------
extern "C" void kernel_launch(void* const* d_in, const int* in_sizes, int n_in,
                              void* d_out, int out_size) {
    const float* x = (const float*)d_in[0];
    const float* pos = (const float*)d_in[1];
    const float* W1 = (const float*)d_in[2];
    const float* b1 = (const float*)d_in[3];
    const float* W2 = (const float*)d_in[4];
    const float* b2 = (const float*)d_in[5];
    const float* Wmid = (const float*)d_in[6];
    const float* bmid = (const float*)d_in[7];
    const float* Wg = (const float*)d_in[8];
    const float* bg = (const float*)d_in[9];
    const float* Wlast = (const float*)d_in[10];
    const float* blast = (const float*)d_in[11];
    float* out = (float*)d_out;

    const int smem_bytes = SMEM_U32 * 4;
    cudaFuncSetAttribute(conv_kernel, cudaFuncAttributeMaxDynamicSharedMemorySize,
                         smem_bytes);

    knn_prep_kernel<<<256 + 128, 128>>>(pos, W1, W2);
    conv_kernel<<<(Bb * Nn) / P4, 256, smem_bytes>>>(
        x, b1, W2, b2, Wmid, bmid, Wg, bg, Wlast, blast, out);
}

// round 13
// speedup vs baseline: 1.2807x; 1.1464x over previous
#include <cuda_runtime.h>
#include <cuda_bf16.h>

#define Bb 8
#define Nn 4096

typedef unsigned long long ull;
typedef unsigned int u32;

// scratch
__device__ int g_nbr[Bb * Nn * 16];
__device__ float g_W1p[64 * 256];       // W1[0:64] - W1[128:192] (x part, fp32)
__device__ uint4 g_W1f[4 * 32 * 32];    // W1n frag-packed bf16 hi/lo
__device__ uint4 g_W2f[16 * 4 * 32];    // W2 frag-packed bf16 hi/lo

// ---------------------------------------------------------------------------
__device__ __forceinline__ ull pack2(float a, float b) {
    ull r;
    asm("mov.b64 %0, {%1, %2};" : "=l"(r) : "f"(a), "f"(b));
    return r;
}
__device__ __forceinline__ ull fma2(ull a, ull b, ull c) {
    ull d;
    asm("fma.rn.f32x2 %0, %1, %2, %3;" : "=l"(d) : "l"(a), "l"(b), "l"(c));
    return d;
}
__device__ __forceinline__ float2 unpack2(ull v) {
    float2 f;
    asm("mov.b64 {%0, %1}, %2;" : "=f"(f.x), "=f"(f.y) : "l"(v));
    return f;
}

// split (a,b) into bf16x2 hi + bf16x2 lo residual. hi lane-lo = bf16(a).
// cvt.rn.bf16x2.f32 rounds each half RN — identical to __float2bfloat16_rn.
__device__ __forceinline__ void split2(float a, float b, u32& hi, u32& lo) {
    u32 h;
    asm("cvt.rn.bf16x2.f32 %0, %1, %2;" : "=r"(h) : "f"(b), "f"(a));
    const float fa = __uint_as_float(h << 16);
    const float fb = __uint_as_float(h & 0xffff0000u);
    const float ra = a - fa;
    const float rb = b - fb;
    u32 l;
    asm("cvt.rn.bf16x2.f32 %0, %1, %2;" : "=r"(l) : "f"(rb), "f"(ra));
    hi = h;
    lo = l;
}

__device__ __forceinline__ void mma_bf16(float* d, u32 a0, u32 a1, u32 a2, u32 a3,
                                         u32 b0, u32 b1) {
    asm volatile(
        "mma.sync.aligned.m16n8k16.row.col.f32.bf16.bf16.f32 "
        "{%0,%1,%2,%3}, {%4,%5,%6,%7}, {%8,%9}, {%0,%1,%2,%3};"
        : "+f"(d[0]), "+f"(d[1]), "+f"(d[2]), "+f"(d[3])
        : "r"(a0), "r"(a1), "r"(a2), "r"(a3), "r"(b0), "r"(b1));
}

// ---------------------------------------------------------------------------
// Kernel 1: KNN (blocks 0..255, ballot-guarded predicated insert with tree
// argmax) + weight prep (blocks 256..383). Unchanged from round 12.
// ---------------------------------------------------------------------------
__global__ __launch_bounds__(128) void knn_prep_kernel(const float* __restrict__ pos,
                                                       const float* __restrict__ W1,
                                                       const float* __restrict__ W2) {
    const int bx = blockIdx.x;
    const int t = threadIdx.x;
    if (bx >= 256) {
        const int i = (bx - 256) * 128 + t;             // 0..16383
        {   // W1p (x-part, fp32)
            const int j = i >> 8;
            const int c = i & 255;
            g_W1p[i] = W1[j * 256 + c] - W1[(128 + j) * 256 + c];
        }
        if (i < 4096) {     // W1n frag pack: [kt 0..3][nt 0..31][lane]
            const int lane = i & 31;
            const int nt = (i >> 5) & 31;
            const int kt = i >> 10;
            const int j0 = kt * 16 + (lane & 3) * 2;
            const int n = nt * 8 + (lane >> 2);
            const float w00 = W1[(64 + j0) * 256 + n] + W1[(128 + j0) * 256 + n];
            const float w01 = W1[(64 + j0 + 1) * 256 + n] + W1[(128 + j0 + 1) * 256 + n];
            const float w10 = W1[(64 + j0 + 8) * 256 + n] + W1[(128 + j0 + 8) * 256 + n];
            const float w11 = W1[(64 + j0 + 9) * 256 + n] + W1[(128 + j0 + 9) * 256 + n];
            u32 h0, l0, h1, l1;
            split2(w00, w01, h0, l0);
            split2(w10, w11, h1, l1);
            g_W1f[i] = make_uint4(h0, h1, l0, l1);
        }
        if (i < 2048) {     // W2 frag pack: [kt 0..15][nt 0..3][lane]
            const int lane = i & 31;
            const int nt = (i >> 5) & 3;
            const int kt = i >> 7;
            const int j0 = kt * 16 + (lane & 3) * 2;
            const int n = nt * 8 + (lane >> 2);
            u32 h0, l0, h1, l1;
            split2(W2[j0 * 32 + n], W2[(j0 + 1) * 32 + n], h0, l0);
            split2(W2[(j0 + 8) * 32 + n], W2[(j0 + 9) * 32 + n], h1, l1);
            g_W2f[i] = make_uint4(h0, h1, l0, l1);
        }
        return;
    }

    const int b = bx >> 5;
    const int n = ((bx & 31) << 7) + t;

    const float qx = pos[(b * Nn + n) * 3 + 0];
    const float qy = pos[(b * Nn + n) * 3 + 1];
    const float qz = pos[(b * Nn + n) * 3 + 2];
    const float sqn = __fadd_rn(__fadd_rn(__fmul_rn(qx, qx), __fmul_rn(qy, qy)),
                                __fmul_rn(qz, qz));

    float bd[16];
    int bi[16];
#pragma unroll
    for (int j = 0; j < 16; ++j) { bd[j] = 3.0e38f; bi[j] = 0; }
    float worst = 3.0e38f;
    int wslot = 0;

    __shared__ float4 tile[1024];

    for (int t0 = 0; t0 < Nn; t0 += 1024) {
        __syncthreads();
        for (int i = t; i < 1024; i += 128) {
            const float px = pos[(b * Nn + t0 + i) * 3 + 0];
            const float py = pos[(b * Nn + t0 + i) * 3 + 1];
            const float pz = pos[(b * Nn + t0 + i) * 3 + 2];
            const float sq = __fadd_rn(__fadd_rn(__fmul_rn(px, px), __fmul_rn(py, py)),
                                       __fmul_rn(pz, pz));
            tile[i] = make_float4(px, py, pz, sq);
        }
        __syncthreads();
#pragma unroll 2
        for (int i = 0; i < 1024; ++i) {
            const float4 c = tile[i];
            const int m = t0 + i;
            float dot = __fmaf_rn(qx, c.x, 0.f);
            dot = __fmaf_rn(qy, c.y, dot);
            dot = __fmaf_rn(qz, c.z, dot);
            const float dist = __fsub_rn(__fadd_rn(sqn, c.w), __fmul_rn(2.0f, dot));
            const bool need = (dist < worst) && (m != n);
            if (__ballot_sync(0xffffffffu, need)) {
#pragma unroll
                for (int j = 0; j < 16; ++j) {
                    const bool take = need && (j == wslot);
                    bd[j] = take ? dist : bd[j];
                    bi[j] = take ? m : bi[j];
                }
                float v0, v1, v2, v3, v4, v5, v6, v7;
                int s0, s1, s2, s3, s4, s5, s6, s7;
                v0 = (bd[0] >= bd[1]) ? bd[0] : bd[1];
                s0 = (bd[0] >= bd[1]) ? 0 : 1;
                v1 = (bd[2] >= bd[3]) ? bd[2] : bd[3];
                s1 = (bd[2] >= bd[3]) ? 2 : 3;
                v2 = (bd[4] >= bd[5]) ? bd[4] : bd[5];
                s2 = (bd[4] >= bd[5]) ? 4 : 5;
                v3 = (bd[6] >= bd[7]) ? bd[6] : bd[7];
                s3 = (bd[6] >= bd[7]) ? 6 : 7;
                v4 = (bd[8] >= bd[9]) ? bd[8] : bd[9];
                s4 = (bd[8] >= bd[9]) ? 8 : 9;
                v5 = (bd[10] >= bd[11]) ? bd[10] : bd[11];
                s5 = (bd[10] >= bd[11]) ? 10 : 11;
                v6 = (bd[12] >= bd[13]) ? bd[12] : bd[13];
                s6 = (bd[12] >= bd[13]) ? 12 : 13;
                v7 = (bd[14] >= bd[15]) ? bd[14] : bd[15];
                s7 = (bd[14] >= bd[15]) ? 14 : 15;
                s0 = (v0 >= v1) ? s0 : s1;  v0 = (v0 >= v1) ? v0 : v1;
                s2 = (v2 >= v3) ? s2 : s3;  v2 = (v2 >= v3) ? v2 : v3;
                s4 = (v4 >= v5) ? s4 : s5;  v4 = (v4 >= v5) ? v4 : v5;
                s6 = (v6 >= v7) ? s6 : s7;  v6 = (v6 >= v7) ? v6 : v7;
                s0 = (v0 >= v2) ? s0 : s2;  v0 = (v0 >= v2) ? v0 : v2;
                s4 = (v4 >= v6) ? s4 : s6;  v4 = (v4 >= v6) ? v4 : v6;
                wslot = (v0 >= v4) ? s0 : s4;
                worst = (v0 >= v4) ? v0 : v4;
            }
        }
    }

#pragma unroll
    for (int j = 0; j < 16; ++j)
        g_nbr[(b * Nn + n) * 16 + j] = bi[j];
}

// ---------------------------------------------------------------------------
// Kernel 2: fused DenseEdgeConv. Tensor-core GEMM1/GEMM2; scalar tail now
// f32x2-packed with unroll 8 (bit-identical accumulation chains).
// ---------------------------------------------------------------------------
#define P4 4
#define SROW 68

#define OFF_AHI   0
#define OFF_ALO   (OFF_AHI + 64 * 36)
#define OFF_Y2    0
#define OFF_HHI   (OFF_ALO + 64 * 36)
#define OFF_HLO   (OFF_HHI + 64 * 68)
#define OFF_XH    (OFF_HLO + 64 * 68)
#define OFF_XN    (OFF_XH + P4 * 256)
#define OFF_MIDX  (OFF_XN + P4 * 64)
#define OFF_XG    (OFF_MIDX + P4 * 32)
#define OFF_YBAR  (OFF_XG + P4 * 64)
#define OFF_GATE  (OFF_YBAR + P4 * 64)
#define OFF_LASTX (OFF_GATE + P4 * 128)
#define OFF_NID   (OFF_LASTX + P4 * 32)
#define SMEM_U32  (OFF_NID + 64)

__global__ __launch_bounds__(256, 2) void conv_kernel(
    const float* __restrict__ x,
    const float* __restrict__ b1,
    const float* __restrict__ W2, const float* __restrict__ b2,
    const float* __restrict__ Wmid, const float* __restrict__ bmid,
    const float* __restrict__ Wg, const float* __restrict__ bg,
    const float* __restrict__ Wlast, const float* __restrict__ blast,
    float* __restrict__ out)
{
    extern __shared__ float sm[];
    u32* sAhi = (u32*)sm + OFF_AHI;
    u32* sAlo = (u32*)sm + OFF_ALO;
    u32* sHhi = (u32*)sm + OFF_HHI;
    u32* sHlo = (u32*)sm + OFF_HLO;
    float* sY2 = sm + OFF_Y2;
    float* sXh = sm + OFF_XH;
    float* sXn = sm + OFF_XN;
    float* sMidX = sm + OFF_MIDX;
    float* sXg = sm + OFF_XG;
    float* sYbar = sm + OFF_YBAR;
    float* sGate = sm + OFF_GATE;
    float* sLastX = sm + OFF_LASTX;
    int* sNid = (int*)((u32*)sm + OFF_NID);

    const int t = threadIdx.x;
    const int g0 = blockIdx.x * P4;
    const int b = g0 >> 12;

    sXn[t] = x[(g0 + (t >> 6)) * 64 + (t & 63)];
    if (t < 64) sNid[t] = g_nbr[g0 * 16 + t];
    __syncthreads();

#pragma unroll
    for (int it = 0; it < 4; ++it) {
        const int idx = it * 256 + t;
        const int kk = idx >> 4;
        const int c4 = (idx & 15) << 2;
        const float4 v = *(const float4*)(x + (b * Nn + sNid[kk]) * 64 + c4);
        u32 h0, l0, h1, l1;
        split2(v.x, v.y, h0, l0);
        split2(v.z, v.w, h1, l1);
        const int base = kk * 36 + (c4 >> 1);
        sAhi[base] = h0; sAhi[base + 1] = h1;
        sAlo[base] = l0; sAlo[base + 1] = l1;
    }
    if (t < 128) {
        const int c0 = t;
        float a[4][2];
#pragma unroll
        for (int p = 0; p < 4; ++p) { a[p][0] = 0.f; a[p][1] = 0.f; }
#pragma unroll 4
        for (int j = 0; j < 64; ++j) {
            const float w0 = g_W1p[j * 256 + c0];
            const float w1 = g_W1p[j * 256 + c0 + 128];
#pragma unroll
            for (int p = 0; p < 4; ++p) {
                const float xv = sXn[p * 64 + j];
                a[p][0] = __fmaf_rn(xv, w0, a[p][0]);
                a[p][1] = __fmaf_rn(xv, w1, a[p][1]);
            }
        }
        const float bb0 = b1[c0];
        const float bb1 = b1[c0 + 128];
#pragma unroll
        for (int p = 0; p < 4; ++p) {
            sXh[p * 256 + c0] = a[p][0] + bb0;
            sXh[p * 256 + c0 + 128] = a[p][1] + bb1;
        }
    } else {
        const int p = (t >> 5) & 3;
        const int c = t & 31;
        float a = 0.f;
#pragma unroll 4
        for (int j = 0; j < 64; ++j)
            a = __fmaf_rn(sXn[p * 64 + j], Wmid[(32 + j) * 32 + c], a);
        sMidX[p * 32 + c] = a;
    }
    __syncthreads();

    const int lane = t & 31;
    const int w = t >> 5;
    const int mt = w & 3;
    const int nhw = w >> 2;
    const int lt = lane & 3;
    const int lg = lane >> 2;

    float d2[2][4];
#pragma unroll
    for (int q = 0; q < 2; ++q)
#pragma unroll
        for (int r = 0; r < 4; ++r) d2[q][r] = 0.f;

#pragma unroll
    for (int h = 0; h < 2; ++h) {
        float d1[8][4];
#pragma unroll
        for (int nt = 0; nt < 8; ++nt)
#pragma unroll
            for (int r = 0; r < 4; ++r) d1[nt][r] = 0.f;

#pragma unroll
        for (int kt = 0; kt < 4; ++kt) {
            const int abase = (mt * 16 + lg) * 36 + kt * 8 + lt;
            const u32 ah0 = sAhi[abase];
            const u32 ah1 = sAhi[abase + 8 * 36];
            const u32 ah2 = sAhi[abase + 4];
            const u32 ah3 = sAhi[abase + 8 * 36 + 4];
            const u32 al0 = sAlo[abase];
            const u32 al1 = sAlo[abase + 8 * 36];
            const u32 al2 = sAlo[abase + 4];
            const u32 al3 = sAlo[abase + 8 * 36 + 4];
#pragma unroll
            for (int nt = 0; nt < 8; ++nt) {
                const int ntg = h * 16 + nhw * 8 + nt;
                const uint4 bb = g_W1f[((kt * 32 + ntg) << 5) + lane];
                mma_bf16(d1[nt], ah0, ah1, ah2, ah3, bb.x, bb.y);
                mma_bf16(d1[nt], ah0, ah1, ah2, ah3, bb.z, bb.w);
                mma_bf16(d1[nt], al0, al1, al2, al3, bb.x, bb.y);
            }
        }
#pragma unroll
        for (int nt = 0; nt < 8; ++nt) {
            const int ntg = h * 16 + nhw * 8 + nt;
            const int c0 = ntg * 8 + 2 * lt;
            const float xh0 = sXh[mt * 256 + c0];
            const float xh1 = sXh[mt * 256 + c0 + 1];
            const float v0 = fmaxf(d1[nt][0] + xh0, 0.f);
            const float v1 = fmaxf(d1[nt][1] + xh1, 0.f);
            const float v2 = fmaxf(d1[nt][2] + xh0, 0.f);
            const float v3 = fmaxf(d1[nt][3] + xh1, 0.f);
            u32 h01, l01, h23, l23;
            split2(v0, v1, h01, l01);
            split2(v2, v3, h23, l23);
            const int pair = (nhw * 8 + nt) * 4 + lt;
            const int r0 = mt * 16 + lg;
            sHhi[r0 * 68 + pair] = h01;
            sHhi[(r0 + 8) * 68 + pair] = h23;
            sHlo[r0 * 68 + pair] = l01;
            sHlo[(r0 + 8) * 68 + pair] = l23;
        }
        __syncthreads();

#pragma unroll
        for (int ktl = 0; ktl < 8; ++ktl) {
            const int hbase = (mt * 16 + lg) * 68 + ktl * 8 + lt;
            const u32 ah0 = sHhi[hbase];
            const u32 ah1 = sHhi[hbase + 8 * 68];
            const u32 ah2 = sHhi[hbase + 4];
            const u32 ah3 = sHhi[hbase + 8 * 68 + 4];
            const u32 al0 = sHlo[hbase];
            const u32 al1 = sHlo[hbase + 8 * 68];
            const u32 al2 = sHlo[hbase + 4];
            const u32 al3 = sHlo[hbase + 8 * 68 + 4];
            const int ktg = h * 8 + ktl;
#pragma unroll
            for (int q = 0; q < 2; ++q) {
                const int nt2 = nhw * 2 + q;
                const uint4 bb = g_W2f[((ktg * 4 + nt2) << 5) + lane];
                mma_bf16(d2[q], ah0, ah1, ah2, ah3, bb.x, bb.y);
                mma_bf16(d2[q], ah0, ah1, ah2, ah3, bb.z, bb.w);
                mma_bf16(d2[q], al0, al1, al2, al3, bb.x, bb.y);
            }
        }
        __syncthreads();
    }

#pragma unroll
    for (int q = 0; q < 2; ++q) {
        const int nt2 = nhw * 2 + q;
        const int c0 = nt2 * 8 + 2 * lt;
        const int kk0 = mt * 16 + lg;
        const float bb0 = b2[c0];
        const float bb1 = b2[c0 + 1];
        sY2[(32 + c0) * SROW + kk0] = fmaxf(d2[q][0] + bb0, 0.f);
        sY2[(33 + c0) * SROW + kk0] = fmaxf(d2[q][1] + bb1, 0.f);
        sY2[(32 + c0) * SROW + kk0 + 8] = fmaxf(d2[q][2] + bb0, 0.f);
        sY2[(33 + c0) * SROW + kk0 + 8] = fmaxf(d2[q][3] + bb1, 0.f);
    }
    __syncthreads();

    const int cpair = t & 15;
    const int kq = t >> 4;
    const int kk2 = kq << 2;
    const int pq = kq >> 2;

    {   // mid: f32x2 k-pair packing (chains identical to scalar version)
        ull aE01 = 0ull, aE23 = 0ull, aO01 = 0ull, aO23 = 0ull;
#pragma unroll 8
        for (int j = 0; j < 32; ++j) {
            const float2 wv = *(const float2*)(Wmid + (j << 5) + 2 * cpair);
            const ull wx = pack2(wv.x, wv.x);
            const ull wy = pack2(wv.y, wv.y);
            const ulonglong2 av = *(const ulonglong2*)(sY2 + (32 + j) * SROW + kk2);
            aE01 = fma2(av.x, wx, aE01);
            aE23 = fma2(av.y, wx, aE23);
            aO01 = fma2(av.x, wy, aO01);
            aO23 = fma2(av.y, wy, aO23);
        }
        const float bx0 = sMidX[pq * 32 + 2 * cpair] + bmid[2 * cpair];
        const float bx1 = sMidX[pq * 32 + 2 * cpair + 1] + bmid[2 * cpair + 1];
        const float2 uE01 = unpack2(aE01), uE23 = unpack2(aE23);
        const float2 uO01 = unpack2(aO01), uO23 = unpack2(aO23);
        float4 r0, r1;
        r0.x = fmaxf(uE01.x + bx0, 0.f); r0.y = fmaxf(uE01.y + bx0, 0.f);
        r0.z = fmaxf(uE23.x + bx0, 0.f); r0.w = fmaxf(uE23.y + bx0, 0.f);
        r1.x = fmaxf(uO01.x + bx1, 0.f); r1.y = fmaxf(uO01.y + bx1, 0.f);
        r1.z = fmaxf(uO23.x + bx1, 0.f); r1.w = fmaxf(uO23.y + bx1, 0.f);
        *(float4*)(sY2 + (2 * cpair) * SROW + kk2) = r0;
        *(float4*)(sY2 + (2 * cpair + 1) * SROW + kk2) = r1;
    }
    __syncthreads();

    {   // ybar
        const int jj = t & 63;
        const int pp = t >> 6;
        const float* row = sY2 + jj * SROW + pp * 16;
        const float4 s0 = *(const float4*)(row + 0);
        const float4 s1 = *(const float4*)(row + 4);
        const float4 s2 = *(const float4*)(row + 8);
        const float4 s3 = *(const float4*)(row + 12);
        const float s = (s0.x + s0.y + s0.z + s0.w) + (s1.x + s1.y + s1.z + s1.w)
                      + (s2.x + s2.y + s2.z + s2.w) + (s3.x + s3.y + s3.z + s3.w);
        sYbar[pp * 64 + jj] = s * (1.0f / 16.0f);
    }
    __syncthreads();

    {   // gate: f32x2 channel-pair packing; j split into two 64-loops
        const int c2g = (t & 63) * 2;
        const int pg = t >> 6;
        ull acc = 0ull;
#pragma unroll 8
        for (int j = 0; j < 64; ++j) {
            const ull wv = *(const ull*)(Wg + j * 128 + c2g);
            acc = fma2(pack2(sYbar[pg * 64 + j], sYbar[pg * 64 + j]), wv, acc);
        }
#pragma unroll 8
        for (int j = 0; j < 64; ++j) {
            const ull wv = *(const ull*)(Wg + (64 + j) * 128 + c2g);
            acc = fma2(pack2(sXn[pg * 64 + j], sXn[pg * 64 + j]), wv, acc);
        }
        const float2 u = unpack2(acc);
        sGate[pg * 128 + c2g] = 1.0f / (1.0f + expf(-(u.x + bg[c2g])));
        sGate[pg * 128 + c2g + 1] = 1.0f / (1.0f + expf(-(u.y + bg[c2g + 1])));
    }
    __syncthreads();

    {   // xg; out 96..159
        const int c = t & 63;
        const int p = t >> 6;
        const float xg = sXn[p * 64 + c] * sGate[p * 128 + 64 + c];
        sXg[p * 64 + c] = xg;
        out[(g0 + p) * 160 + 96 + c] = xg;
    }
    __syncthreads();

    {   // y2 *= gate; out 32..95
        const int jj = t & 63;
        const int pp = t >> 6;
        const float gv = sGate[pp * 128 + jj];
        float* row = sY2 + jj * SROW + pp * 16;
        float mx = -3.0e38f;
#pragma unroll
        for (int q = 0; q < 4; ++q) {
            float4 v = *(const float4*)(row + 4 * q);
            v.x *= gv; v.y *= gv; v.z *= gv; v.w *= gv;
            mx = fmaxf(mx, fmaxf(fmaxf(v.x, v.y), fmaxf(v.z, v.w)));
            *(float4*)(row + 4 * q) = v;
        }
        out[(g0 + pp) * 160 + 32 + jj] = mx;
    }
    if (t < 128) {  // last_x
        const int p = t >> 5;
        const int c = t & 31;
        float a = 0.f;
#pragma unroll 8
        for (int j = 0; j < 64; ++j)
            a = __fmaf_rn(sXg[p * 64 + j], Wlast[(64 + j) * 32 + c], a);
        sLastX[p * 32 + c] = a;
    }
    __syncthreads();

    float* sRed = sXh;
    {   // last: f32x2 k-pair packing; out 0..31
        ull aE01 = 0ull, aE23 = 0ull, aO01 = 0ull, aO23 = 0ull;
#pragma unroll 8
        for (int j = 0; j < 64; ++j) {
            const float2 wv = *(const float2*)(Wlast + (j << 5) + 2 * cpair);
            const ull wx = pack2(wv.x, wv.x);
            const ull wy = pack2(wv.y, wv.y);
            const ulonglong2 av = *(const ulonglong2*)(sY2 + j * SROW + kk2);
            aE01 = fma2(av.x, wx, aE01);
            aE23 = fma2(av.y, wx, aE23);
            aO01 = fma2(av.x, wy, aO01);
            aO23 = fma2(av.y, wy, aO23);
        }
        const float t0 = sLastX[pq * 32 + 2 * cpair] + blast[2 * cpair];
        const float t1 = sLastX[pq * 32 + 2 * cpair + 1] + blast[2 * cpair + 1];
        const float2 uE01 = unpack2(aE01), uE23 = unpack2(aE23);
        const float2 uO01 = unpack2(aO01), uO23 = unpack2(aO23);
        const float mx0 = fmaxf(fmaxf(uE01.x + t0, uE01.y + t0),
                                fmaxf(uE23.x + t0, uE23.y + t0));
        const float mx1 = fmaxf(fmaxf(uO01.x + t1, uO01.y + t1),
                                fmaxf(uO23.x + t1, uO23.y + t1));
        sRed[kq * 32 + 2 * cpair] = mx0;
        sRed[kq * 32 + 2 * cpair + 1] = mx1;
    }
    __syncthreads();
    if (t < 128) {
        const int p = t >> 5;
        const int cc = t & 31;
        float mx = sRed[(p * 4 + 0) * 32 + cc];
        mx = fmaxf(mx, sRed[(p * 4 + 1) * 32 + cc]);
        mx = fmaxf(mx, sRed[(p * 4 + 2) * 32 + cc]);
        mx = fmaxf(mx, sRed[(p * 4 + 3) * 32 + cc]);
        out[(g0 + p) * 160 + cc] = mx;
    }
}

// ---------------------------------------------------------------------------
extern "C" void kernel_launch(void* const* d_in, const int* in_sizes, int n_in,
                              void* d_out, int out_size) {
    const float* x = (const float*)d_in[0];
    const float* pos = (const float*)d_in[1];
    const float* W1 = (const float*)d_in[2];
    const float* b1 = (const float*)d_in[3];
    const float* W2 = (const float*)d_in[4];
    const float* b2 = (const float*)d_in[5];
    const float* Wmid = (const float*)d_in[6];
    const float* bmid = (const float*)d_in[7];
    const float* Wg = (const float*)d_in[8];
    const float* bg = (const float*)d_in[9];
    const float* Wlast = (const float*)d_in[10];
    const float* blast = (const float*)d_in[11];
    float* out = (float*)d_out;

    const int smem_bytes = SMEM_U32 * 4;
    cudaFuncSetAttribute(conv_kernel, cudaFuncAttributeMaxDynamicSharedMemorySize,
                         smem_bytes);

    knn_prep_kernel<<<256 + 128, 128>>>(pos, W1, W2);
    conv_kernel<<<(Bb * Nn) / P4, 256, smem_bytes>>>(
        x, b1, W2, b2, Wmid, bmid, Wg, bg, Wlast, blast, out);
}

// round 14
// speedup vs baseline: 1.5347x; 1.1983x over previous
#include <cuda_runtime.h>
#include <cuda_bf16.h>

#define Bb 8
#define Nn 4096

typedef unsigned long long ull;
typedef unsigned int u32;

// scratch
__device__ int g_nbr[Bb * Nn * 16];
__device__ float g_W1p[64 * 256];       // W1[0:64] - W1[128:192] (x part, fp32)
__device__ uint4 g_W1f[4 * 32 * 32];    // W1n frag-packed bf16 hi/lo
__device__ uint4 g_W2f[16 * 4 * 32];    // W2 frag-packed bf16 hi/lo

// ---------------------------------------------------------------------------
__device__ __forceinline__ ull pack2(float a, float b) {
    ull r;
    asm("mov.b64 %0, {%1, %2};" : "=l"(r) : "f"(a), "f"(b));
    return r;
}
__device__ __forceinline__ ull fma2(ull a, ull b, ull c) {
    ull d;
    asm("fma.rn.f32x2 %0, %1, %2, %3;" : "=l"(d) : "l"(a), "l"(b), "l"(c));
    return d;
}
__device__ __forceinline__ float2 unpack2(ull v) {
    float2 f;
    asm("mov.b64 {%0, %1}, %2;" : "=f"(f.x), "=f"(f.y) : "l"(v));
    return f;
}

// split (a,b) into bf16x2 hi + bf16x2 lo residual (RN per half).
__device__ __forceinline__ void split2(float a, float b, u32& hi, u32& lo) {
    u32 h;
    asm("cvt.rn.bf16x2.f32 %0, %1, %2;" : "=r"(h) : "f"(b), "f"(a));
    const float fa = __uint_as_float(h << 16);
    const float fb = __uint_as_float(h & 0xffff0000u);
    const float ra = a - fa;
    const float rb = b - fb;
    u32 l;
    asm("cvt.rn.bf16x2.f32 %0, %1, %2;" : "=r"(l) : "f"(rb), "f"(ra));
    hi = h;
    lo = l;
}

__device__ __forceinline__ void mma_bf16(float* d, u32 a0, u32 a1, u32 a2, u32 a3,
                                         u32 b0, u32 b1) {
    asm volatile(
        "mma.sync.aligned.m16n8k16.row.col.f32.bf16.bf16.f32 "
        "{%0,%1,%2,%3}, {%4,%5,%6,%7}, {%8,%9}, {%0,%1,%2,%3};"
        : "+f"(d[0]), "+f"(d[1]), "+f"(d[2]), "+f"(d[3])
        : "r"(a0), "r"(a1), "r"(a2), "r"(a3), "r"(b0), "r"(b1));
}

// ---------------------------------------------------------------------------
// Kernel 1: KNN (blocks 0..255) + weight prep (blocks 256..383).
// Heap lives in smem [slot][thread] (conflict-free): insert = 1 predicated STS
// per array; argmax = 16 LDS + SEL tree. Bit-identical selected set.
// ---------------------------------------------------------------------------
__global__ __launch_bounds__(128) void knn_prep_kernel(const float* __restrict__ pos,
                                                       const float* __restrict__ W1,
                                                       const float* __restrict__ W2) {
    const int bx = blockIdx.x;
    const int t = threadIdx.x;
    if (bx >= 256) {
        const int i = (bx - 256) * 128 + t;             // 0..16383
        {   // W1p (x-part, fp32)
            const int j = i >> 8;
            const int c = i & 255;
            g_W1p[i] = W1[j * 256 + c] - W1[(128 + j) * 256 + c];
        }
        if (i < 4096) {     // W1n frag pack: [kt 0..3][nt 0..31][lane]
            const int lane = i & 31;
            const int nt = (i >> 5) & 31;
            const int kt = i >> 10;
            const int j0 = kt * 16 + (lane & 3) * 2;
            const int n = nt * 8 + (lane >> 2);
            const float w00 = W1[(64 + j0) * 256 + n] + W1[(128 + j0) * 256 + n];
            const float w01 = W1[(64 + j0 + 1) * 256 + n] + W1[(128 + j0 + 1) * 256 + n];
            const float w10 = W1[(64 + j0 + 8) * 256 + n] + W1[(128 + j0 + 8) * 256 + n];
            const float w11 = W1[(64 + j0 + 9) * 256 + n] + W1[(128 + j0 + 9) * 256 + n];
            u32 h0, l0, h1, l1;
            split2(w00, w01, h0, l0);
            split2(w10, w11, h1, l1);
            g_W1f[i] = make_uint4(h0, h1, l0, l1);
        }
        if (i < 2048) {     // W2 frag pack: [kt 0..15][nt 0..3][lane]
            const int lane = i & 31;
            const int nt = (i >> 5) & 3;
            const int kt = i >> 7;
            const int j0 = kt * 16 + (lane & 3) * 2;
            const int n = nt * 8 + (lane >> 2);
            u32 h0, l0, h1, l1;
            split2(W2[j0 * 32 + n], W2[(j0 + 1) * 32 + n], h0, l0);
            split2(W2[(j0 + 8) * 32 + n], W2[(j0 + 9) * 32 + n], h1, l1);
            g_W2f[i] = make_uint4(h0, h1, l0, l1);
        }
        return;
    }

    const int b = bx >> 5;
    const int n = ((bx & 31) << 7) + t;

    const float qx = pos[(b * Nn + n) * 3 + 0];
    const float qy = pos[(b * Nn + n) * 3 + 1];
    const float qz = pos[(b * Nn + n) * 3 + 2];
    const float sqn = __fadd_rn(__fadd_rn(__fmul_rn(qx, qx), __fmul_rn(qy, qy)),
                                __fmul_rn(qz, qz));

    __shared__ float4 tile[1024];
    __shared__ float bdS[16][128];
    __shared__ int biS[16][128];

#pragma unroll
    for (int j = 0; j < 16; ++j) { bdS[j][t] = 3.0e38f; biS[j][t] = 0; }
    float worst = 3.0e38f;
    int wslot = 0;

    for (int t0 = 0; t0 < Nn; t0 += 1024) {
        __syncthreads();
        for (int i = t; i < 1024; i += 128) {
            const float px = pos[(b * Nn + t0 + i) * 3 + 0];
            const float py = pos[(b * Nn + t0 + i) * 3 + 1];
            const float pz = pos[(b * Nn + t0 + i) * 3 + 2];
            const float sq = __fadd_rn(__fadd_rn(__fmul_rn(px, px), __fmul_rn(py, py)),
                                       __fmul_rn(pz, pz));
            tile[i] = make_float4(px, py, pz, sq);
        }
        __syncthreads();
#pragma unroll 2
        for (int i = 0; i < 1024; ++i) {
            const float4 c = tile[i];
            const int m = t0 + i;
            float dot = __fmaf_rn(qx, c.x, 0.f);
            dot = __fmaf_rn(qy, c.y, dot);
            dot = __fmaf_rn(qz, c.z, dot);
            const float dist = __fsub_rn(__fadd_rn(sqn, c.w), __fmul_rn(2.0f, dot));
            const bool need = (dist < worst) && (m != n);
            if (__ballot_sync(0xffffffffu, need)) {
                if (need) {
                    bdS[wslot][t] = dist;       // predicated STS, bank t%32
                    biS[wslot][t] = m;
                }
                // reload heap row + balanced tree argmax (>= prefers lower
                // slot, matching original first-max semantics). Non-insert
                // lanes recompute identical worst/wslot.
                float d0 = bdS[0][t], d1 = bdS[1][t], d2v = bdS[2][t], d3 = bdS[3][t];
                float d4 = bdS[4][t], d5 = bdS[5][t], d6 = bdS[6][t], d7 = bdS[7][t];
                float d8 = bdS[8][t], d9 = bdS[9][t], d10 = bdS[10][t], d11 = bdS[11][t];
                float d12 = bdS[12][t], d13 = bdS[13][t], d14 = bdS[14][t], d15 = bdS[15][t];
                float v0, v1, v2, v3, v4, v5, v6, v7;
                int s0, s1, s2, s3, s4, s5, s6, s7;
                v0 = (d0 >= d1) ? d0 : d1;      s0 = (d0 >= d1) ? 0 : 1;
                v1 = (d2v >= d3) ? d2v : d3;    s1 = (d2v >= d3) ? 2 : 3;
                v2 = (d4 >= d5) ? d4 : d5;      s2 = (d4 >= d5) ? 4 : 5;
                v3 = (d6 >= d7) ? d6 : d7;      s3 = (d6 >= d7) ? 6 : 7;
                v4 = (d8 >= d9) ? d8 : d9;      s4 = (d8 >= d9) ? 8 : 9;
                v5 = (d10 >= d11) ? d10 : d11;  s5 = (d10 >= d11) ? 10 : 11;
                v6 = (d12 >= d13) ? d12 : d13;  s6 = (d12 >= d13) ? 12 : 13;
                v7 = (d14 >= d15) ? d14 : d15;  s7 = (d14 >= d15) ? 14 : 15;
                s0 = (v0 >= v1) ? s0 : s1;  v0 = (v0 >= v1) ? v0 : v1;
                s2 = (v2 >= v3) ? s2 : s3;  v2 = (v2 >= v3) ? v2 : v3;
                s4 = (v4 >= v5) ? s4 : s5;  v4 = (v4 >= v5) ? v4 : v5;
                s6 = (v6 >= v7) ? s6 : s7;  v6 = (v6 >= v7) ? v6 : v7;
                s0 = (v0 >= v2) ? s0 : s2;  v0 = (v0 >= v2) ? v0 : v2;
                s4 = (v4 >= v6) ? s4 : s6;  v4 = (v4 >= v6) ? v4 : v6;
                wslot = (v0 >= v4) ? s0 : s4;
                worst = (v0 >= v4) ? v0 : v4;
            }
        }
    }

#pragma unroll
    for (int j = 0; j < 16; ++j)
        g_nbr[(b * Nn + n) * 16 + j] = biS[j][t];
}

// ---------------------------------------------------------------------------
// Kernel 2: fused DenseEdgeConv (as round 13; xh loop unroll 8).
// ---------------------------------------------------------------------------
#define P4 4
#define SROW 68

#define OFF_AHI   0
#define OFF_ALO   (OFF_AHI + 64 * 36)
#define OFF_Y2    0
#define OFF_HHI   (OFF_ALO + 64 * 36)
#define OFF_HLO   (OFF_HHI + 64 * 68)
#define OFF_XH    (OFF_HLO + 64 * 68)
#define OFF_XN    (OFF_XH + P4 * 256)
#define OFF_MIDX  (OFF_XN + P4 * 64)
#define OFF_XG    (OFF_MIDX + P4 * 32)
#define OFF_YBAR  (OFF_XG + P4 * 64)
#define OFF_GATE  (OFF_YBAR + P4 * 64)
#define OFF_LASTX (OFF_GATE + P4 * 128)
#define OFF_NID   (OFF_LASTX + P4 * 32)
#define SMEM_U32  (OFF_NID + 64)

__global__ __launch_bounds__(256, 2) void conv_kernel(
    const float* __restrict__ x,
    const float* __restrict__ b1,
    const float* __restrict__ W2, const float* __restrict__ b2,
    const float* __restrict__ Wmid, const float* __restrict__ bmid,
    const float* __restrict__ Wg, const float* __restrict__ bg,
    const float* __restrict__ Wlast, const float* __restrict__ blast,
    float* __restrict__ out)
{
    extern __shared__ float sm[];
    u32* sAhi = (u32*)sm + OFF_AHI;
    u32* sAlo = (u32*)sm + OFF_ALO;
    u32* sHhi = (u32*)sm + OFF_HHI;
    u32* sHlo = (u32*)sm + OFF_HLO;
    float* sY2 = sm + OFF_Y2;
    float* sXh = sm + OFF_XH;
    float* sXn = sm + OFF_XN;
    float* sMidX = sm + OFF_MIDX;
    float* sXg = sm + OFF_XG;
    float* sYbar = sm + OFF_YBAR;
    float* sGate = sm + OFF_GATE;
    float* sLastX = sm + OFF_LASTX;
    int* sNid = (int*)((u32*)sm + OFF_NID);

    const int t = threadIdx.x;
    const int g0 = blockIdx.x * P4;
    const int b = g0 >> 12;

    sXn[t] = x[(g0 + (t >> 6)) * 64 + (t & 63)];
    if (t < 64) sNid[t] = g_nbr[g0 * 16 + t];
    __syncthreads();

#pragma unroll
    for (int it = 0; it < 4; ++it) {
        const int idx = it * 256 + t;
        const int kk = idx >> 4;
        const int c4 = (idx & 15) << 2;
        const float4 v = *(const float4*)(x + (b * Nn + sNid[kk]) * 64 + c4);
        u32 h0, l0, h1, l1;
        split2(v.x, v.y, h0, l0);
        split2(v.z, v.w, h1, l1);
        const int base = kk * 36 + (c4 >> 1);
        sAhi[base] = h0; sAhi[base + 1] = h1;
        sAlo[base] = l0; sAlo[base + 1] = l1;
    }
    if (t < 128) {
        const int c0 = t;
        float a[4][2];
#pragma unroll
        for (int p = 0; p < 4; ++p) { a[p][0] = 0.f; a[p][1] = 0.f; }
#pragma unroll 8
        for (int j = 0; j < 64; ++j) {
            const float w0 = g_W1p[j * 256 + c0];
            const float w1 = g_W1p[j * 256 + c0 + 128];
#pragma unroll
            for (int p = 0; p < 4; ++p) {
                const float xv = sXn[p * 64 + j];
                a[p][0] = __fmaf_rn(xv, w0, a[p][0]);
                a[p][1] = __fmaf_rn(xv, w1, a[p][1]);
            }
        }
        const float bb0 = b1[c0];
        const float bb1 = b1[c0 + 128];
#pragma unroll
        for (int p = 0; p < 4; ++p) {
            sXh[p * 256 + c0] = a[p][0] + bb0;
            sXh[p * 256 + c0 + 128] = a[p][1] + bb1;
        }
    } else {
        const int p = (t >> 5) & 3;
        const int c = t & 31;
        float a = 0.f;
#pragma unroll 4
        for (int j = 0; j < 64; ++j)
            a = __fmaf_rn(sXn[p * 64 + j], Wmid[(32 + j) * 32 + c], a);
        sMidX[p * 32 + c] = a;
    }
    __syncthreads();

    const int lane = t & 31;
    const int w = t >> 5;
    const int mt = w & 3;
    const int nhw = w >> 2;
    const int lt = lane & 3;
    const int lg = lane >> 2;

    float d2[2][4];
#pragma unroll
    for (int q = 0; q < 2; ++q)
#pragma unroll
        for (int r = 0; r < 4; ++r) d2[q][r] = 0.f;

#pragma unroll
    for (int h = 0; h < 2; ++h) {
        float d1[8][4];
#pragma unroll
        for (int nt = 0; nt < 8; ++nt)
#pragma unroll
            for (int r = 0; r < 4; ++r) d1[nt][r] = 0.f;

#pragma unroll
        for (int kt = 0; kt < 4; ++kt) {
            const int abase = (mt * 16 + lg) * 36 + kt * 8 + lt;
            const u32 ah0 = sAhi[abase];
            const u32 ah1 = sAhi[abase + 8 * 36];
            const u32 ah2 = sAhi[abase + 4];
            const u32 ah3 = sAhi[abase + 8 * 36 + 4];
            const u32 al0 = sAlo[abase];
            const u32 al1 = sAlo[abase + 8 * 36];
            const u32 al2 = sAlo[abase + 4];
            const u32 al3 = sAlo[abase + 8 * 36 + 4];
#pragma unroll
            for (int nt = 0; nt < 8; ++nt) {
                const int ntg = h * 16 + nhw * 8 + nt;
                const uint4 bb = g_W1f[((kt * 32 + ntg) << 5) + lane];
                mma_bf16(d1[nt], ah0, ah1, ah2, ah3, bb.x, bb.y);
                mma_bf16(d1[nt], ah0, ah1, ah2, ah3, bb.z, bb.w);
                mma_bf16(d1[nt], al0, al1, al2, al3, bb.x, bb.y);
            }
        }
#pragma unroll
        for (int nt = 0; nt < 8; ++nt) {
            const int ntg = h * 16 + nhw * 8 + nt;
            const int c0 = ntg * 8 + 2 * lt;
            const float xh0 = sXh[mt * 256 + c0];
            const float xh1 = sXh[mt * 256 + c0 + 1];
            const float v0 = fmaxf(d1[nt][0] + xh0, 0.f);
            const float v1 = fmaxf(d1[nt][1] + xh1, 0.f);
            const float v2 = fmaxf(d1[nt][2] + xh0, 0.f);
            const float v3 = fmaxf(d1[nt][3] + xh1, 0.f);
            u32 h01, l01, h23, l23;
            split2(v0, v1, h01, l01);
            split2(v2, v3, h23, l23);
            const int pair = (nhw * 8 + nt) * 4 + lt;
            const int r0 = mt * 16 + lg;
            sHhi[r0 * 68 + pair] = h01;
            sHhi[(r0 + 8) * 68 + pair] = h23;
            sHlo[r0 * 68 + pair] = l01;
            sHlo[(r0 + 8) * 68 + pair] = l23;
        }
        __syncthreads();

#pragma unroll
        for (int ktl = 0; ktl < 8; ++ktl) {
            const int hbase = (mt * 16 + lg) * 68 + ktl * 8 + lt;
            const u32 ah0 = sHhi[hbase];
            const u32 ah1 = sHhi[hbase + 8 * 68];
            const u32 ah2 = sHhi[hbase + 4];
            const u32 ah3 = sHhi[hbase + 8 * 68 + 4];
            const u32 al0 = sHlo[hbase];
            const u32 al1 = sHlo[hbase + 8 * 68];
            const u32 al2 = sHlo[hbase + 4];
            const u32 al3 = sHlo[hbase + 8 * 68 + 4];
            const int ktg = h * 8 + ktl;
#pragma unroll
            for (int q = 0; q < 2; ++q) {
                const int nt2 = nhw * 2 + q;
                const uint4 bb = g_W2f[((ktg * 4 + nt2) << 5) + lane];
                mma_bf16(d2[q], ah0, ah1, ah2, ah3, bb.x, bb.y);
                mma_bf16(d2[q], ah0, ah1, ah2, ah3, bb.z, bb.w);
                mma_bf16(d2[q], al0, al1, al2, al3, bb.x, bb.y);
            }
        }
        __syncthreads();
    }

#pragma unroll
    for (int q = 0; q < 2; ++q) {
        const int nt2 = nhw * 2 + q;
        const int c0 = nt2 * 8 + 2 * lt;
        const int kk0 = mt * 16 + lg;
        const float bb0 = b2[c0];
        const float bb1 = b2[c0 + 1];
        sY2[(32 + c0) * SROW + kk0] = fmaxf(d2[q][0] + bb0, 0.f);
        sY2[(33 + c0) * SROW + kk0] = fmaxf(d2[q][1] + bb1, 0.f);
        sY2[(32 + c0) * SROW + kk0 + 8] = fmaxf(d2[q][2] + bb0, 0.f);
        sY2[(33 + c0) * SROW + kk0 + 8] = fmaxf(d2[q][3] + bb1, 0.f);
    }
    __syncthreads();

    const int cpair = t & 15;
    const int kq = t >> 4;
    const int kk2 = kq << 2;
    const int pq = kq >> 2;

    {   // mid: f32x2 k-pair packing
        ull aE01 = 0ull, aE23 = 0ull, aO01 = 0ull, aO23 = 0ull;
#pragma unroll 8
        for (int j = 0; j < 32; ++j) {
            const float2 wv = *(const float2*)(Wmid + (j << 5) + 2 * cpair);
            const ull wx = pack2(wv.x, wv.x);
            const ull wy = pack2(wv.y, wv.y);
            const ulonglong2 av = *(const ulonglong2*)(sY2 + (32 + j) * SROW + kk2);
            aE01 = fma2(av.x, wx, aE01);
            aE23 = fma2(av.y, wx, aE23);
            aO01 = fma2(av.x, wy, aO01);
            aO23 = fma2(av.y, wy, aO23);
        }
        const float bx0 = sMidX[pq * 32 + 2 * cpair] + bmid[2 * cpair];
        const float bx1 = sMidX[pq * 32 + 2 * cpair + 1] + bmid[2 * cpair + 1];
        const float2 uE01 = unpack2(aE01), uE23 = unpack2(aE23);
        const float2 uO01 = unpack2(aO01), uO23 = unpack2(aO23);
        float4 r0, r1;
        r0.x = fmaxf(uE01.x + bx0, 0.f); r0.y = fmaxf(uE01.y + bx0, 0.f);
        r0.z = fmaxf(uE23.x + bx0, 0.f); r0.w = fmaxf(uE23.y + bx0, 0.f);
        r1.x = fmaxf(uO01.x + bx1, 0.f); r1.y = fmaxf(uO01.y + bx1, 0.f);
        r1.z = fmaxf(uO23.x + bx1, 0.f); r1.w = fmaxf(uO23.y + bx1, 0.f);
        *(float4*)(sY2 + (2 * cpair) * SROW + kk2) = r0;
        *(float4*)(sY2 + (2 * cpair + 1) * SROW + kk2) = r1;
    }
    __syncthreads();

    {   // ybar
        const int jj = t & 63;
        const int pp = t >> 6;
        const float* row = sY2 + jj * SROW + pp * 16;
        const float4 s0 = *(const float4*)(row + 0);
        const float4 s1 = *(const float4*)(row + 4);
        const float4 s2 = *(const float4*)(row + 8);
        const float4 s3 = *(const float4*)(row + 12);
        const float s = (s0.x + s0.y + s0.z + s0.w) + (s1.x + s1.y + s1.z + s1.w)
                      + (s2.x + s2.y + s2.z + s2.w) + (s3.x + s3.y + s3.z + s3.w);
        sYbar[pp * 64 + jj] = s * (1.0f / 16.0f);
    }
    __syncthreads();

    {   // gate: f32x2 channel-pair packing
        const int c2g = (t & 63) * 2;
        const int pg = t >> 6;
        ull acc = 0ull;
#pragma unroll 8
        for (int j = 0; j < 64; ++j) {
            const ull wv = *(const ull*)(Wg + j * 128 + c2g);
            acc = fma2(pack2(sYbar[pg * 64 + j], sYbar[pg * 64 + j]), wv, acc);
        }
#pragma unroll 8
        for (int j = 0; j < 64; ++j) {
            const ull wv = *(const ull*)(Wg + (64 + j) * 128 + c2g);
            acc = fma2(pack2(sXn[pg * 64 + j], sXn[pg * 64 + j]), wv, acc);
        }
        const float2 u = unpack2(acc);
        sGate[pg * 128 + c2g] = 1.0f / (1.0f + expf(-(u.x + bg[c2g])));
        sGate[pg * 128 + c2g + 1] = 1.0f / (1.0f + expf(-(u.y + bg[c2g + 1])));
    }
    __syncthreads();

    {   // xg; out 96..159
        const int c = t & 63;
        const int p = t >> 6;
        const float xg = sXn[p * 64 + c] * sGate[p * 128 + 64 + c];
        sXg[p * 64 + c] = xg;
        out[(g0 + p) * 160 + 96 + c] = xg;
    }
    __syncthreads();

    {   // y2 *= gate; out 32..95
        const int jj = t & 63;
        const int pp = t >> 6;
        const float gv = sGate[pp * 128 + jj];
        float* row = sY2 + jj * SROW + pp * 16;
        float mx = -3.0e38f;
#pragma unroll
        for (int q = 0; q < 4; ++q) {
            float4 v = *(const float4*)(row + 4 * q);
            v.x *= gv; v.y *= gv; v.z *= gv; v.w *= gv;
            mx = fmaxf(mx, fmaxf(fmaxf(v.x, v.y), fmaxf(v.z, v.w)));
            *(float4*)(row + 4 * q) = v;
        }
        out[(g0 + pp) * 160 + 32 + jj] = mx;
    }
    if (t < 128) {  // last_x
        const int p = t >> 5;
        const int c = t & 31;
        float a = 0.f;
#pragma unroll 8
        for (int j = 0; j < 64; ++j)
            a = __fmaf_rn(sXg[p * 64 + j], Wlast[(64 + j) * 32 + c], a);
        sLastX[p * 32 + c] = a;
    }
    __syncthreads();

    float* sRed = sXh;
    {   // last: f32x2 k-pair packing; out 0..31
        ull aE01 = 0ull, aE23 = 0ull, aO01 = 0ull, aO23 = 0ull;
#pragma unroll 8
        for (int j = 0; j < 64; ++j) {
            const float2 wv = *(const float2*)(Wlast + (j << 5) + 2 * cpair);
            const ull wx = pack2(wv.x, wv.x);
            const ull wy = pack2(wv.y, wv.y);
            const ulonglong2 av = *(const ulonglong2*)(sY2 + j * SROW + kk2);
            aE01 = fma2(av.x, wx, aE01);
            aE23 = fma2(av.y, wx, aE23);
            aO01 = fma2(av.x, wy, aO01);
            aO23 = fma2(av.y, wy, aO23);
        }
        const float t0 = sLastX[pq * 32 + 2 * cpair] + blast[2 * cpair];
        const float t1 = sLastX[pq * 32 + 2 * cpair + 1] + blast[2 * cpair + 1];
        const float2 uE01 = unpack2(aE01), uE23 = unpack2(aE23);
        const float2 uO01 = unpack2(aO01), uO23 = unpack2(aO23);
        const float mx0 = fmaxf(fmaxf(uE01.x + t0, uE01.y + t0),
                                fmaxf(uE23.x + t0, uE23.y + t0));
        const float mx1 = fmaxf(fmaxf(uO01.x + t1, uO01.y + t1),
                                fmaxf(uO23.x + t1, uO23.y + t1));
        sRed[kq * 32 + 2 * cpair] = mx0;
        sRed[kq * 32 + 2 * cpair + 1] = mx1;
    }
    __syncthreads();
    if (t < 128) {
        const int p = t >> 5;
        const int cc = t & 31;
        float mx = sRed[(p * 4 + 0) * 32 + cc];
        mx = fmaxf(mx, sRed[(p * 4 + 1) * 32 + cc]);
        mx = fmaxf(mx, sRed[(p * 4 + 2) * 32 + cc]);
        mx = fmaxf(mx, sRed[(p * 4 + 3) * 32 + cc]);
        out[(g0 + p) * 160 + cc] = mx;
    }
}

// ---------------------------------------------------------------------------
extern "C" void kernel_launch(void* const* d_in, const int* in_sizes, int n_in,
                              void* d_out, int out_size) {
    const float* x = (const float*)d_in[0];
    const float* pos = (const float*)d_in[1];
    const float* W1 = (const float*)d_in[2];
    const float* b1 = (const float*)d_in[3];
    const float* W2 = (const float*)d_in[4];
    const float* b2 = (const float*)d_in[5];
    const float* Wmid = (const float*)d_in[6];
    const float* bmid = (const float*)d_in[7];
    const float* Wg = (const float*)d_in[8];
    const float* bg = (const float*)d_in[9];
    const float* Wlast = (const float*)d_in[10];
    const float* blast = (const float*)d_in[11];
    float* out = (float*)d_out;

    const int smem_bytes = SMEM_U32 * 4;
    cudaFuncSetAttribute(conv_kernel, cudaFuncAttributeMaxDynamicSharedMemorySize,
                         smem_bytes);

    knn_prep_kernel<<<256 + 128, 128>>>(pos, W1, W2);
    conv_kernel<<<(Bb * Nn) / P4, 256, smem_bytes>>>(
        x, b1, W2, b2, Wmid, bmid, Wg, bg, Wlast, blast, out);
}

// round 15
// speedup vs baseline: 1.5649x; 1.0197x over previous
#include <cuda_runtime.h>
#include <cuda_bf16.h>

#define Bb 8
#define Nn 4096

typedef unsigned long long ull;
typedef unsigned int u32;

// scratch
__device__ int g_nbr[Bb * Nn * 16];
__device__ float g_W1p[64 * 256];       // W1[0:64] - W1[128:192] (x part, fp32)
__device__ uint4 g_W1f[4 * 32 * 32];    // W1n frag-packed bf16 hi/lo
__device__ uint4 g_W2f[16 * 4 * 32];    // W2 frag-packed bf16 hi/lo
__device__ ulonglong2 g_Wmid2[32 * 16]; // Wmid[0:32] dup-packed f32x2 pairs
__device__ ulonglong2 g_Wlast2[64 * 16];// Wlast[0:64] dup-packed f32x2 pairs

// ---------------------------------------------------------------------------
__device__ __forceinline__ ull pack2(float a, float b) {
    ull r;
    asm("mov.b64 %0, {%1, %2};" : "=l"(r) : "f"(a), "f"(b));
    return r;
}
__device__ __forceinline__ ull fma2(ull a, ull b, ull c) {
    ull d;
    asm("fma.rn.f32x2 %0, %1, %2, %3;" : "=l"(d) : "l"(a), "l"(b), "l"(c));
    return d;
}
__device__ __forceinline__ ull add2(ull a, ull b) {
    ull d;
    asm("add.rn.f32x2 %0, %1, %2;" : "=l"(d) : "l"(a), "l"(b));
    return d;
}
__device__ __forceinline__ float2 unpack2(ull v) {
    float2 f;
    asm("mov.b64 {%0, %1}, %2;" : "=f"(f.x), "=f"(f.y) : "l"(v));
    return f;
}

// split (a,b) into bf16x2 hi + bf16x2 lo residual (RN per half).
__device__ __forceinline__ void split2(float a, float b, u32& hi, u32& lo) {
    u32 h;
    asm("cvt.rn.bf16x2.f32 %0, %1, %2;" : "=r"(h) : "f"(b), "f"(a));
    const float fa = __uint_as_float(h << 16);
    const float fb = __uint_as_float(h & 0xffff0000u);
    const float ra = a - fa;
    const float rb = b - fb;
    u32 l;
    asm("cvt.rn.bf16x2.f32 %0, %1, %2;" : "=r"(l) : "f"(rb), "f"(ra));
    hi = h;
    lo = l;
}

__device__ __forceinline__ void mma_bf16(float* d, u32 a0, u32 a1, u32 a2, u32 a3,
                                         u32 b0, u32 b1) {
    asm volatile(
        "mma.sync.aligned.m16n8k16.row.col.f32.bf16.bf16.f32 "
        "{%0,%1,%2,%3}, {%4,%5,%6,%7}, {%8,%9}, {%0,%1,%2,%3};"
        : "+f"(d[0]), "+f"(d[1]), "+f"(d[2]), "+f"(d[3])
        : "r"(a0), "r"(a1), "r"(a2), "r"(a3), "r"(b0), "r"(b1));
}

// ---------------------------------------------------------------------------
// Kernel 1: KNN (blocks 0..255, smem heap) + weight prep (blocks 256..383).
// ---------------------------------------------------------------------------
__global__ __launch_bounds__(128) void knn_prep_kernel(const float* __restrict__ pos,
                                                       const float* __restrict__ W1,
                                                       const float* __restrict__ W2,
                                                       const float* __restrict__ Wmid,
                                                       const float* __restrict__ Wlast) {
    const int bx = blockIdx.x;
    const int t = threadIdx.x;
    if (bx >= 256) {
        const int i = (bx - 256) * 128 + t;             // 0..16383
        {   // W1p (x-part, fp32)
            const int j = i >> 8;
            const int c = i & 255;
            g_W1p[i] = W1[j * 256 + c] - W1[(128 + j) * 256 + c];
        }
        if (i < 4096) {     // W1n frag pack: [kt 0..3][nt 0..31][lane]
            const int lane = i & 31;
            const int nt = (i >> 5) & 31;
            const int kt = i >> 10;
            const int j0 = kt * 16 + (lane & 3) * 2;
            const int n = nt * 8 + (lane >> 2);
            const float w00 = W1[(64 + j0) * 256 + n] + W1[(128 + j0) * 256 + n];
            const float w01 = W1[(64 + j0 + 1) * 256 + n] + W1[(128 + j0 + 1) * 256 + n];
            const float w10 = W1[(64 + j0 + 8) * 256 + n] + W1[(128 + j0 + 8) * 256 + n];
            const float w11 = W1[(64 + j0 + 9) * 256 + n] + W1[(128 + j0 + 9) * 256 + n];
            u32 h0, l0, h1, l1;
            split2(w00, w01, h0, l0);
            split2(w10, w11, h1, l1);
            g_W1f[i] = make_uint4(h0, h1, l0, l1);
        }
        if (i < 2048) {     // W2 frag pack: [kt 0..15][nt 0..3][lane]
            const int lane = i & 31;
            const int nt = (i >> 5) & 3;
            const int kt = i >> 7;
            const int j0 = kt * 16 + (lane & 3) * 2;
            const int n = nt * 8 + (lane >> 2);
            u32 h0, l0, h1, l1;
            split2(W2[j0 * 32 + n], W2[(j0 + 1) * 32 + n], h0, l0);
            split2(W2[(j0 + 8) * 32 + n], W2[(j0 + 9) * 32 + n], h1, l1);
            g_W2f[i] = make_uint4(h0, h1, l0, l1);
        }
        if (i < 512) {      // Wmid[0:32] dup-packed: [j][cpair]
            const int j = i >> 4;
            const int cp = i & 15;
            const float we = Wmid[j * 32 + 2 * cp];
            const float wo = Wmid[j * 32 + 2 * cp + 1];
            g_Wmid2[i] = make_ulonglong2(pack2(we, we), pack2(wo, wo));
        }
        if (i < 1024) {     // Wlast[0:64] dup-packed: [j][cpair]
            const int j = i >> 4;
            const int cp = i & 15;
            const float we = Wlast[j * 32 + 2 * cp];
            const float wo = Wlast[j * 32 + 2 * cp + 1];
            g_Wlast2[i] = make_ulonglong2(pack2(we, we), pack2(wo, wo));
        }
        return;
    }

    const int b = bx >> 5;
    const int n = ((bx & 31) << 7) + t;

    const float qx = pos[(b * Nn + n) * 3 + 0];
    const float qy = pos[(b * Nn + n) * 3 + 1];
    const float qz = pos[(b * Nn + n) * 3 + 2];
    const float sqn = __fadd_rn(__fadd_rn(__fmul_rn(qx, qx), __fmul_rn(qy, qy)),
                                __fmul_rn(qz, qz));

    __shared__ float4 tile[1024];
    __shared__ float bdS[16][128];
    __shared__ int biS[16][128];

#pragma unroll
    for (int j = 0; j < 16; ++j) { bdS[j][t] = 3.0e38f; biS[j][t] = 0; }
    float worst = 3.0e38f;
    int wslot = 0;

    for (int t0 = 0; t0 < Nn; t0 += 1024) {
        __syncthreads();
        for (int i = t; i < 1024; i += 128) {
            const float px = pos[(b * Nn + t0 + i) * 3 + 0];
            const float py = pos[(b * Nn + t0 + i) * 3 + 1];
            const float pz = pos[(b * Nn + t0 + i) * 3 + 2];
            const float sq = __fadd_rn(__fadd_rn(__fmul_rn(px, px), __fmul_rn(py, py)),
                                       __fmul_rn(pz, pz));
            tile[i] = make_float4(px, py, pz, sq);
        }
        __syncthreads();
#pragma unroll 2
        for (int i = 0; i < 1024; ++i) {
            const float4 c = tile[i];
            const int m = t0 + i;
            float dot = __fmaf_rn(qx, c.x, 0.f);
            dot = __fmaf_rn(qy, c.y, dot);
            dot = __fmaf_rn(qz, c.z, dot);
            const float dist = __fsub_rn(__fadd_rn(sqn, c.w), __fmul_rn(2.0f, dot));
            const bool need = (dist < worst) && (m != n);
            if (__ballot_sync(0xffffffffu, need)) {
                if (need) {
                    bdS[wslot][t] = dist;
                    biS[wslot][t] = m;
                }
                float d0 = bdS[0][t], d1 = bdS[1][t], d2v = bdS[2][t], d3 = bdS[3][t];
                float d4 = bdS[4][t], d5 = bdS[5][t], d6 = bdS[6][t], d7 = bdS[7][t];
                float d8 = bdS[8][t], d9 = bdS[9][t], d10 = bdS[10][t], d11 = bdS[11][t];
                float d12 = bdS[12][t], d13 = bdS[13][t], d14 = bdS[14][t], d15 = bdS[15][t];
                float v0, v1, v2, v3, v4, v5, v6, v7;
                int s0, s1, s2, s3, s4, s5, s6, s7;
                v0 = (d0 >= d1) ? d0 : d1;      s0 = (d0 >= d1) ? 0 : 1;
                v1 = (d2v >= d3) ? d2v : d3;    s1 = (d2v >= d3) ? 2 : 3;
                v2 = (d4 >= d5) ? d4 : d5;      s2 = (d4 >= d5) ? 4 : 5;
                v3 = (d6 >= d7) ? d6 : d7;      s3 = (d6 >= d7) ? 6 : 7;
                v4 = (d8 >= d9) ? d8 : d9;      s4 = (d8 >= d9) ? 8 : 9;
                v5 = (d10 >= d11) ? d10 : d11;  s5 = (d10 >= d11) ? 10 : 11;
                v6 = (d12 >= d13) ? d12 : d13;  s6 = (d12 >= d13) ? 12 : 13;
                v7 = (d14 >= d15) ? d14 : d15;  s7 = (d14 >= d15) ? 14 : 15;
                s0 = (v0 >= v1) ? s0 : s1;  v0 = (v0 >= v1) ? v0 : v1;
                s2 = (v2 >= v3) ? s2 : s3;  v2 = (v2 >= v3) ? v2 : v3;
                s4 = (v4 >= v5) ? s4 : s5;  v4 = (v4 >= v5) ? v4 : v5;
                s6 = (v6 >= v7) ? s6 : s7;  v6 = (v6 >= v7) ? v6 : v7;
                s0 = (v0 >= v2) ? s0 : s2;  v0 = (v0 >= v2) ? v0 : v2;
                s4 = (v4 >= v6) ? s4 : s6;  v4 = (v4 >= v6) ? v4 : v6;
                wslot = (v0 >= v4) ? s0 : s4;
                worst = (v0 >= v4) ? v0 : v4;
            }
        }
    }

#pragma unroll
    for (int j = 0; j < 16; ++j)
        g_nbr[(b * Nn + n) * 16 + j] = biS[j][t];
}

// ---------------------------------------------------------------------------
// Kernel 2: fused DenseEdgeConv. Tensor-core GEMM1/GEMM2; K-split gate;
// dup-packed weight tables for mid/last.
// ---------------------------------------------------------------------------
#define P4 4
#define SROW 68

#define OFF_AHI   0
#define OFF_ALO   (OFF_AHI + 64 * 36)
#define OFF_Y2    0
#define OFF_HHI   (OFF_ALO + 64 * 36)
#define OFF_HLO   (OFF_HHI + 64 * 68)
#define OFF_XH    (OFF_HLO + 64 * 68)
#define OFF_XN    (OFF_XH + P4 * 256)
#define OFF_MIDX  (OFF_XN + P4 * 64)
#define OFF_XG    (OFF_MIDX + P4 * 32)
#define OFF_YBAR  (OFF_XG + P4 * 64)
#define OFF_GATE  (OFF_YBAR + P4 * 64)
#define OFF_LASTX (OFF_GATE + P4 * 128)
#define OFF_NID   (OFF_LASTX + P4 * 32)
#define SMEM_U32  (OFF_NID + 64)

__global__ __launch_bounds__(256, 2) void conv_kernel(
    const float* __restrict__ x,
    const float* __restrict__ b1,
    const float* __restrict__ W2, const float* __restrict__ b2,
    const float* __restrict__ Wmid, const float* __restrict__ bmid,
    const float* __restrict__ Wg, const float* __restrict__ bg,
    const float* __restrict__ Wlast, const float* __restrict__ blast,
    float* __restrict__ out)
{
    extern __shared__ float sm[];
    u32* sAhi = (u32*)sm + OFF_AHI;
    u32* sAlo = (u32*)sm + OFF_ALO;
    u32* sHhi = (u32*)sm + OFF_HHI;
    u32* sHlo = (u32*)sm + OFF_HLO;
    float* sY2 = sm + OFF_Y2;
    float* sXh = sm + OFF_XH;
    float* sXn = sm + OFF_XN;
    float* sMidX = sm + OFF_MIDX;
    float* sXg = sm + OFF_XG;
    float* sYbar = sm + OFF_YBAR;
    float* sGate = sm + OFF_GATE;
    float* sLastX = sm + OFF_LASTX;
    int* sNid = (int*)((u32*)sm + OFF_NID);

    const int t = threadIdx.x;
    const int g0 = blockIdx.x * P4;
    const int b = g0 >> 12;

    sXn[t] = x[(g0 + (t >> 6)) * 64 + (t & 63)];
    if (t < 64) sNid[t] = g_nbr[g0 * 16 + t];
    __syncthreads();

#pragma unroll
    for (int it = 0; it < 4; ++it) {
        const int idx = it * 256 + t;
        const int kk = idx >> 4;
        const int c4 = (idx & 15) << 2;
        const float4 v = *(const float4*)(x + (b * Nn + sNid[kk]) * 64 + c4);
        u32 h0, l0, h1, l1;
        split2(v.x, v.y, h0, l0);
        split2(v.z, v.w, h1, l1);
        const int base = kk * 36 + (c4 >> 1);
        sAhi[base] = h0; sAhi[base + 1] = h1;
        sAlo[base] = l0; sAlo[base + 1] = l1;
    }
    if (t < 128) {
        const int c0 = t;
        float a[4][2];
#pragma unroll
        for (int p = 0; p < 4; ++p) { a[p][0] = 0.f; a[p][1] = 0.f; }
#pragma unroll 8
        for (int j = 0; j < 64; ++j) {
            const float w0 = g_W1p[j * 256 + c0];
            const float w1 = g_W1p[j * 256 + c0 + 128];
#pragma unroll
            for (int p = 0; p < 4; ++p) {
                const float xv = sXn[p * 64 + j];
                a[p][0] = __fmaf_rn(xv, w0, a[p][0]);
                a[p][1] = __fmaf_rn(xv, w1, a[p][1]);
            }
        }
        const float bb0 = b1[c0];
        const float bb1 = b1[c0 + 128];
#pragma unroll
        for (int p = 0; p < 4; ++p) {
            sXh[p * 256 + c0] = a[p][0] + bb0;
            sXh[p * 256 + c0 + 128] = a[p][1] + bb1;
        }
    } else {
        const int p = (t >> 5) & 3;
        const int c = t & 31;
        float a = 0.f;
#pragma unroll 4
        for (int j = 0; j < 64; ++j)
            a = __fmaf_rn(sXn[p * 64 + j], Wmid[(32 + j) * 32 + c], a);
        sMidX[p * 32 + c] = a;
    }
    __syncthreads();

    const int lane = t & 31;
    const int w = t >> 5;
    const int mt = w & 3;
    const int nhw = w >> 2;
    const int lt = lane & 3;
    const int lg = lane >> 2;

    float d2[2][4];
#pragma unroll
    for (int q = 0; q < 2; ++q)
#pragma unroll
        for (int r = 0; r < 4; ++r) d2[q][r] = 0.f;

#pragma unroll
    for (int h = 0; h < 2; ++h) {
        float d1[8][4];
#pragma unroll
        for (int nt = 0; nt < 8; ++nt)
#pragma unroll
            for (int r = 0; r < 4; ++r) d1[nt][r] = 0.f;

#pragma unroll
        for (int kt = 0; kt < 4; ++kt) {
            const int abase = (mt * 16 + lg) * 36 + kt * 8 + lt;
            const u32 ah0 = sAhi[abase];
            const u32 ah1 = sAhi[abase + 8 * 36];
            const u32 ah2 = sAhi[abase + 4];
            const u32 ah3 = sAhi[abase + 8 * 36 + 4];
            const u32 al0 = sAlo[abase];
            const u32 al1 = sAlo[abase + 8 * 36];
            const u32 al2 = sAlo[abase + 4];
            const u32 al3 = sAlo[abase + 8 * 36 + 4];
#pragma unroll
            for (int nt = 0; nt < 8; ++nt) {
                const int ntg = h * 16 + nhw * 8 + nt;
                const uint4 bb = g_W1f[((kt * 32 + ntg) << 5) + lane];
                mma_bf16(d1[nt], ah0, ah1, ah2, ah3, bb.x, bb.y);
                mma_bf16(d1[nt], ah0, ah1, ah2, ah3, bb.z, bb.w);
                mma_bf16(d1[nt], al0, al1, al2, al3, bb.x, bb.y);
            }
        }
#pragma unroll
        for (int nt = 0; nt < 8; ++nt) {
            const int ntg = h * 16 + nhw * 8 + nt;
            const int c0 = ntg * 8 + 2 * lt;
            const float xh0 = sXh[mt * 256 + c0];
            const float xh1 = sXh[mt * 256 + c0 + 1];
            const float v0 = fmaxf(d1[nt][0] + xh0, 0.f);
            const float v1 = fmaxf(d1[nt][1] + xh1, 0.f);
            const float v2 = fmaxf(d1[nt][2] + xh0, 0.f);
            const float v3 = fmaxf(d1[nt][3] + xh1, 0.f);
            u32 h01, l01, h23, l23;
            split2(v0, v1, h01, l01);
            split2(v2, v3, h23, l23);
            const int pair = (nhw * 8 + nt) * 4 + lt;
            const int r0 = mt * 16 + lg;
            sHhi[r0 * 68 + pair] = h01;
            sHhi[(r0 + 8) * 68 + pair] = h23;
            sHlo[r0 * 68 + pair] = l01;
            sHlo[(r0 + 8) * 68 + pair] = l23;
        }
        __syncthreads();

#pragma unroll
        for (int ktl = 0; ktl < 8; ++ktl) {
            const int hbase = (mt * 16 + lg) * 68 + ktl * 8 + lt;
            const u32 ah0 = sHhi[hbase];
            const u32 ah1 = sHhi[hbase + 8 * 68];
            const u32 ah2 = sHhi[hbase + 4];
            const u32 ah3 = sHhi[hbase + 8 * 68 + 4];
            const u32 al0 = sHlo[hbase];
            const u32 al1 = sHlo[hbase + 8 * 68];
            const u32 al2 = sHlo[hbase + 4];
            const u32 al3 = sHlo[hbase + 8 * 68 + 4];
            const int ktg = h * 8 + ktl;
#pragma unroll
            for (int q = 0; q < 2; ++q) {
                const int nt2 = nhw * 2 + q;
                const uint4 bb = g_W2f[((ktg * 4 + nt2) << 5) + lane];
                mma_bf16(d2[q], ah0, ah1, ah2, ah3, bb.x, bb.y);
                mma_bf16(d2[q], ah0, ah1, ah2, ah3, bb.z, bb.w);
                mma_bf16(d2[q], al0, al1, al2, al3, bb.x, bb.y);
            }
        }
        __syncthreads();
    }

#pragma unroll
    for (int q = 0; q < 2; ++q) {
        const int nt2 = nhw * 2 + q;
        const int c0 = nt2 * 8 + 2 * lt;
        const int kk0 = mt * 16 + lg;
        const float bb0 = b2[c0];
        const float bb1 = b2[c0 + 1];
        sY2[(32 + c0) * SROW + kk0] = fmaxf(d2[q][0] + bb0, 0.f);
        sY2[(33 + c0) * SROW + kk0] = fmaxf(d2[q][1] + bb1, 0.f);
        sY2[(32 + c0) * SROW + kk0 + 8] = fmaxf(d2[q][2] + bb0, 0.f);
        sY2[(33 + c0) * SROW + kk0 + 8] = fmaxf(d2[q][3] + bb1, 0.f);
    }
    __syncthreads();

    const int cpair = t & 15;
    const int kq = t >> 4;
    const int kk2 = kq << 2;
    const int pq = kq >> 2;

    {   // mid: f32x2 k-pair packing, dup-packed weights
        ull aE01 = 0ull, aE23 = 0ull, aO01 = 0ull, aO23 = 0ull;
#pragma unroll 8
        for (int j = 0; j < 32; ++j) {
            const ulonglong2 wd = g_Wmid2[(j << 4) + cpair];
            const ulonglong2 av = *(const ulonglong2*)(sY2 + (32 + j) * SROW + kk2);
            aE01 = fma2(av.x, wd.x, aE01);
            aE23 = fma2(av.y, wd.x, aE23);
            aO01 = fma2(av.x, wd.y, aO01);
            aO23 = fma2(av.y, wd.y, aO23);
        }
        const float bx0 = sMidX[pq * 32 + 2 * cpair] + bmid[2 * cpair];
        const float bx1 = sMidX[pq * 32 + 2 * cpair + 1] + bmid[2 * cpair + 1];
        const float2 uE01 = unpack2(aE01), uE23 = unpack2(aE23);
        const float2 uO01 = unpack2(aO01), uO23 = unpack2(aO23);
        float4 r0, r1;
        r0.x = fmaxf(uE01.x + bx0, 0.f); r0.y = fmaxf(uE01.y + bx0, 0.f);
        r0.z = fmaxf(uE23.x + bx0, 0.f); r0.w = fmaxf(uE23.y + bx0, 0.f);
        r1.x = fmaxf(uO01.x + bx1, 0.f); r1.y = fmaxf(uO01.y + bx1, 0.f);
        r1.z = fmaxf(uO23.x + bx1, 0.f); r1.w = fmaxf(uO23.y + bx1, 0.f);
        *(float4*)(sY2 + (2 * cpair) * SROW + kk2) = r0;
        *(float4*)(sY2 + (2 * cpair + 1) * SROW + kk2) = r1;
    }
    __syncthreads();

    {   // ybar
        const int jj = t & 63;
        const int pp = t >> 6;
        const float* row = sY2 + jj * SROW + pp * 16;
        const float4 s0 = *(const float4*)(row + 0);
        const float4 s1 = *(const float4*)(row + 4);
        const float4 s2 = *(const float4*)(row + 8);
        const float4 s3 = *(const float4*)(row + 12);
        const float s = (s0.x + s0.y + s0.z + s0.w) + (s1.x + s1.y + s1.z + s1.w)
                      + (s2.x + s2.y + s2.z + s2.w) + (s3.x + s3.y + s3.z + s3.w);
        sYbar[pp * 64 + jj] = s * (1.0f / 16.0f);
    }
    __syncthreads();

    {   // gate partials: warp w covers j in [16w, 16w+16) for all 4p x 128c.
        // Partials land in the dead sHhi region (16KB alias).
        float* sPart = (float*)sHhi;
        const int jbase = w * 16;
        ull acc[2][4];
#pragma unroll
        for (int g = 0; g < 2; ++g)
#pragma unroll
            for (int p = 0; p < 4; ++p) acc[g][p] = 0ull;
#pragma unroll
        for (int jj = 0; jj < 16; ++jj) {
            const int j = jbase + jj;
            const ull wv0 = *(const ull*)(Wg + j * 128 + 2 * lane);
            const ull wv1 = *(const ull*)(Wg + j * 128 + 64 + 2 * lane);
#pragma unroll
            for (int p = 0; p < 4; ++p) {
                const float yv = (w < 4) ? sYbar[p * 64 + j]
                                         : sXn[p * 64 + (j - 64)];
                const ull yp = pack2(yv, yv);
                acc[0][p] = fma2(yp, wv0, acc[0][p]);
                acc[1][p] = fma2(yp, wv1, acc[1][p]);
            }
        }
#pragma unroll
        for (int p = 0; p < 4; ++p) {
            *(ull*)(sPart + w * 512 + p * 128 + 2 * lane) = acc[0][p];
            *(ull*)(sPart + w * 512 + p * 128 + 64 + 2 * lane) = acc[1][p];
        }
    }
    __syncthreads();

    {   // gate reduce (w ascending) + sigmoid
        float* sPart = (float*)sHhi;
        const int c2g = (t & 63) * 2;
        const int pg = t >> 6;
        ull s = *(const ull*)(sPart + pg * 128 + c2g);
#pragma unroll
        for (int wq = 1; wq < 8; ++wq)
            s = add2(s, *(const ull*)(sPart + wq * 512 + pg * 128 + c2g));
        const float2 u = unpack2(s);
        sGate[pg * 128 + c2g] = 1.0f / (1.0f + expf(-(u.x + bg[c2g])));
        sGate[pg * 128 + c2g + 1] = 1.0f / (1.0f + expf(-(u.y + bg[c2g + 1])));
    }
    __syncthreads();

    {   // xg; out 96..159
        const int c = t & 63;
        const int p = t >> 6;
        const float xg = sXn[p * 64 + c] * sGate[p * 128 + 64 + c];
        sXg[p * 64 + c] = xg;
        out[(g0 + p) * 160 + 96 + c] = xg;
    }
    __syncthreads();

    {   // y2 *= gate; out 32..95
        const int jj = t & 63;
        const int pp = t >> 6;
        const float gv = sGate[pp * 128 + jj];
        float* row = sY2 + jj * SROW + pp * 16;
        float mx = -3.0e38f;
#pragma unroll
        for (int q = 0; q < 4; ++q) {
            float4 v = *(const float4*)(row + 4 * q);
            v.x *= gv; v.y *= gv; v.z *= gv; v.w *= gv;
            mx = fmaxf(mx, fmaxf(fmaxf(v.x, v.y), fmaxf(v.z, v.w)));
            *(float4*)(row + 4 * q) = v;
        }
        out[(g0 + pp) * 160 + 32 + jj] = mx;
    }
    if (t < 128) {  // last_x
        const int p = t >> 5;
        const int c = t & 31;
        float a = 0.f;
#pragma unroll 8
        for (int j = 0; j < 64; ++j)
            a = __fmaf_rn(sXg[p * 64 + j], Wlast[(64 + j) * 32 + c], a);
        sLastX[p * 32 + c] = a;
    }
    __syncthreads();

    float* sRed = sXh;
    {   // last: f32x2 k-pair packing, dup-packed weights; out 0..31
        ull aE01 = 0ull, aE23 = 0ull, aO01 = 0ull, aO23 = 0ull;
#pragma unroll 8
        for (int j = 0; j < 64; ++j) {
            const ulonglong2 wd = g_Wlast2[(j << 4) + cpair];
            const ulonglong2 av = *(const ulonglong2*)(sY2 + j * SROW + kk2);
            aE01 = fma2(av.x, wd.x, aE01);
            aE23 = fma2(av.y, wd.x, aE23);
            aO01 = fma2(av.x, wd.y, aO01);
            aO23 = fma2(av.y, wd.y, aO23);
        }
        const float t0 = sLastX[pq * 32 + 2 * cpair] + blast[2 * cpair];
        const float t1 = sLastX[pq * 32 + 2 * cpair + 1] + blast[2 * cpair + 1];
        const float2 uE01 = unpack2(aE01), uE23 = unpack2(aE23);
        const float2 uO01 = unpack2(aO01), uO23 = unpack2(aO23);
        const float mx0 = fmaxf(fmaxf(uE01.x + t0, uE01.y + t0),
                                fmaxf(uE23.x + t0, uE23.y + t0));
        const float mx1 = fmaxf(fmaxf(uO01.x + t1, uO01.y + t1),
                                fmaxf(uO23.x + t1, uO23.y + t1));
        sRed[kq * 32 + 2 * cpair] = mx0;
        sRed[kq * 32 + 2 * cpair + 1] = mx1;
    }
    __syncthreads();
    if (t < 128) {
        const int p = t >> 5;
        const int cc = t & 31;
        float mx = sRed[(p * 4 + 0) * 32 + cc];
        mx = fmaxf(mx, sRed[(p * 4 + 1) * 32 + cc]);
        mx = fmaxf(mx, sRed[(p * 4 + 2) * 32 + cc]);
        mx = fmaxf(mx, sRed[(p * 4 + 3) * 32 + cc]);
        out[(g0 + p) * 160 + cc] = mx;
    }
}

// ---------------------------------------------------------------------------
extern "C" void kernel_launch(void* const* d_in, const int* in_sizes, int n_in,
                              void* d_out, int out_size) {
    const float* x = (const float*)d_in[0];
    const float* pos = (const float*)d_in[1];
    const float* W1 = (const float*)d_in[2];
    const float* b1 = (const float*)d_in[3];
    const float* W2 = (const float*)d_in[4];
    const float* b2 = (const float*)d_in[5];
    const float* Wmid = (const float*)d_in[6];
    const float* bmid = (const float*)d_in[7];
    const float* Wg = (const float*)d_in[8];
    const float* bg = (const float*)d_in[9];
    const float* Wlast = (const float*)d_in[10];
    const float* blast = (const float*)d_in[11];
    float* out = (float*)d_out;

    const int smem_bytes = SMEM_U32 * 4;
    cudaFuncSetAttribute(conv_kernel, cudaFuncAttributeMaxDynamicSharedMemorySize,
                         smem_bytes);

    knn_prep_kernel<<<256 + 128, 128>>>(pos, W1, W2, Wmid, Wlast);
    conv_kernel<<<(Bb * Nn) / P4, 256, smem_bytes>>>(
        x, b1, W2, b2, Wmid, bmid, Wg, bg, Wlast, blast, out);
}

// round 16
// speedup vs baseline: 1.6078x; 1.0274x over previous
#include <cuda_runtime.h>
#include <cuda_bf16.h>

#define Bb 8
#define Nn 4096

typedef unsigned long long ull;
typedef unsigned int u32;

// scratch
__device__ int g_nbr[Bb * Nn * 16];
__device__ float g_W1p[64 * 256];       // W1[0:64] - W1[128:192] (x part, fp32)
__device__ uint4 g_W1f[4 * 32 * 32];    // W1n frag-packed bf16 hi/lo
__device__ uint4 g_W2f[16 * 4 * 32];    // W2 frag-packed bf16 hi/lo
__device__ ulonglong2 g_Wmid2[32 * 16]; // Wmid[0:32] dup-packed f32x2 pairs
__device__ ulonglong2 g_Wlast2[64 * 16];// Wlast[0:64] dup-packed f32x2 pairs

// ---------------------------------------------------------------------------
__device__ __forceinline__ ull pack2(float a, float b) {
    ull r;
    asm("mov.b64 %0, {%1, %2};" : "=l"(r) : "f"(a), "f"(b));
    return r;
}
__device__ __forceinline__ ull fma2(ull a, ull b, ull c) {
    ull d;
    asm("fma.rn.f32x2 %0, %1, %2, %3;" : "=l"(d) : "l"(a), "l"(b), "l"(c));
    return d;
}
__device__ __forceinline__ ull add2(ull a, ull b) {
    ull d;
    asm("add.rn.f32x2 %0, %1, %2;" : "=l"(d) : "l"(a), "l"(b));
    return d;
}
__device__ __forceinline__ float2 unpack2(ull v) {
    float2 f;
    asm("mov.b64 {%0, %1}, %2;" : "=f"(f.x), "=f"(f.y) : "l"(v));
    return f;
}

// split (a,b) into bf16x2 hi + bf16x2 lo residual (RN per half).
__device__ __forceinline__ void split2(float a, float b, u32& hi, u32& lo) {
    u32 h;
    asm("cvt.rn.bf16x2.f32 %0, %1, %2;" : "=r"(h) : "f"(b), "f"(a));
    const float fa = __uint_as_float(h << 16);
    const float fb = __uint_as_float(h & 0xffff0000u);
    const float ra = a - fa;
    const float rb = b - fb;
    u32 l;
    asm("cvt.rn.bf16x2.f32 %0, %1, %2;" : "=r"(l) : "f"(rb), "f"(ra));
    hi = h;
    lo = l;
}

__device__ __forceinline__ void mma_bf16(float* d, u32 a0, u32 a1, u32 a2, u32 a3,
                                         u32 b0, u32 b1) {
    asm volatile(
        "mma.sync.aligned.m16n8k16.row.col.f32.bf16.bf16.f32 "
        "{%0,%1,%2,%3}, {%4,%5,%6,%7}, {%8,%9}, {%0,%1,%2,%3};"
        : "+f"(d[0]), "+f"(d[1]), "+f"(d[2]), "+f"(d[3])
        : "r"(a0), "r"(a1), "r"(a2), "r"(a3), "r"(b0), "r"(b1));
}

// ---------------------------------------------------------------------------
// Kernel 1: KNN (blocks 0..255, smem heap) + weight prep (blocks 256..383).
// ---------------------------------------------------------------------------
__global__ __launch_bounds__(128) void knn_prep_kernel(const float* __restrict__ pos,
                                                       const float* __restrict__ W1,
                                                       const float* __restrict__ W2,
                                                       const float* __restrict__ Wmid,
                                                       const float* __restrict__ Wlast) {
    const int bx = blockIdx.x;
    const int t = threadIdx.x;
    if (bx >= 256) {
        const int i = (bx - 256) * 128 + t;             // 0..16383
        {   // W1p (x-part, fp32)
            const int j = i >> 8;
            const int c = i & 255;
            g_W1p[i] = W1[j * 256 + c] - W1[(128 + j) * 256 + c];
        }
        if (i < 4096) {     // W1n frag pack: [kt 0..3][nt 0..31][lane]
            const int lane = i & 31;
            const int nt = (i >> 5) & 31;
            const int kt = i >> 10;
            const int j0 = kt * 16 + (lane & 3) * 2;
            const int n = nt * 8 + (lane >> 2);
            const float w00 = W1[(64 + j0) * 256 + n] + W1[(128 + j0) * 256 + n];
            const float w01 = W1[(64 + j0 + 1) * 256 + n] + W1[(128 + j0 + 1) * 256 + n];
            const float w10 = W1[(64 + j0 + 8) * 256 + n] + W1[(128 + j0 + 8) * 256 + n];
            const float w11 = W1[(64 + j0 + 9) * 256 + n] + W1[(128 + j0 + 9) * 256 + n];
            u32 h0, l0, h1, l1;
            split2(w00, w01, h0, l0);
            split2(w10, w11, h1, l1);
            g_W1f[i] = make_uint4(h0, h1, l0, l1);
        }
        if (i < 2048) {     // W2 frag pack: [kt 0..15][nt 0..3][lane]
            const int lane = i & 31;
            const int nt = (i >> 5) & 3;
            const int kt = i >> 7;
            const int j0 = kt * 16 + (lane & 3) * 2;
            const int n = nt * 8 + (lane >> 2);
            u32 h0, l0, h1, l1;
            split2(W2[j0 * 32 + n], W2[(j0 + 1) * 32 + n], h0, l0);
            split2(W2[(j0 + 8) * 32 + n], W2[(j0 + 9) * 32 + n], h1, l1);
            g_W2f[i] = make_uint4(h0, h1, l0, l1);
        }
        if (i < 512) {      // Wmid[0:32] dup-packed: [j][cpair]
            const int j = i >> 4;
            const int cp = i & 15;
            const float we = Wmid[j * 32 + 2 * cp];
            const float wo = Wmid[j * 32 + 2 * cp + 1];
            g_Wmid2[i] = make_ulonglong2(pack2(we, we), pack2(wo, wo));
        }
        if (i < 1024) {     // Wlast[0:64] dup-packed: [j][cpair]
            const int j = i >> 4;
            const int cp = i & 15;
            const float we = Wlast[j * 32 + 2 * cp];
            const float wo = Wlast[j * 32 + 2 * cp + 1];
            g_Wlast2[i] = make_ulonglong2(pack2(we, we), pack2(wo, wo));
        }
        return;
    }

    const int b = bx >> 5;
    const int n = ((bx & 31) << 7) + t;

    const float qx = pos[(b * Nn + n) * 3 + 0];
    const float qy = pos[(b * Nn + n) * 3 + 1];
    const float qz = pos[(b * Nn + n) * 3 + 2];
    const float sqn = __fadd_rn(__fadd_rn(__fmul_rn(qx, qx), __fmul_rn(qy, qy)),
                                __fmul_rn(qz, qz));

    __shared__ float4 tile[1024];
    __shared__ float bdS[16][128];
    __shared__ int biS[16][128];

#pragma unroll
    for (int j = 0; j < 16; ++j) { bdS[j][t] = 3.0e38f; biS[j][t] = 0; }
    float worst = 3.0e38f;
    int wslot = 0;

    for (int t0 = 0; t0 < Nn; t0 += 1024) {
        __syncthreads();
        for (int i = t; i < 1024; i += 128) {
            const float px = pos[(b * Nn + t0 + i) * 3 + 0];
            const float py = pos[(b * Nn + t0 + i) * 3 + 1];
            const float pz = pos[(b * Nn + t0 + i) * 3 + 2];
            const float sq = __fadd_rn(__fadd_rn(__fmul_rn(px, px), __fmul_rn(py, py)),
                                       __fmul_rn(pz, pz));
            tile[i] = make_float4(px, py, pz, sq);
        }
        __syncthreads();
#pragma unroll 4
        for (int i = 0; i < 1024; ++i) {
            const float4 c = tile[i];
            const int m = t0 + i;
            float dot = __fmaf_rn(qx, c.x, 0.f);
            dot = __fmaf_rn(qy, c.y, dot);
            dot = __fmaf_rn(qz, c.z, dot);
            const float dist = __fsub_rn(__fadd_rn(sqn, c.w), __fmul_rn(2.0f, dot));
            const bool need = (dist < worst) && (m != n);
            if (__ballot_sync(0xffffffffu, need)) {
                if (need) {
                    bdS[wslot][t] = dist;
                    biS[wslot][t] = m;
                }
                float d0 = bdS[0][t], d1 = bdS[1][t], d2v = bdS[2][t], d3 = bdS[3][t];
                float d4 = bdS[4][t], d5 = bdS[5][t], d6 = bdS[6][t], d7 = bdS[7][t];
                float d8 = bdS[8][t], d9 = bdS[9][t], d10 = bdS[10][t], d11 = bdS[11][t];
                float d12 = bdS[12][t], d13 = bdS[13][t], d14 = bdS[14][t], d15 = bdS[15][t];
                float v0, v1, v2, v3, v4, v5, v6, v7;
                int s0, s1, s2, s3, s4, s5, s6, s7;
                v0 = (d0 >= d1) ? d0 : d1;      s0 = (d0 >= d1) ? 0 : 1;
                v1 = (d2v >= d3) ? d2v : d3;    s1 = (d2v >= d3) ? 2 : 3;
                v2 = (d4 >= d5) ? d4 : d5;      s2 = (d4 >= d5) ? 4 : 5;
                v3 = (d6 >= d7) ? d6 : d7;      s3 = (d6 >= d7) ? 6 : 7;
                v4 = (d8 >= d9) ? d8 : d9;      s4 = (d8 >= d9) ? 8 : 9;
                v5 = (d10 >= d11) ? d10 : d11;  s5 = (d10 >= d11) ? 10 : 11;
                v6 = (d12 >= d13) ? d12 : d13;  s6 = (d12 >= d13) ? 12 : 13;
                v7 = (d14 >= d15) ? d14 : d15;  s7 = (d14 >= d15) ? 14 : 15;
                s0 = (v0 >= v1) ? s0 : s1;  v0 = (v0 >= v1) ? v0 : v1;
                s2 = (v2 >= v3) ? s2 : s3;  v2 = (v2 >= v3) ? v2 : v3;
                s4 = (v4 >= v5) ? s4 : s5;  v4 = (v4 >= v5) ? v4 : v5;
                s6 = (v6 >= v7) ? s6 : s7;  v6 = (v6 >= v7) ? v6 : v7;
                s0 = (v0 >= v2) ? s0 : s2;  v0 = (v0 >= v2) ? v0 : v2;
                s4 = (v4 >= v6) ? s4 : s6;  v4 = (v4 >= v6) ? v4 : v6;
                wslot = (v0 >= v4) ? s0 : s4;
                worst = (v0 >= v4) ? v0 : v4;
            }
        }
    }

#pragma unroll
    for (int j = 0; j < 16; ++j)
        g_nbr[(b * Nn + n) * 16 + j] = biS[j][t];
}

// ---------------------------------------------------------------------------
// Kernel 2: fused DenseEdgeConv. GEMM1 uses mt-pair warps (B LDG halved);
// GEMM2 keeps single-mt layout. Scalar tail as round 15.
// ---------------------------------------------------------------------------
#define P4 4
#define SROW 68

#define OFF_AHI   0
#define OFF_ALO   (OFF_AHI + 64 * 36)
#define OFF_Y2    0
#define OFF_HHI   (OFF_ALO + 64 * 36)
#define OFF_HLO   (OFF_HHI + 64 * 68)
#define OFF_XH    (OFF_HLO + 64 * 68)
#define OFF_XN    (OFF_XH + P4 * 256)
#define OFF_MIDX  (OFF_XN + P4 * 64)
#define OFF_XG    (OFF_MIDX + P4 * 32)
#define OFF_YBAR  (OFF_XG + P4 * 64)
#define OFF_GATE  (OFF_YBAR + P4 * 64)
#define OFF_LASTX (OFF_GATE + P4 * 128)
#define OFF_NID   (OFF_LASTX + P4 * 32)
#define SMEM_U32  (OFF_NID + 64)

__global__ __launch_bounds__(256, 2) void conv_kernel(
    const float* __restrict__ x,
    const float* __restrict__ b1,
    const float* __restrict__ W2, const float* __restrict__ b2,
    const float* __restrict__ Wmid, const float* __restrict__ bmid,
    const float* __restrict__ Wg, const float* __restrict__ bg,
    const float* __restrict__ Wlast, const float* __restrict__ blast,
    float* __restrict__ out)
{
    extern __shared__ float sm[];
    u32* sAhi = (u32*)sm + OFF_AHI;
    u32* sAlo = (u32*)sm + OFF_ALO;
    u32* sHhi = (u32*)sm + OFF_HHI;
    u32* sHlo = (u32*)sm + OFF_HLO;
    float* sY2 = sm + OFF_Y2;
    float* sXh = sm + OFF_XH;
    float* sXn = sm + OFF_XN;
    float* sMidX = sm + OFF_MIDX;
    float* sXg = sm + OFF_XG;
    float* sYbar = sm + OFF_YBAR;
    float* sGate = sm + OFF_GATE;
    float* sLastX = sm + OFF_LASTX;
    int* sNid = (int*)((u32*)sm + OFF_NID);

    const int t = threadIdx.x;
    const int g0 = blockIdx.x * P4;
    const int b = g0 >> 12;

    sXn[t] = x[(g0 + (t >> 6)) * 64 + (t & 63)];
    if (t < 64) sNid[t] = g_nbr[g0 * 16 + t];
    __syncthreads();

#pragma unroll
    for (int it = 0; it < 4; ++it) {
        const int idx = it * 256 + t;
        const int kk = idx >> 4;
        const int c4 = (idx & 15) << 2;
        const float4 v = *(const float4*)(x + (b * Nn + sNid[kk]) * 64 + c4);
        u32 h0, l0, h1, l1;
        split2(v.x, v.y, h0, l0);
        split2(v.z, v.w, h1, l1);
        const int base = kk * 36 + (c4 >> 1);
        sAhi[base] = h0; sAhi[base + 1] = h1;
        sAlo[base] = l0; sAlo[base + 1] = l1;
    }
    if (t < 128) {
        const int c0 = t;
        float a[4][2];
#pragma unroll
        for (int p = 0; p < 4; ++p) { a[p][0] = 0.f; a[p][1] = 0.f; }
#pragma unroll 8
        for (int j = 0; j < 64; ++j) {
            const float w0 = g_W1p[j * 256 + c0];
            const float w1 = g_W1p[j * 256 + c0 + 128];
#pragma unroll
            for (int p = 0; p < 4; ++p) {
                const float xv = sXn[p * 64 + j];
                a[p][0] = __fmaf_rn(xv, w0, a[p][0]);
                a[p][1] = __fmaf_rn(xv, w1, a[p][1]);
            }
        }
        const float bb0 = b1[c0];
        const float bb1 = b1[c0 + 128];
#pragma unroll
        for (int p = 0; p < 4; ++p) {
            sXh[p * 256 + c0] = a[p][0] + bb0;
            sXh[p * 256 + c0 + 128] = a[p][1] + bb1;
        }
    } else {
        const int p = (t >> 5) & 3;
        const int c = t & 31;
        float a = 0.f;
#pragma unroll 4
        for (int j = 0; j < 64; ++j)
            a = __fmaf_rn(sXn[p * 64 + j], Wmid[(32 + j) * 32 + c], a);
        sMidX[p * 32 + c] = a;
    }
    __syncthreads();

    const int lane = t & 31;
    const int w = t >> 5;
    const int lt = lane & 3;
    const int lg = lane >> 2;
    // GEMM1 layout: warp = (mtp: 2 point-pair) x (ng: 4 nt-groups)
    const int mtp = w & 1;
    const int ng = w >> 1;
    // GEMM2 layout (unchanged): warp = (mt: 4 points) x (nhw: 2 n-halves)
    const int mt = w & 3;
    const int nhw = w >> 2;

    float d2[2][4];
#pragma unroll
    for (int q = 0; q < 2; ++q)
#pragma unroll
        for (int r = 0; r < 4; ++r) d2[q][r] = 0.f;

#pragma unroll
    for (int h = 0; h < 2; ++h) {
        // ---- GEMM1 half: warp covers 2 m-tiles x 4 n-tiles ----------------
        float d1[2][4][4];
#pragma unroll
        for (int mi = 0; mi < 2; ++mi)
#pragma unroll
            for (int nt = 0; nt < 4; ++nt)
#pragma unroll
                for (int r = 0; r < 4; ++r) d1[mi][nt][r] = 0.f;

#pragma unroll
        for (int kt = 0; kt < 4; ++kt) {
            u32 ah[2][4], al[2][4];
#pragma unroll
            for (int mi = 0; mi < 2; ++mi) {
                const int abase = ((mtp * 2 + mi) * 16 + lg) * 36 + kt * 8 + lt;
                ah[mi][0] = sAhi[abase];
                ah[mi][1] = sAhi[abase + 8 * 36];
                ah[mi][2] = sAhi[abase + 4];
                ah[mi][3] = sAhi[abase + 8 * 36 + 4];
                al[mi][0] = sAlo[abase];
                al[mi][1] = sAlo[abase + 8 * 36];
                al[mi][2] = sAlo[abase + 4];
                al[mi][3] = sAlo[abase + 8 * 36 + 4];
            }
#pragma unroll
            for (int nt = 0; nt < 4; ++nt) {
                const int ntg = h * 16 + ng * 4 + nt;
                const uint4 bb = g_W1f[((kt * 32 + ntg) << 5) + lane];
#pragma unroll
                for (int mi = 0; mi < 2; ++mi) {
                    mma_bf16(d1[mi][nt], ah[mi][0], ah[mi][1], ah[mi][2], ah[mi][3],
                             bb.x, bb.y);
                    mma_bf16(d1[mi][nt], ah[mi][0], ah[mi][1], ah[mi][2], ah[mi][3],
                             bb.z, bb.w);
                    mma_bf16(d1[mi][nt], al[mi][0], al[mi][1], al[mi][2], al[mi][3],
                             bb.x, bb.y);
                }
            }
        }
        // epilogue: + xh, relu, bf16-split, store to sH
#pragma unroll
        for (int mi = 0; mi < 2; ++mi) {
#pragma unroll
            for (int nt = 0; nt < 4; ++nt) {
                const int ntg = h * 16 + ng * 4 + nt;
                const int c0 = ntg * 8 + 2 * lt;
                const int p = mtp * 2 + mi;
                const float xh0 = sXh[p * 256 + c0];
                const float xh1 = sXh[p * 256 + c0 + 1];
                const float v0 = fmaxf(d1[mi][nt][0] + xh0, 0.f);
                const float v1 = fmaxf(d1[mi][nt][1] + xh1, 0.f);
                const float v2 = fmaxf(d1[mi][nt][2] + xh0, 0.f);
                const float v3 = fmaxf(d1[mi][nt][3] + xh1, 0.f);
                u32 h01, l01, h23, l23;
                split2(v0, v1, h01, l01);
                split2(v2, v3, h23, l23);
                const int pair = (ng * 4 + nt) * 4 + lt;
                const int r0 = p * 16 + lg;
                sHhi[r0 * 68 + pair] = h01;
                sHhi[(r0 + 8) * 68 + pair] = h23;
                sHlo[r0 * 68 + pair] = l01;
                sHlo[(r0 + 8) * 68 + pair] = l23;
            }
        }
        __syncthreads();

        // ---- GEMM2 partial: K-tiles ktg = h*8 .. h*8+7 (old layout) --------
#pragma unroll
        for (int ktl = 0; ktl < 8; ++ktl) {
            const int hbase = (mt * 16 + lg) * 68 + ktl * 8 + lt;
            const u32 ah0 = sHhi[hbase];
            const u32 ah1 = sHhi[hbase + 8 * 68];
            const u32 ah2 = sHhi[hbase + 4];
            const u32 ah3 = sHhi[hbase + 8 * 68 + 4];
            const u32 al0 = sHlo[hbase];
            const u32 al1 = sHlo[hbase + 8 * 68];
            const u32 al2 = sHlo[hbase + 4];
            const u32 al3 = sHlo[hbase + 8 * 68 + 4];
            const int ktg = h * 8 + ktl;
#pragma unroll
            for (int q = 0; q < 2; ++q) {
                const int nt2 = nhw * 2 + q;
                const uint4 bb = g_W2f[((ktg * 4 + nt2) << 5) + lane];
                mma_bf16(d2[q], ah0, ah1, ah2, ah3, bb.x, bb.y);
                mma_bf16(d2[q], ah0, ah1, ah2, ah3, bb.z, bb.w);
                mma_bf16(d2[q], al0, al1, al2, al3, bb.x, bb.y);
            }
        }
        __syncthreads();
    }

#pragma unroll
    for (int q = 0; q < 2; ++q) {
        const int nt2 = nhw * 2 + q;
        const int c0 = nt2 * 8 + 2 * lt;
        const int kk0 = mt * 16 + lg;
        const float bb0 = b2[c0];
        const float bb1 = b2[c0 + 1];
        sY2[(32 + c0) * SROW + kk0] = fmaxf(d2[q][0] + bb0, 0.f);
        sY2[(33 + c0) * SROW + kk0] = fmaxf(d2[q][1] + bb1, 0.f);
        sY2[(32 + c0) * SROW + kk0 + 8] = fmaxf(d2[q][2] + bb0, 0.f);
        sY2[(33 + c0) * SROW + kk0 + 8] = fmaxf(d2[q][3] + bb1, 0.f);
    }
    __syncthreads();

    const int cpair = t & 15;
    const int kq = t >> 4;
    const int kk2 = kq << 2;
    const int pq = kq >> 2;

    {   // mid: f32x2 k-pair packing, dup-packed weights
        ull aE01 = 0ull, aE23 = 0ull, aO01 = 0ull, aO23 = 0ull;
#pragma unroll 8
        for (int j = 0; j < 32; ++j) {
            const ulonglong2 wd = g_Wmid2[(j << 4) + cpair];
            const ulonglong2 av = *(const ulonglong2*)(sY2 + (32 + j) * SROW + kk2);
            aE01 = fma2(av.x, wd.x, aE01);
            aE23 = fma2(av.y, wd.x, aE23);
            aO01 = fma2(av.x, wd.y, aO01);
            aO23 = fma2(av.y, wd.y, aO23);
        }
        const float bx0 = sMidX[pq * 32 + 2 * cpair] + bmid[2 * cpair];
        const float bx1 = sMidX[pq * 32 + 2 * cpair + 1] + bmid[2 * cpair + 1];
        const float2 uE01 = unpack2(aE01), uE23 = unpack2(aE23);
        const float2 uO01 = unpack2(aO01), uO23 = unpack2(aO23);
        float4 r0, r1;
        r0.x = fmaxf(uE01.x + bx0, 0.f); r0.y = fmaxf(uE01.y + bx0, 0.f);
        r0.z = fmaxf(uE23.x + bx0, 0.f); r0.w = fmaxf(uE23.y + bx0, 0.f);
        r1.x = fmaxf(uO01.x + bx1, 0.f); r1.y = fmaxf(uO01.y + bx1, 0.f);
        r1.z = fmaxf(uO23.x + bx1, 0.f); r1.w = fmaxf(uO23.y + bx1, 0.f);
        *(float4*)(sY2 + (2 * cpair) * SROW + kk2) = r0;
        *(float4*)(sY2 + (2 * cpair + 1) * SROW + kk2) = r1;
    }
    __syncthreads();

    {   // ybar
        const int jj = t & 63;
        const int pp = t >> 6;
        const float* row = sY2 + jj * SROW + pp * 16;
        const float4 s0 = *(const float4*)(row + 0);
        const float4 s1 = *(const float4*)(row + 4);
        const float4 s2 = *(const float4*)(row + 8);
        const float4 s3 = *(const float4*)(row + 12);
        const float s = (s0.x + s0.y + s0.z + s0.w) + (s1.x + s1.y + s1.z + s1.w)
                      + (s2.x + s2.y + s2.z + s2.w) + (s3.x + s3.y + s3.z + s3.w);
        sYbar[pp * 64 + jj] = s * (1.0f / 16.0f);
    }
    __syncthreads();

    {   // gate partials: warp w covers j in [16w, 16w+16)
        float* sPart = (float*)sHhi;
        const int jbase = w * 16;
        ull acc[2][4];
#pragma unroll
        for (int g = 0; g < 2; ++g)
#pragma unroll
            for (int p = 0; p < 4; ++p) acc[g][p] = 0ull;
#pragma unroll
        for (int jj = 0; jj < 16; ++jj) {
            const int j = jbase + jj;
            const ull wv0 = *(const ull*)(Wg + j * 128 + 2 * lane);
            const ull wv1 = *(const ull*)(Wg + j * 128 + 64 + 2 * lane);
#pragma unroll
            for (int p = 0; p < 4; ++p) {
                const float yv = (w < 4) ? sYbar[p * 64 + j]
                                         : sXn[p * 64 + (j - 64)];
                const ull yp = pack2(yv, yv);
                acc[0][p] = fma2(yp, wv0, acc[0][p]);
                acc[1][p] = fma2(yp, wv1, acc[1][p]);
            }
        }
#pragma unroll
        for (int p = 0; p < 4; ++p) {
            *(ull*)(sPart + w * 512 + p * 128 + 2 * lane) = acc[0][p];
            *(ull*)(sPart + w * 512 + p * 128 + 64 + 2 * lane) = acc[1][p];
        }
    }
    __syncthreads();

    {   // gate reduce (w ascending) + sigmoid
        float* sPart = (float*)sHhi;
        const int c2g = (t & 63) * 2;
        const int pg = t >> 6;
        ull s = *(const ull*)(sPart + pg * 128 + c2g);
#pragma unroll
        for (int wq = 1; wq < 8; ++wq)
            s = add2(s, *(const ull*)(sPart + wq * 512 + pg * 128 + c2g));
        const float2 u = unpack2(s);
        sGate[pg * 128 + c2g] = 1.0f / (1.0f + expf(-(u.x + bg[c2g])));
        sGate[pg * 128 + c2g + 1] = 1.0f / (1.0f + expf(-(u.y + bg[c2g + 1])));
    }
    __syncthreads();

    {   // xg; out 96..159
        const int c = t & 63;
        const int p = t >> 6;
        const float xg = sXn[p * 64 + c] * sGate[p * 128 + 64 + c];
        sXg[p * 64 + c] = xg;
        out[(g0 + p) * 160 + 96 + c] = xg;
    }
    __syncthreads();

    {   // y2 *= gate; out 32..95
        const int jj = t & 63;
        const int pp = t >> 6;
        const float gv = sGate[pp * 128 + jj];
        float* row = sY2 + jj * SROW + pp * 16;
        float mx = -3.0e38f;
#pragma unroll
        for (int q = 0; q < 4; ++q) {
            float4 v = *(const float4*)(row + 4 * q);
            v.x *= gv; v.y *= gv; v.z *= gv; v.w *= gv;
            mx = fmaxf(mx, fmaxf(fmaxf(v.x, v.y), fmaxf(v.z, v.w)));
            *(float4*)(row + 4 * q) = v;
        }
        out[(g0 + pp) * 160 + 32 + jj] = mx;
    }
    if (t < 128) {  // last_x
        const int p = t >> 5;
        const int c = t & 31;
        float a = 0.f;
#pragma unroll 8
        for (int j = 0; j < 64; ++j)
            a = __fmaf_rn(sXg[p * 64 + j], Wlast[(64 + j) * 32 + c], a);
        sLastX[p * 32 + c] = a;
    }
    __syncthreads();

    float* sRed = sXh;
    {   // last: f32x2 k-pair packing, dup-packed weights; out 0..31
        ull aE01 = 0ull, aE23 = 0ull, aO01 = 0ull, aO23 = 0ull;
#pragma unroll 8
        for (int j = 0; j < 64; ++j) {
            const ulonglong2 wd = g_Wlast2[(j << 4) + cpair];
            const ulonglong2 av = *(const ulonglong2*)(sY2 + j * SROW + kk2);
            aE01 = fma2(av.x, wd.x, aE01);
            aE23 = fma2(av.y, wd.x, aE23);
            aO01 = fma2(av.x, wd.y, aO01);
            aO23 = fma2(av.y, wd.y, aO23);
        }
        const float t0 = sLastX[pq * 32 + 2 * cpair] + blast[2 * cpair];
        const float t1 = sLastX[pq * 32 + 2 * cpair + 1] + blast[2 * cpair + 1];
        const float2 uE01 = unpack2(aE01), uE23 = unpack2(aE23);
        const float2 uO01 = unpack2(aO01), uO23 = unpack2(aO23);
        const float mx0 = fmaxf(fmaxf(uE01.x + t0, uE01.y + t0),
                                fmaxf(uE23.x + t0, uE23.y + t0));
        const float mx1 = fmaxf(fmaxf(uO01.x + t1, uO01.y + t1),
                                fmaxf(uO23.x + t1, uO23.y + t1));
        sRed[kq * 32 + 2 * cpair] = mx0;
        sRed[kq * 32 + 2 * cpair + 1] = mx1;
    }
    __syncthreads();
    if (t < 128) {
        const int p = t >> 5;
        const int cc = t & 31;
        float mx = sRed[(p * 4 + 0) * 32 + cc];
        mx = fmaxf(mx, sRed[(p * 4 + 1) * 32 + cc]);
        mx = fmaxf(mx, sRed[(p * 4 + 2) * 32 + cc]);
        mx = fmaxf(mx, sRed[(p * 4 + 3) * 32 + cc]);
        out[(g0 + p) * 160 + cc] = mx;
    }
}

// ---------------------------------------------------------------------------
extern "C" void kernel_launch(void* const* d_in, const int* in_sizes, int n_in,
                              void* d_out, int out_size) {
    const float* x = (const float*)d_in[0];
    const float* pos = (const float*)d_in[1];
    const float* W1 = (const float*)d_in[2];
    const float* b1 = (const float*)d_in[3];
    const float* W2 = (const float*)d_in[4];
    const float* b2 = (const float*)d_in[5];
    const float* Wmid = (const float*)d_in[6];
    const float* bmid = (const float*)d_in[7];
    const float* Wg = (const float*)d_in[8];
    const float* bg = (const float*)d_in[9];
    const float* Wlast = (const float*)d_in[10];
    const float* blast = (const float*)d_in[11];
    float* out = (float*)d_out;

    const int smem_bytes = SMEM_U32 * 4;
    cudaFuncSetAttribute(conv_kernel, cudaFuncAttributeMaxDynamicSharedMemorySize,
                         smem_bytes);

    knn_prep_kernel<<<256 + 128, 128>>>(pos, W1, W2, Wmid, Wlast);
    conv_kernel<<<(Bb * Nn) / P4, 256, smem_bytes>>>(
        x, b1, W2, b2, Wmid, bmid, Wg, bg, Wlast, blast, out);
}

// round 17
// speedup vs baseline: 1.6471x; 1.0244x over previous
#include <cuda_runtime.h>
#include <cuda_bf16.h>

#define Bb 8
#define Nn 4096

typedef unsigned long long ull;
typedef unsigned int u32;

// scratch
__device__ int g_nbr[Bb * Nn * 16];
__device__ uint4 g_W1f[4 * 32 * 32];    // W1n frag-packed bf16 hi/lo
__device__ uint4 g_W1pf[4 * 32 * 32];   // W1p (x-part) frag-packed bf16 hi/lo
__device__ uint4 g_W2f[16 * 4 * 32];    // W2 frag-packed bf16 hi/lo
__device__ uint4 g_Wmidf[4 * 4 * 32];   // Wmid[32:96] frag-packed bf16 hi/lo
__device__ ulonglong2 g_Wmid2[32 * 16]; // Wmid[0:32] dup-packed f32x2 pairs
__device__ ulonglong2 g_Wlast2[64 * 16];// Wlast[0:64] dup-packed f32x2 pairs

// ---------------------------------------------------------------------------
__device__ __forceinline__ ull pack2(float a, float b) {
    ull r;
    asm("mov.b64 %0, {%1, %2};" : "=l"(r) : "f"(a), "f"(b));
    return r;
}
__device__ __forceinline__ ull fma2(ull a, ull b, ull c) {
    ull d;
    asm("fma.rn.f32x2 %0, %1, %2, %3;" : "=l"(d) : "l"(a), "l"(b), "l"(c));
    return d;
}
__device__ __forceinline__ ull add2(ull a, ull b) {
    ull d;
    asm("add.rn.f32x2 %0, %1, %2;" : "=l"(d) : "l"(a), "l"(b));
    return d;
}
__device__ __forceinline__ float2 unpack2(ull v) {
    float2 f;
    asm("mov.b64 {%0, %1}, %2;" : "=f"(f.x), "=f"(f.y) : "l"(v));
    return f;
}

// split (a,b) into bf16x2 hi + bf16x2 lo residual (RN per half).
__device__ __forceinline__ void split2(float a, float b, u32& hi, u32& lo) {
    u32 h;
    asm("cvt.rn.bf16x2.f32 %0, %1, %2;" : "=r"(h) : "f"(b), "f"(a));
    const float fa = __uint_as_float(h << 16);
    const float fb = __uint_as_float(h & 0xffff0000u);
    const float ra = a - fa;
    const float rb = b - fb;
    u32 l;
    asm("cvt.rn.bf16x2.f32 %0, %1, %2;" : "=r"(l) : "f"(rb), "f"(ra));
    hi = h;
    lo = l;
}

__device__ __forceinline__ void mma_bf16(float* d, u32 a0, u32 a1, u32 a2, u32 a3,
                                         u32 b0, u32 b1) {
    asm volatile(
        "mma.sync.aligned.m16n8k16.row.col.f32.bf16.bf16.f32 "
        "{%0,%1,%2,%3}, {%4,%5,%6,%7}, {%8,%9}, {%0,%1,%2,%3};"
        : "+f"(d[0]), "+f"(d[1]), "+f"(d[2]), "+f"(d[3])
        : "r"(a0), "r"(a1), "r"(a2), "r"(a3), "r"(b0), "r"(b1));
}

// ---------------------------------------------------------------------------
// Kernel 1: KNN (blocks 0..255, smem heap) + weight prep (blocks 256..383).
// ---------------------------------------------------------------------------
__global__ __launch_bounds__(128) void knn_prep_kernel(const float* __restrict__ pos,
                                                       const float* __restrict__ W1,
                                                       const float* __restrict__ W2,
                                                       const float* __restrict__ Wmid,
                                                       const float* __restrict__ Wlast) {
    const int bx = blockIdx.x;
    const int t = threadIdx.x;
    if (bx >= 256) {
        const int i = (bx - 256) * 128 + t;             // 0..16383
        if (i < 4096) {     // W1n + W1p frag pack: [kt 0..3][nt 0..31][lane]
            const int lane = i & 31;
            const int nt = (i >> 5) & 31;
            const int kt = i >> 10;
            const int j0 = kt * 16 + (lane & 3) * 2;
            const int n = nt * 8 + (lane >> 2);
            {   // nbr part: W1[64+j] + W1[128+j]
                const float w00 = W1[(64 + j0) * 256 + n] + W1[(128 + j0) * 256 + n];
                const float w01 = W1[(64 + j0 + 1) * 256 + n] + W1[(128 + j0 + 1) * 256 + n];
                const float w10 = W1[(64 + j0 + 8) * 256 + n] + W1[(128 + j0 + 8) * 256 + n];
                const float w11 = W1[(64 + j0 + 9) * 256 + n] + W1[(128 + j0 + 9) * 256 + n];
                u32 h0, l0, h1, l1;
                split2(w00, w01, h0, l0);
                split2(w10, w11, h1, l1);
                g_W1f[i] = make_uint4(h0, h1, l0, l1);
            }
            {   // x part: W1[j] - W1[128+j]
                const float w00 = W1[j0 * 256 + n] - W1[(128 + j0) * 256 + n];
                const float w01 = W1[(j0 + 1) * 256 + n] - W1[(128 + j0 + 1) * 256 + n];
                const float w10 = W1[(j0 + 8) * 256 + n] - W1[(128 + j0 + 8) * 256 + n];
                const float w11 = W1[(j0 + 9) * 256 + n] - W1[(128 + j0 + 9) * 256 + n];
                u32 h0, l0, h1, l1;
                split2(w00, w01, h0, l0);
                split2(w10, w11, h1, l1);
                g_W1pf[i] = make_uint4(h0, h1, l0, l1);
            }
        }
        if (i < 2048) {     // W2 frag pack: [kt 0..15][nt 0..3][lane]
            const int lane = i & 31;
            const int nt = (i >> 5) & 3;
            const int kt = i >> 7;
            const int j0 = kt * 16 + (lane & 3) * 2;
            const int n = nt * 8 + (lane >> 2);
            u32 h0, l0, h1, l1;
            split2(W2[j0 * 32 + n], W2[(j0 + 1) * 32 + n], h0, l0);
            split2(W2[(j0 + 8) * 32 + n], W2[(j0 + 9) * 32 + n], h1, l1);
            g_W2f[i] = make_uint4(h0, h1, l0, l1);
        }
        if (i < 512) {      // Wmid[0:32] dup-packed + Wmid[32:96] frag pack
            {
                const int j = i >> 4;
                const int cp = i & 15;
                const float we = Wmid[j * 32 + 2 * cp];
                const float wo = Wmid[j * 32 + 2 * cp + 1];
                g_Wmid2[i] = make_ulonglong2(pack2(we, we), pack2(wo, wo));
            }
            {   // frag: [kt 0..3][nt 0..3][lane], rows Wmid[32 + j]
                const int lane = i & 31;
                const int nt = (i >> 5) & 3;
                const int kt = i >> 7;
                const int j0 = kt * 16 + (lane & 3) * 2;
                const int n = nt * 8 + (lane >> 2);
                u32 h0, l0, h1, l1;
                split2(Wmid[(32 + j0) * 32 + n], Wmid[(32 + j0 + 1) * 32 + n], h0, l0);
                split2(Wmid[(32 + j0 + 8) * 32 + n], Wmid[(32 + j0 + 9) * 32 + n], h1, l1);
                g_Wmidf[i] = make_uint4(h0, h1, l0, l1);
            }
        }
        if (i < 1024) {     // Wlast[0:64] dup-packed: [j][cpair]
            const int j = i >> 4;
            const int cp = i & 15;
            const float we = Wlast[j * 32 + 2 * cp];
            const float wo = Wlast[j * 32 + 2 * cp + 1];
            g_Wlast2[i] = make_ulonglong2(pack2(we, we), pack2(wo, wo));
        }
        return;
    }

    const int b = bx >> 5;
    const int n = ((bx & 31) << 7) + t;

    const float qx = pos[(b * Nn + n) * 3 + 0];
    const float qy = pos[(b * Nn + n) * 3 + 1];
    const float qz = pos[(b * Nn + n) * 3 + 2];
    const float sqn = __fadd_rn(__fadd_rn(__fmul_rn(qx, qx), __fmul_rn(qy, qy)),
                                __fmul_rn(qz, qz));

    __shared__ float4 tile[1024];
    __shared__ float bdS[16][128];
    __shared__ int biS[16][128];

#pragma unroll
    for (int j = 0; j < 16; ++j) { bdS[j][t] = 3.0e38f; biS[j][t] = 0; }
    float worst = 3.0e38f;
    int wslot = 0;

    for (int t0 = 0; t0 < Nn; t0 += 1024) {
        __syncthreads();
        for (int i = t; i < 1024; i += 128) {
            const float px = pos[(b * Nn + t0 + i) * 3 + 0];
            const float py = pos[(b * Nn + t0 + i) * 3 + 1];
            const float pz = pos[(b * Nn + t0 + i) * 3 + 2];
            const float sq = __fadd_rn(__fadd_rn(__fmul_rn(px, px), __fmul_rn(py, py)),
                                       __fmul_rn(pz, pz));
            tile[i] = make_float4(px, py, pz, sq);
        }
        __syncthreads();
#pragma unroll 4
        for (int i = 0; i < 1024; ++i) {
            const float4 c = tile[i];
            const int m = t0 + i;
            float dot = __fmaf_rn(qx, c.x, 0.f);
            dot = __fmaf_rn(qy, c.y, dot);
            dot = __fmaf_rn(qz, c.z, dot);
            const float dist = __fsub_rn(__fadd_rn(sqn, c.w), __fmul_rn(2.0f, dot));
            const bool need = (dist < worst) && (m != n);
            if (__ballot_sync(0xffffffffu, need)) {
                if (need) {
                    bdS[wslot][t] = dist;
                    biS[wslot][t] = m;
                }
                float d0 = bdS[0][t], d1 = bdS[1][t], d2v = bdS[2][t], d3 = bdS[3][t];
                float d4 = bdS[4][t], d5 = bdS[5][t], d6 = bdS[6][t], d7 = bdS[7][t];
                float d8 = bdS[8][t], d9 = bdS[9][t], d10 = bdS[10][t], d11 = bdS[11][t];
                float d12 = bdS[12][t], d13 = bdS[13][t], d14 = bdS[14][t], d15 = bdS[15][t];
                float v0, v1, v2, v3, v4, v5, v6, v7;
                int s0, s1, s2, s3, s4, s5, s6, s7;
                v0 = (d0 >= d1) ? d0 : d1;      s0 = (d0 >= d1) ? 0 : 1;
                v1 = (d2v >= d3) ? d2v : d3;    s1 = (d2v >= d3) ? 2 : 3;
                v2 = (d4 >= d5) ? d4 : d5;      s2 = (d4 >= d5) ? 4 : 5;
                v3 = (d6 >= d7) ? d6 : d7;      s3 = (d6 >= d7) ? 6 : 7;
                v4 = (d8 >= d9) ? d8 : d9;      s4 = (d8 >= d9) ? 8 : 9;
                v5 = (d10 >= d11) ? d10 : d11;  s5 = (d10 >= d11) ? 10 : 11;
                v6 = (d12 >= d13) ? d12 : d13;  s6 = (d12 >= d13) ? 12 : 13;
                v7 = (d14 >= d15) ? d14 : d15;  s7 = (d14 >= d15) ? 14 : 15;
                s0 = (v0 >= v1) ? s0 : s1;  v0 = (v0 >= v1) ? v0 : v1;
                s2 = (v2 >= v3) ? s2 : s3;  v2 = (v2 >= v3) ? v2 : v3;
                s4 = (v4 >= v5) ? s4 : s5;  v4 = (v4 >= v5) ? v4 : v5;
                s6 = (v6 >= v7) ? s6 : s7;  v6 = (v6 >= v7) ? v6 : v7;
                s0 = (v0 >= v2) ? s0 : s2;  v0 = (v0 >= v2) ? v0 : v2;
                s4 = (v4 >= v6) ? s4 : s6;  v4 = (v4 >= v6) ? v4 : v6;
                wslot = (v0 >= v4) ? s0 : s4;
                worst = (v0 >= v4) ? v0 : v4;
            }
        }
    }

#pragma unroll
    for (int j = 0; j < 16; ++j)
        g_nbr[(b * Nn + n) * 16 + j] = biS[j][t];
}

// ---------------------------------------------------------------------------
// Kernel 2: fused DenseEdgeConv. All four GEMMs with a K-dim (GEMM1, GEMM2,
// xh, mid_x) on tensor cores. Scalar tail as round 16.
// ---------------------------------------------------------------------------
#define P4 4
#define SROW 68

#define OFF_AHI   0
#define OFF_ALO   (OFF_AHI + 64 * 36)
#define OFF_Y2    0
#define OFF_HHI   (OFF_ALO + 64 * 36)
#define OFF_HLO   (OFF_HHI + 64 * 68)
#define OFF_XH    (OFF_HLO + 64 * 68)
#define OFF_XN    (OFF_XH + P4 * 256)
#define OFF_XNH   (OFF_XN + P4 * 64)         // [4 p][32] bf16x2 hi
#define OFF_XNL   (OFF_XNH + P4 * 32)        // [4 p][32] bf16x2 lo
#define OFF_MIDX  (OFF_XNL + P4 * 32)
#define OFF_XG    (OFF_MIDX + P4 * 32)
#define OFF_YBAR  (OFF_XG + P4 * 64)
#define OFF_GATE  (OFF_YBAR + P4 * 64)
#define OFF_LASTX (OFF_GATE + P4 * 128)
#define OFF_NID   (OFF_LASTX + P4 * 32)
#define SMEM_U32  (OFF_NID + 64)

__global__ __launch_bounds__(256, 2) void conv_kernel(
    const float* __restrict__ x,
    const float* __restrict__ b1,
    const float* __restrict__ W2, const float* __restrict__ b2,
    const float* __restrict__ Wmid, const float* __restrict__ bmid,
    const float* __restrict__ Wg, const float* __restrict__ bg,
    const float* __restrict__ Wlast, const float* __restrict__ blast,
    float* __restrict__ out)
{
    extern __shared__ float sm[];
    u32* sAhi = (u32*)sm + OFF_AHI;
    u32* sAlo = (u32*)sm + OFF_ALO;
    u32* sHhi = (u32*)sm + OFF_HHI;
    u32* sHlo = (u32*)sm + OFF_HLO;
    float* sY2 = sm + OFF_Y2;
    float* sXh = sm + OFF_XH;
    float* sXn = sm + OFF_XN;
    u32* sXnHi = (u32*)sm + OFF_XNH;
    u32* sXnLo = (u32*)sm + OFF_XNL;
    float* sMidX = sm + OFF_MIDX;
    float* sXg = sm + OFF_XG;
    float* sYbar = sm + OFF_YBAR;
    float* sGate = sm + OFF_GATE;
    float* sLastX = sm + OFF_LASTX;
    int* sNid = (int*)((u32*)sm + OFF_NID);

    const int t = threadIdx.x;
    const int g0 = blockIdx.x * P4;
    const int b = g0 >> 12;

    sXn[t] = x[(g0 + (t >> 6)) * 64 + (t & 63)];
    if (t < 64) sNid[t] = g_nbr[g0 * 16 + t];
    __syncthreads();

    // ---- gather neighbors -> bf16 hi/lo smem; xn -> bf16 pair table --------
#pragma unroll
    for (int it = 0; it < 4; ++it) {
        const int idx = it * 256 + t;
        const int kk = idx >> 4;
        const int c4 = (idx & 15) << 2;
        const float4 v = *(const float4*)(x + (b * Nn + sNid[kk]) * 64 + c4);
        u32 h0, l0, h1, l1;
        split2(v.x, v.y, h0, l0);
        split2(v.z, v.w, h1, l1);
        const int base = kk * 36 + (c4 >> 1);
        sAhi[base] = h0; sAhi[base + 1] = h1;
        sAlo[base] = l0; sAlo[base + 1] = l1;
    }
    if (t < 128) {
        u32 h, l;
        split2(sXn[2 * t], sXn[2 * t + 1], h, l);
        sXnHi[t] = h;
        sXnLo[t] = l;
    }
    __syncthreads();

    const int lane = t & 31;
    const int w = t >> 5;
    const int lt = lane & 3;
    const int lg = lane >> 2;

    // ---- xh + mid_x via tensor cores (M padded 4->16, rows 4..15 dup) ------
    {
        float dxh[4][4];
        float dmx[4];
#pragma unroll
        for (int nt = 0; nt < 4; ++nt)
#pragma unroll
            for (int r = 0; r < 4; ++r) dxh[nt][r] = 0.f;
#pragma unroll
        for (int r = 0; r < 4; ++r) dmx[r] = 0.f;

#pragma unroll
        for (int kt = 0; kt < 4; ++kt) {
            const int pb = (lg & 3) * 32 + kt * 8 + lt;
            const u32 ah0 = sXnHi[pb];
            const u32 ah2 = sXnHi[pb + 4];
            const u32 al0 = sXnLo[pb];
            const u32 al2 = sXnLo[pb + 4];
#pragma unroll
            for (int nt = 0; nt < 4; ++nt) {
                const int ntg = w * 4 + nt;
                const uint4 bb = g_W1pf[((kt * 32 + ntg) << 5) + lane];
                mma_bf16(dxh[nt], ah0, ah0, ah2, ah2, bb.x, bb.y);
                mma_bf16(dxh[nt], ah0, ah0, ah2, ah2, bb.z, bb.w);
                mma_bf16(dxh[nt], al0, al0, al2, al2, bb.x, bb.y);
            }
            if (w < 4) {
                const uint4 bb = g_Wmidf[((kt * 4 + w) << 5) + lane];
                mma_bf16(dmx, ah0, ah0, ah2, ah2, bb.x, bb.y);
                mma_bf16(dmx, ah0, ah0, ah2, ah2, bb.z, bb.w);
                mma_bf16(dmx, al0, al0, al2, al2, bb.x, bb.y);
            }
        }
        if (lg < 4) {
#pragma unroll
            for (int nt = 0; nt < 4; ++nt) {
                const int c0 = (w * 4 + nt) * 8 + 2 * lt;
                const float2 bv = *(const float2*)(b1 + c0);
                sXh[lg * 256 + c0] = dxh[nt][0] + bv.x;
                sXh[lg * 256 + c0 + 1] = dxh[nt][1] + bv.y;
            }
            if (w < 4) {
                const int c0 = w * 8 + 2 * lt;
                sMidX[lg * 32 + c0] = dmx[0];
                sMidX[lg * 32 + c0 + 1] = dmx[1];
            }
        }
    }
    __syncthreads();

    // GEMM1 layout: warp = (mtp: 2 point-pair) x (ng: 4 nt-groups)
    const int mtp = w & 1;
    const int ng = w >> 1;
    // GEMM2 layout: warp = (mt: 4 points) x (nhw: 2 n-halves)
    const int mt = w & 3;
    const int nhw = w >> 2;

    float d2[2][4];
#pragma unroll
    for (int q = 0; q < 2; ++q)
#pragma unroll
        for (int r = 0; r < 4; ++r) d2[q][r] = 0.f;

#pragma unroll
    for (int h = 0; h < 2; ++h) {
        // ---- GEMM1 half: warp covers 2 m-tiles x 4 n-tiles ----------------
        float d1[2][4][4];
#pragma unroll
        for (int mi = 0; mi < 2; ++mi)
#pragma unroll
            for (int nt = 0; nt < 4; ++nt)
#pragma unroll
                for (int r = 0; r < 4; ++r) d1[mi][nt][r] = 0.f;

#pragma unroll
        for (int kt = 0; kt < 4; ++kt) {
            u32 ah[2][4], al[2][4];
#pragma unroll
            for (int mi = 0; mi < 2; ++mi) {
                const int abase = ((mtp * 2 + mi) * 16 + lg) * 36 + kt * 8 + lt;
                ah[mi][0] = sAhi[abase];
                ah[mi][1] = sAhi[abase + 8 * 36];
                ah[mi][2] = sAhi[abase + 4];
                ah[mi][3] = sAhi[abase + 8 * 36 + 4];
                al[mi][0] = sAlo[abase];
                al[mi][1] = sAlo[abase + 8 * 36];
                al[mi][2] = sAlo[abase + 4];
                al[mi][3] = sAlo[abase + 8 * 36 + 4];
            }
#pragma unroll
            for (int nt = 0; nt < 4; ++nt) {
                const int ntg = h * 16 + ng * 4 + nt;
                const uint4 bb = g_W1f[((kt * 32 + ntg) << 5) + lane];
#pragma unroll
                for (int mi = 0; mi < 2; ++mi) {
                    mma_bf16(d1[mi][nt], ah[mi][0], ah[mi][1], ah[mi][2], ah[mi][3],
                             bb.x, bb.y);
                    mma_bf16(d1[mi][nt], ah[mi][0], ah[mi][1], ah[mi][2], ah[mi][3],
                             bb.z, bb.w);
                    mma_bf16(d1[mi][nt], al[mi][0], al[mi][1], al[mi][2], al[mi][3],
                             bb.x, bb.y);
                }
            }
        }
        // epilogue: + xh, relu, bf16-split, store to sH
#pragma unroll
        for (int mi = 0; mi < 2; ++mi) {
#pragma unroll
            for (int nt = 0; nt < 4; ++nt) {
                const int ntg = h * 16 + ng * 4 + nt;
                const int c0 = ntg * 8 + 2 * lt;
                const int p = mtp * 2 + mi;
                const float xh0 = sXh[p * 256 + c0];
                const float xh1 = sXh[p * 256 + c0 + 1];
                const float v0 = fmaxf(d1[mi][nt][0] + xh0, 0.f);
                const float v1 = fmaxf(d1[mi][nt][1] + xh1, 0.f);
                const float v2 = fmaxf(d1[mi][nt][2] + xh0, 0.f);
                const float v3 = fmaxf(d1[mi][nt][3] + xh1, 0.f);
                u32 h01, l01, h23, l23;
                split2(v0, v1, h01, l01);
                split2(v2, v3, h23, l23);
                const int pair = (ng * 4 + nt) * 4 + lt;
                const int r0 = p * 16 + lg;
                sHhi[r0 * 68 + pair] = h01;
                sHhi[(r0 + 8) * 68 + pair] = h23;
                sHlo[r0 * 68 + pair] = l01;
                sHlo[(r0 + 8) * 68 + pair] = l23;
            }
        }
        __syncthreads();

        // ---- GEMM2 partial: K-tiles ktg = h*8 .. h*8+7 ----------------------
#pragma unroll
        for (int ktl = 0; ktl < 8; ++ktl) {
            const int hbase = (mt * 16 + lg) * 68 + ktl * 8 + lt;
            const u32 ah0 = sHhi[hbase];
            const u32 ah1 = sHhi[hbase + 8 * 68];
            const u32 ah2 = sHhi[hbase + 4];
            const u32 ah3 = sHhi[hbase + 8 * 68 + 4];
            const u32 al0 = sHlo[hbase];
            const u32 al1 = sHlo[hbase + 8 * 68];
            const u32 al2 = sHlo[hbase + 4];
            const u32 al3 = sHlo[hbase + 8 * 68 + 4];
            const int ktg = h * 8 + ktl;
#pragma unroll
            for (int q = 0; q < 2; ++q) {
                const int nt2 = nhw * 2 + q;
                const uint4 bb = g_W2f[((ktg * 4 + nt2) << 5) + lane];
                mma_bf16(d2[q], ah0, ah1, ah2, ah3, bb.x, bb.y);
                mma_bf16(d2[q], ah0, ah1, ah2, ah3, bb.z, bb.w);
                mma_bf16(d2[q], al0, al1, al2, al3, bb.x, bb.y);
            }
        }
        __syncthreads();
    }

#pragma unroll
    for (int q = 0; q < 2; ++q) {
        const int nt2 = nhw * 2 + q;
        const int c0 = nt2 * 8 + 2 * lt;
        const int kk0 = mt * 16 + lg;
        const float bb0 = b2[c0];
        const float bb1 = b2[c0 + 1];
        sY2[(32 + c0) * SROW + kk0] = fmaxf(d2[q][0] + bb0, 0.f);
        sY2[(33 + c0) * SROW + kk0] = fmaxf(d2[q][1] + bb1, 0.f);
        sY2[(32 + c0) * SROW + kk0 + 8] = fmaxf(d2[q][2] + bb0, 0.f);
        sY2[(33 + c0) * SROW + kk0 + 8] = fmaxf(d2[q][3] + bb1, 0.f);
    }
    __syncthreads();

    const int cpair = t & 15;
    const int kq = t >> 4;
    const int kk2 = kq << 2;
    const int pq = kq >> 2;

    {   // mid: f32x2 k-pair packing, dup-packed weights
        ull aE01 = 0ull, aE23 = 0ull, aO01 = 0ull, aO23 = 0ull;
#pragma unroll 8
        for (int j = 0; j < 32; ++j) {
            const ulonglong2 wd = g_Wmid2[(j << 4) + cpair];
            const ulonglong2 av = *(const ulonglong2*)(sY2 + (32 + j) * SROW + kk2);
            aE01 = fma2(av.x, wd.x, aE01);
            aE23 = fma2(av.y, wd.x, aE23);
            aO01 = fma2(av.x, wd.y, aO01);
            aO23 = fma2(av.y, wd.y, aO23);
        }
        const float bx0 = sMidX[pq * 32 + 2 * cpair] + bmid[2 * cpair];
        const float bx1 = sMidX[pq * 32 + 2 * cpair + 1] + bmid[2 * cpair + 1];
        const float2 uE01 = unpack2(aE01), uE23 = unpack2(aE23);
        const float2 uO01 = unpack2(aO01), uO23 = unpack2(aO23);
        float4 r0, r1;
        r0.x = fmaxf(uE01.x + bx0, 0.f); r0.y = fmaxf(uE01.y + bx0, 0.f);
        r0.z = fmaxf(uE23.x + bx0, 0.f); r0.w = fmaxf(uE23.y + bx0, 0.f);
        r1.x = fmaxf(uO01.x + bx1, 0.f); r1.y = fmaxf(uO01.y + bx1, 0.f);
        r1.z = fmaxf(uO23.x + bx1, 0.f); r1.w = fmaxf(uO23.y + bx1, 0.f);
        *(float4*)(sY2 + (2 * cpair) * SROW + kk2) = r0;
        *(float4*)(sY2 + (2 * cpair + 1) * SROW + kk2) = r1;
    }
    __syncthreads();

    {   // ybar
        const int jj = t & 63;
        const int pp = t >> 6;
        const float* row = sY2 + jj * SROW + pp * 16;
        const float4 s0 = *(const float4*)(row + 0);
        const float4 s1 = *(const float4*)(row + 4);
        const float4 s2 = *(const float4*)(row + 8);
        const float4 s3 = *(const float4*)(row + 12);
        const float s = (s0.x + s0.y + s0.z + s0.w) + (s1.x + s1.y + s1.z + s1.w)
                      + (s2.x + s2.y + s2.z + s2.w) + (s3.x + s3.y + s3.z + s3.w);
        sYbar[pp * 64 + jj] = s * (1.0f / 16.0f);
    }
    __syncthreads();

    {   // gate partials: warp w covers j in [16w, 16w+16)
        float* sPart = (float*)sHhi;
        const int jbase = w * 16;
        ull acc[2][4];
#pragma unroll
        for (int g = 0; g < 2; ++g)
#pragma unroll
            for (int p = 0; p < 4; ++p) acc[g][p] = 0ull;
#pragma unroll
        for (int jj = 0; jj < 16; ++jj) {
            const int j = jbase + jj;
            const ull wv0 = *(const ull*)(Wg + j * 128 + 2 * lane);
            const ull wv1 = *(const ull*)(Wg + j * 128 + 64 + 2 * lane);
#pragma unroll
            for (int p = 0; p < 4; ++p) {
                const float yv = (w < 4) ? sYbar[p * 64 + j]
                                         : sXn[p * 64 + (j - 64)];
                const ull yp = pack2(yv, yv);
                acc[0][p] = fma2(yp, wv0, acc[0][p]);
                acc[1][p] = fma2(yp, wv1, acc[1][p]);
            }
        }
#pragma unroll
        for (int p = 0; p < 4; ++p) {
            *(ull*)(sPart + w * 512 + p * 128 + 2 * lane) = acc[0][p];
            *(ull*)(sPart + w * 512 + p * 128 + 64 + 2 * lane) = acc[1][p];
        }
    }
    __syncthreads();

    {   // gate reduce (w ascending) + sigmoid
        float* sPart = (float*)sHhi;
        const int c2g = (t & 63) * 2;
        const int pg = t >> 6;
        ull s = *(const ull*)(sPart + pg * 128 + c2g);
#pragma unroll
        for (int wq = 1; wq < 8; ++wq)
            s = add2(s, *(const ull*)(sPart + wq * 512 + pg * 128 + c2g));
        const float2 u = unpack2(s);
        sGate[pg * 128 + c2g] = 1.0f / (1.0f + expf(-(u.x + bg[c2g])));
        sGate[pg * 128 + c2g + 1] = 1.0f / (1.0f + expf(-(u.y + bg[c2g + 1])));
    }
    __syncthreads();

    {   // xg; out 96..159
        const int c = t & 63;
        const int p = t >> 6;
        const float xg = sXn[p * 64 + c] * sGate[p * 128 + 64 + c];
        sXg[p * 64 + c] = xg;
        out[(g0 + p) * 160 + 96 + c] = xg;
    }
    __syncthreads();

    {   // y2 *= gate; out 32..95
        const int jj = t & 63;
        const int pp = t >> 6;
        const float gv = sGate[pp * 128 + jj];
        float* row = sY2 + jj * SROW + pp * 16;
        float mx = -3.0e38f;
#pragma unroll
        for (int q = 0; q < 4; ++q) {
            float4 v = *(const float4*)(row + 4 * q);
            v.x *= gv; v.y *= gv; v.z *= gv; v.w *= gv;
            mx = fmaxf(mx, fmaxf(fmaxf(v.x, v.y), fmaxf(v.z, v.w)));
            *(float4*)(row + 4 * q) = v;
        }
        out[(g0 + pp) * 160 + 32 + jj] = mx;
    }
    if (t < 128) {  // last_x
        const int p = t >> 5;
        const int c = t & 31;
        float a = 0.f;
#pragma unroll 8
        for (int j = 0; j < 64; ++j)
            a = __fmaf_rn(sXg[p * 64 + j], Wlast[(64 + j) * 32 + c], a);
        sLastX[p * 32 + c] = a;
    }
    __syncthreads();

    float* sRed = sXh;
    {   // last: f32x2 k-pair packing, dup-packed weights; out 0..31
        ull aE01 = 0ull, aE23 = 0ull, aO01 = 0ull, aO23 = 0ull;
#pragma unroll 8
        for (int j = 0; j < 64; ++j) {
            const ulonglong2 wd = g_Wlast2[(j << 4) + cpair];
            const ulonglong2 av = *(const ulonglong2*)(sY2 + j * SROW + kk2);
            aE01 = fma2(av.x, wd.x, aE01);
            aE23 = fma2(av.y, wd.x, aE23);
            aO01 = fma2(av.x, wd.y, aO01);
            aO23 = fma2(av.y, wd.y, aO23);
        }
        const float t0 = sLastX[pq * 32 + 2 * cpair] + blast[2 * cpair];
        const float t1 = sLastX[pq * 32 + 2 * cpair + 1] + blast[2 * cpair + 1];
        const float2 uE01 = unpack2(aE01), uE23 = unpack2(aE23);
        const float2 uO01 = unpack2(aO01), uO23 = unpack2(aO23);
        const float mx0 = fmaxf(fmaxf(uE01.x + t0, uE01.y + t0),
                                fmaxf(uE23.x + t0, uE23.y + t0));
        const float mx1 = fmaxf(fmaxf(uO01.x + t1, uO01.y + t1),
                                fmaxf(uO23.x + t1, uO23.y + t1));
        sRed[kq * 32 + 2 * cpair] = mx0;
        sRed[kq * 32 + 2 * cpair + 1] = mx1;
    }
    __syncthreads();
    if (t < 128) {
        const int p = t >> 5;
        const int cc = t & 31;
        float mx = sRed[(p * 4 + 0) * 32 + cc];
        mx = fmaxf(mx, sRed[(p * 4 + 1) * 32 + cc]);
        mx = fmaxf(mx, sRed[(p * 4 + 2) * 32 + cc]);
        mx = fmaxf(mx, sRed[(p * 4 + 3) * 32 + cc]);
        out[(g0 + p) * 160 + cc] = mx;
    }
}

// ---------------------------------------------------------------------------
extern "C" void kernel_launch(void* const* d_in, const int* in_sizes, int n_in,
                              void* d_out, int out_size) {
    const float* x = (const float*)d_in[0];
    const float* pos = (const float*)d_in[1];
    const float* W1 = (const float*)d_in[2];
    const float* b1 = (const float*)d_in[3];
    const float* W2 = (const float*)d_in[4];
    const float* b2 = (const float*)d_in[5];
    const float* Wmid = (const float*)d_in[6];
    const float* bmid = (const float*)d_in[7];
    const float* Wg = (const float*)d_in[8];
    const float* bg = (const float*)d_in[9];
    const float* Wlast = (const float*)d_in[10];
    const float* blast = (const float*)d_in[11];
    float* out = (float*)d_out;

    const int smem_bytes = SMEM_U32 * 4;
    cudaFuncSetAttribute(conv_kernel, cudaFuncAttributeMaxDynamicSharedMemorySize,
                         smem_bytes);

    knn_prep_kernel<<<256 + 128, 128>>>(pos, W1, W2, Wmid, Wlast);
    conv_kernel<<<(Bb * Nn) / P4, 256, smem_bytes>>>(
        x, b1, W2, b2, Wmid, bmid, Wg, bg, Wlast, blast, out);
}